// round 1
// baseline (speedup 1.0000x reference)
#include <cuda_runtime.h>
#include <cuda_bf16.h>
#include <cstdint>

#define Bb 8
#define Nn 4096
#define Dd 64
#define Ss 1024
#define Kk 32
#define RAD2 0.04f
#define NELEM 262144.0f   // B*32*S elements per channel for BN

// ---------------- scratch (device globals; no allocation allowed) ----------------
__device__ float g_featT[Bb * Nn * Dd];            // [b][n][c] point-major features
__device__ int   g_fps[Bb * Ss];
__device__ float g_centers[Bb * Ss * 3];           // [bs][3]
__device__ int   g_gi[Bb * Ss * Kk];
__device__ float g_y0[Bb * Ss * Kk * 64];          // [bs][h][o]
__device__ float g_y1[Bb * Ss * Kk * 64];
__device__ float g_y2[Bb * Ss * Kk * 128];
__device__ float g_sum0[64],  g_sq0[64],  g_scale0[64],  g_shift0[64];
__device__ float g_sum1[64],  g_sq1[64],  g_scale1[64],  g_shift1[64];
__device__ float g_sum2[128], g_sq2[128], g_scale2[128], g_shift2[128];

// ---------------- zero stats ----------------
__global__ void zero_stats_kernel() {
    int t = threadIdx.x;
    if (t < 64)  { g_sum0[t] = 0.f; g_sq0[t] = 0.f; g_sum1[t] = 0.f; g_sq1[t] = 0.f; }
    if (t < 128) { g_sum2[t] = 0.f; g_sq2[t] = 0.f; }
}

// ---------------- feature transpose: (B,64,N) -> (B,N,64) ----------------
__global__ void transpose_feat_kernel(const float* __restrict__ feat) {
    int e = blockIdx.x * blockDim.x + threadIdx.x;   // 2,097,152 elements
    if (e >= Bb * Nn * Dd) return;
    int c = e & 63;
    int n = (e >> 6) & (Nn - 1);
    int b = e >> 18;
    g_featT[e] = feat[b * (Dd * Nn) + c * Nn + n];
}

// ---------------- FPS: one block per batch, 512 threads, 8 pts/thread -----------
__global__ __launch_bounds__(512) void fps_kernel(const float* __restrict__ pos) {
    int b = blockIdx.x;
    const float* P = pos + b * 3 * Nn;
    int t = threadIdx.x;

    float px[8], py[8], pz[8], cum[8];
    unsigned maskbits = 0;
#pragma unroll
    for (int k = 0; k < 8; k++) {
        int n = t + 512 * k;
        px[k] = P[n];
        py[k] = P[Nn + n];
        pz[k] = P[2 * Nn + n];
        cum[k] = 0.f;
    }

    __shared__ float s_cx, s_cy, s_cz;
    __shared__ int   s_nxt;
    __shared__ float s_wv[16];
    __shared__ int   s_wn[16];

    if (t == 0) {
        s_cx = px[0]; s_cy = py[0]; s_cz = pz[0];
        maskbits |= 1u;                       // point 0 selected
        g_fps[b * Ss] = 0;
        float* c = &g_centers[(b * Ss) * 3];
        c[0] = px[0]; c[1] = py[0]; c[2] = pz[0];
    }
    __syncthreads();

    const float NEG = -3.4e38f;
    for (int step = 1; step < Ss; step++) {
        float cx = s_cx, cy = s_cy, cz = s_cz;
        float bv = NEG; int bn = 0x7fffffff;
#pragma unroll
        for (int k = 0; k < 8; k++) {
            float dx = px[k] - cx, dy = py[k] - cy, dz = pz[k] - cz;
            float sqd = dx * dx + dy * dy + dz * dz;
            cum[k] = cum[k] + sqd;
            float v = ((maskbits >> k) & 1u) ? NEG : cum[k];
            int n = t + 512 * k;
            if (v > bv || (v == bv && n < bn)) { bv = v; bn = n; }
        }
        // warp argmax (min-index tie-break)
#pragma unroll
        for (int off = 16; off; off >>= 1) {
            float ov = __shfl_down_sync(0xffffffffu, bv, off);
            int   on = __shfl_down_sync(0xffffffffu, bn, off);
            if (ov > bv || (ov == bv && on < bn)) { bv = ov; bn = on; }
        }
        int w = t >> 5;
        if ((t & 31) == 0) { s_wv[w] = bv; s_wn[w] = bn; }
        __syncthreads();
        if (t < 32) {
            bv = (t < 16) ? s_wv[t] : NEG;
            bn = (t < 16) ? s_wn[t] : 0x7fffffff;
#pragma unroll
            for (int off = 8; off; off >>= 1) {
                float ov = __shfl_down_sync(0xffffffffu, bv, off);
                int   on = __shfl_down_sync(0xffffffffu, bn, off);
                if (ov > bv || (ov == bv && on < bn)) { bv = ov; bn = on; }
            }
            if (t == 0) s_nxt = bn;
        }
        __syncthreads();
        int nxt = s_nxt;
        if ((nxt & 511) == t) {
            int k = nxt >> 9;
            maskbits |= (1u << k);
            s_cx = px[k]; s_cy = py[k]; s_cz = pz[k];
            g_fps[b * Ss + step] = nxt;
            float* c = &g_centers[(b * Ss + step) * 3];
            c[0] = px[k]; c[1] = py[k]; c[2] = pz[k];
        }
        __syncthreads();
    }
}

// ---------------- ball query: 8 warps/block, pos tile in SMEM -------------------
__global__ __launch_bounds__(256) void ballquery_kernel(const float* __restrict__ pos) {
    __shared__ float sx[Nn], sy[Nn], sz[Nn];
    int b  = blockIdx.x >> 7;
    int s0 = (blockIdx.x & 127) * 8;
    const float* P = pos + b * 3 * Nn;
    for (int i = threadIdx.x; i < Nn; i += 256) {
        sx[i] = P[i]; sy[i] = P[Nn + i]; sz[i] = P[2 * Nn + i];
    }
    __syncthreads();

    int warp = threadIdx.x >> 5, lane = threadIdx.x & 31;
    int bs = b * Ss + s0 + warp;
    float cx = g_centers[bs * 3 + 0];
    float cy = g_centers[bs * 3 + 1];
    float cz = g_centers[bs * 3 + 2];
    float csq = cx * cx + cy * cy + cz * cz;

    int cnt = 0, first = 0;
    int* G = &g_gi[bs * Kk];
    unsigned lanemask = (1u << lane) - 1u;
    for (int j0 = 0; j0 < Nn; j0 += 32) {
        int j = j0 + lane;
        float x = sx[j], y = sy[j], z = sz[j];
        float dot = cx * x + cy * y + cz * z;
        float psq = x * x + y * y + z * z;
        float d = -2.0f * dot + csq + psq;
        bool ok = !(d > RAD2);
        unsigned m = __ballot_sync(0xffffffffu, ok);
        if (cnt == 0 && m) first = j0 + __ffs(m) - 1;
        int p = cnt + __popc(m & lanemask);
        if (ok && p < Kk) G[p] = j;
        cnt += __popc(m);
        if (cnt >= Kk) break;
    }
    for (int p = cnt + lane; p < Kk; p += 32) G[p] = first;
}

// ---------------- conv0: gather(67ch) -> 64, + BN stats -------------------------
__global__ __launch_bounds__(256) void conv0_kernel(const float* __restrict__ pos,
                                                    const float* __restrict__ w0,
                                                    const float* __restrict__ b0) {
    __shared__ float wT[67 * 64];
    __shared__ float xs[2][32][68];
    __shared__ int   sgi[64];
    __shared__ float sc[2][3];
    __shared__ float ssum[64], ssq[64];

    int t = threadIdx.x;
    int bs0 = blockIdx.x * 2;
    for (int e = t; e < 67 * 64; e += 256) {
        int o = e & 63, i = e >> 6;
        wT[i * 64 + o] = w0[o * 67 + i];
    }
    if (t < 64) sgi[t] = g_gi[bs0 * Kk + t];
    if (t < 6)  sc[t / 3][t % 3] = g_centers[bs0 * 3 + t];
    if (t < 64) { ssum[t] = 0.f; ssq[t] = 0.f; }
    __syncthreads();

    int b = bs0 >> 10;
    const float* Pb = pos + b * 3 * Nn;
    for (int e = t; e < 2 * 32 * 67; e += 256) {
        int g = e / (32 * 67);
        int r = e - g * (32 * 67);
        int h = r / 67;
        int i = r - h * 67;
        int idx = sgi[g * 32 + h];
        float v;
        if (i < 3) v = Pb[i * Nn + idx] - sc[g][i];
        else       v = g_featT[(b * Nn + idx) * 64 + (i - 3)];
        xs[g][h][i] = v;
    }
    __syncthreads();

    int om = (t & 15) * 4;
    int hg = t >> 4;
    int g  = hg >> 3;
    int h4 = (hg & 7) * 4;

    float acc[4][4];
#pragma unroll
    for (int a = 0; a < 4; a++)
#pragma unroll
        for (int j = 0; j < 4; j++) acc[a][j] = 0.f;

    for (int i = 0; i < 67; i++) {
        float4 wv = *(const float4*)&wT[i * 64 + om];
        float xr0 = xs[g][h4 + 0][i];
        float xr1 = xs[g][h4 + 1][i];
        float xr2 = xs[g][h4 + 2][i];
        float xr3 = xs[g][h4 + 3][i];
        acc[0][0] += xr0 * wv.x; acc[0][1] += xr0 * wv.y; acc[0][2] += xr0 * wv.z; acc[0][3] += xr0 * wv.w;
        acc[1][0] += xr1 * wv.x; acc[1][1] += xr1 * wv.y; acc[1][2] += xr1 * wv.z; acc[1][3] += xr1 * wv.w;
        acc[2][0] += xr2 * wv.x; acc[2][1] += xr2 * wv.y; acc[2][2] += xr2 * wv.z; acc[2][3] += xr2 * wv.w;
        acc[3][0] += xr3 * wv.x; acc[3][1] += xr3 * wv.y; acc[3][2] += xr3 * wv.z; acc[3][3] += xr3 * wv.w;
    }

    float4 bias4 = *(const float4*)&b0[om];
    float ls[4] = {0, 0, 0, 0}, lq[4] = {0, 0, 0, 0};
    int bs = bs0 + g;
#pragma unroll
    for (int hh = 0; hh < 4; hh++) {
        float4 v;
        v.x = acc[hh][0] + bias4.x;
        v.y = acc[hh][1] + bias4.y;
        v.z = acc[hh][2] + bias4.z;
        v.w = acc[hh][3] + bias4.w;
        ls[0] += v.x; lq[0] += v.x * v.x;
        ls[1] += v.y; lq[1] += v.y * v.y;
        ls[2] += v.z; lq[2] += v.z * v.z;
        ls[3] += v.w; lq[3] += v.w * v.w;
        *(float4*)&g_y0[(bs * 32 + h4 + hh) * 64 + om] = v;
    }
#pragma unroll
    for (int j = 0; j < 4; j++) {
        atomicAdd(&ssum[om + j], ls[j]);
        atomicAdd(&ssq[om + j],  lq[j]);
    }
    __syncthreads();
    if (t < 64) {
        atomicAdd(&g_sum0[t], ssum[t]);
        atomicAdd(&g_sq0[t],  ssq[t]);
    }
}

// ---------------- BN finalize: fold into scale/shift ----------------------------
__global__ void finalize_kernel(const float* __restrict__ gam,
                                const float* __restrict__ bet, int layer) {
    int o = threadIdx.x;
    float *sum, *sq, *sc, *sh; int C;
    if (layer == 0)      { sum = g_sum0; sq = g_sq0; sc = g_scale0; sh = g_shift0; C = 64; }
    else if (layer == 1) { sum = g_sum1; sq = g_sq1; sc = g_scale1; sh = g_shift1; C = 64; }
    else                 { sum = g_sum2; sq = g_sq2; sc = g_scale2; sh = g_shift2; C = 128; }
    if (o < C) {
        float mean = sum[o] * (1.0f / NELEM);
        float var  = sq[o] * (1.0f / NELEM) - mean * mean;
        float inv  = rsqrtf(var + 1e-5f);
        float s = gam[o] * inv;
        sc[o] = s;
        sh[o] = bet[o] - mean * s;
    }
}

// ---------------- conv1: 64->64 with fused BN0+ReLU -----------------------------
__global__ __launch_bounds__(256) void conv1_kernel(const float* __restrict__ w1,
                                                    const float* __restrict__ b1) {
    __shared__ float wT[64 * 64];
    __shared__ float xs[2][32][64];
    __shared__ float ssum[64], ssq[64];

    int t = threadIdx.x;
    int bs0 = blockIdx.x * 2;
    for (int e = t; e < 64 * 64; e += 256) {
        int o = e & 63, i = e >> 6;
        wT[i * 64 + o] = w1[o * 64 + i];
    }
    if (t < 64) { ssum[t] = 0.f; ssq[t] = 0.f; }
    const float* Y = &g_y0[bs0 * 2048];
    float* xf = &xs[0][0][0];
    for (int e = t; e < 4096; e += 256) {
        int i = e & 63;
        float v = Y[e] * g_scale0[i] + g_shift0[i];
        xf[e] = fmaxf(v, 0.f);
    }
    __syncthreads();

    int om = (t & 15) * 4;
    int hg = t >> 4;
    int g  = hg >> 3;
    int h4 = (hg & 7) * 4;

    float acc[4][4];
#pragma unroll
    for (int a = 0; a < 4; a++)
#pragma unroll
        for (int j = 0; j < 4; j++) acc[a][j] = 0.f;

    for (int i = 0; i < 64; i++) {
        float4 wv = *(const float4*)&wT[i * 64 + om];
        float xr0 = xs[g][h4 + 0][i];
        float xr1 = xs[g][h4 + 1][i];
        float xr2 = xs[g][h4 + 2][i];
        float xr3 = xs[g][h4 + 3][i];
        acc[0][0] += xr0 * wv.x; acc[0][1] += xr0 * wv.y; acc[0][2] += xr0 * wv.z; acc[0][3] += xr0 * wv.w;
        acc[1][0] += xr1 * wv.x; acc[1][1] += xr1 * wv.y; acc[1][2] += xr1 * wv.z; acc[1][3] += xr1 * wv.w;
        acc[2][0] += xr2 * wv.x; acc[2][1] += xr2 * wv.y; acc[2][2] += xr2 * wv.z; acc[2][3] += xr2 * wv.w;
        acc[3][0] += xr3 * wv.x; acc[3][1] += xr3 * wv.y; acc[3][2] += xr3 * wv.z; acc[3][3] += xr3 * wv.w;
    }

    float4 bias4 = *(const float4*)&b1[om];
    float ls[4] = {0, 0, 0, 0}, lq[4] = {0, 0, 0, 0};
    int bs = bs0 + g;
#pragma unroll
    for (int hh = 0; hh < 4; hh++) {
        float4 v;
        v.x = acc[hh][0] + bias4.x;
        v.y = acc[hh][1] + bias4.y;
        v.z = acc[hh][2] + bias4.z;
        v.w = acc[hh][3] + bias4.w;
        ls[0] += v.x; lq[0] += v.x * v.x;
        ls[1] += v.y; lq[1] += v.y * v.y;
        ls[2] += v.z; lq[2] += v.z * v.z;
        ls[3] += v.w; lq[3] += v.w * v.w;
        *(float4*)&g_y1[(bs * 32 + h4 + hh) * 64 + om] = v;
    }
#pragma unroll
    for (int j = 0; j < 4; j++) {
        atomicAdd(&ssum[om + j], ls[j]);
        atomicAdd(&ssq[om + j],  lq[j]);
    }
    __syncthreads();
    if (t < 64) {
        atomicAdd(&g_sum1[t], ssum[t]);
        atomicAdd(&g_sq1[t],  ssq[t]);
    }
}

// ---------------- conv2: 64->128 with fused BN1+ReLU ----------------------------
__global__ __launch_bounds__(256) void conv2_kernel(const float* __restrict__ w2,
                                                    const float* __restrict__ b2) {
    __shared__ float wT[64 * 128];
    __shared__ float xs[32][64];
    __shared__ float ssum[128], ssq[128];

    int t = threadIdx.x;
    int bs = blockIdx.x;
    for (int e = t; e < 64 * 128; e += 256) {
        int o = e & 127, i = e >> 7;
        wT[i * 128 + o] = w2[o * 64 + i];
    }
    if (t < 128) { ssum[t] = 0.f; ssq[t] = 0.f; }
    const float* Y = &g_y1[bs * 2048];
    float* xf = &xs[0][0];
    for (int e = t; e < 2048; e += 256) {
        int i = e & 63;
        float v = Y[e] * g_scale1[i] + g_shift1[i];
        xf[e] = fmaxf(v, 0.f);
    }
    __syncthreads();

    int om = (t & 31) * 4;
    int h4 = (t >> 5) * 4;

    float acc[4][4];
#pragma unroll
    for (int a = 0; a < 4; a++)
#pragma unroll
        for (int j = 0; j < 4; j++) acc[a][j] = 0.f;

    for (int i = 0; i < 64; i++) {
        float4 wv = *(const float4*)&wT[i * 128 + om];
        float xr0 = xs[h4 + 0][i];
        float xr1 = xs[h4 + 1][i];
        float xr2 = xs[h4 + 2][i];
        float xr3 = xs[h4 + 3][i];
        acc[0][0] += xr0 * wv.x; acc[0][1] += xr0 * wv.y; acc[0][2] += xr0 * wv.z; acc[0][3] += xr0 * wv.w;
        acc[1][0] += xr1 * wv.x; acc[1][1] += xr1 * wv.y; acc[1][2] += xr1 * wv.z; acc[1][3] += xr1 * wv.w;
        acc[2][0] += xr2 * wv.x; acc[2][1] += xr2 * wv.y; acc[2][2] += xr2 * wv.z; acc[2][3] += xr2 * wv.w;
        acc[3][0] += xr3 * wv.x; acc[3][1] += xr3 * wv.y; acc[3][2] += xr3 * wv.z; acc[3][3] += xr3 * wv.w;
    }

    float4 bias4 = *(const float4*)&b2[om];
    float ls[4] = {0, 0, 0, 0}, lq[4] = {0, 0, 0, 0};
#pragma unroll
    for (int hh = 0; hh < 4; hh++) {
        float4 v;
        v.x = acc[hh][0] + bias4.x;
        v.y = acc[hh][1] + bias4.y;
        v.z = acc[hh][2] + bias4.z;
        v.w = acc[hh][3] + bias4.w;
        ls[0] += v.x; lq[0] += v.x * v.x;
        ls[1] += v.y; lq[1] += v.y * v.y;
        ls[2] += v.z; lq[2] += v.z * v.z;
        ls[3] += v.w; lq[3] += v.w * v.w;
        *(float4*)&g_y2[(bs * 32 + h4 + hh) * 128 + om] = v;
    }
#pragma unroll
    for (int j = 0; j < 4; j++) {
        atomicAdd(&ssum[om + j], ls[j]);
        atomicAdd(&ssq[om + j],  lq[j]);
    }
    __syncthreads();
    if (t < 128) {
        atomicAdd(&g_sum2[t], ssum[t]);
        atomicAdd(&g_sq2[t],  ssq[t]);
    }
}

// ---------------- final: BN2 + ReLU + max over samples -> feat_out ---------------
__global__ __launch_bounds__(256) void finalpool_kernel(float* __restrict__ out) {
    int gwarp = (blockIdx.x * blockDim.x + threadIdx.x) >> 5;   // bs
    int lane = threadIdx.x & 31;
    if (gwarp >= Bb * Ss) return;
    int bs = gwarp;
    int b = bs >> 10, s = bs & 1023;

    float scl[4], sft[4];
#pragma unroll
    for (int j = 0; j < 4; j++) {
        scl[j] = g_scale2[lane + 32 * j];
        sft[j] = g_shift2[lane + 32 * j];
    }
    float m[4] = {-3.4e38f, -3.4e38f, -3.4e38f, -3.4e38f};
    const float* Y = &g_y2[bs * 32 * 128];
    for (int h = 0; h < 32; h++) {
#pragma unroll
        for (int j = 0; j < 4; j++) {
            float v = Y[h * 128 + lane + 32 * j] * scl[j] + sft[j];
            v = fmaxf(v, 0.f);
            m[j] = fmaxf(m[j], v);
        }
    }
    float* F = out + Bb * 3 * Ss + b * 128 * Ss + s;
#pragma unroll
    for (int j = 0; j < 4; j++) F[(lane + 32 * j) * Ss] = m[j];
}

// ---------------- pos_out copy --------------------------------------------------
__global__ void poscopy_kernel(float* __restrict__ out) {
    int e = blockIdx.x * blockDim.x + threadIdx.x;
    if (e >= Bb * 3 * Ss) return;
    int b = e / (3 * Ss);
    int r = e - b * (3 * Ss);
    int c = r / Ss;
    int s = r - c * Ss;
    out[e] = g_centers[(b * Ss + s) * 3 + c];
}

// ---------------- launch --------------------------------------------------------
extern "C" void kernel_launch(void* const* d_in, const int* in_sizes, int n_in,
                              void* d_out, int out_size) {
    const float* pos  = (const float*)d_in[0];
    const float* feat = (const float*)d_in[1];
    const float* w0   = (const float*)d_in[2];
    const float* b0   = (const float*)d_in[3];
    const float* g0   = (const float*)d_in[4];
    const float* be0  = (const float*)d_in[5];
    const float* w1   = (const float*)d_in[6];
    const float* b1   = (const float*)d_in[7];
    const float* g1   = (const float*)d_in[8];
    const float* be1  = (const float*)d_in[9];
    const float* w2   = (const float*)d_in[10];
    const float* b2   = (const float*)d_in[11];
    const float* g2   = (const float*)d_in[12];
    const float* be2  = (const float*)d_in[13];
    float* out = (float*)d_out;

    zero_stats_kernel<<<1, 128>>>();
    transpose_feat_kernel<<<(Bb * Nn * Dd) / 256, 256>>>(feat);
    fps_kernel<<<Bb, 512>>>(pos);
    ballquery_kernel<<<1024, 256>>>(pos);
    conv0_kernel<<<Bb * Ss / 2, 256>>>(pos, w0, b0);
    finalize_kernel<<<1, 128>>>(g0, be0, 0);
    conv1_kernel<<<Bb * Ss / 2, 256>>>(w1, b1);
    finalize_kernel<<<1, 128>>>(g1, be1, 1);
    conv2_kernel<<<Bb * Ss, 256>>>(w2, b2);
    finalize_kernel<<<1, 128>>>(g2, be2, 2);
    finalpool_kernel<<<Bb * Ss / 8, 256>>>(out);
    poscopy_kernel<<<(Bb * 3 * Ss + 255) / 256, 256>>>(out);
}

// round 3
// speedup vs baseline: 1.3282x; 1.3282x over previous
#include <cuda_runtime.h>
#include <cuda_bf16.h>
#include <cstdint>

#define Bb 8
#define Nn 4096
#define Dd 64
#define Ss 1024
#define Kk 32
#define RAD2 0.04f
#define NELEM 262144.0f   // B*32*S elements per channel for BN

// ---------------- scratch (device globals; no allocation allowed) ----------------
__device__ float g_featT[Bb * Nn * Dd];            // [b][n][c] point-major features
__device__ float g_centers[Bb * Ss * 3];           // [bs][3]
__device__ int   g_gi[Bb * Ss * Kk];
__device__ float g_y0[Bb * Ss * Kk * 64];          // [bs][h][o]
__device__ float g_y1[Bb * Ss * Kk * 64];
__device__ float g_y2[Bb * Ss * Kk * 128];
__device__ float g_sum0[64],  g_sq0[64];
__device__ float g_sum1[64],  g_sq1[64];
__device__ float g_sum2[128], g_sq2[128];

// ---------------- zero stats ----------------
__global__ void zero_stats_kernel() {
    int t = threadIdx.x;
    if (t < 64)  { g_sum0[t] = 0.f; g_sq0[t] = 0.f; g_sum1[t] = 0.f; g_sq1[t] = 0.f; }
    if (t < 128) { g_sum2[t] = 0.f; g_sq2[t] = 0.f; }
}

// ---------------- feature transpose: (B,64,N) -> (B,N,64) ----------------
__global__ void transpose_feat_kernel(const float* __restrict__ feat) {
    int e = blockIdx.x * blockDim.x + threadIdx.x;   // 2,097,152 elements
    if (e >= Bb * Nn * Dd) return;
    int c = e & 63;
    int n = (e >> 6) & (Nn - 1);
    int b = e >> 18;
    g_featT[e] = feat[b * (Dd * Nn) + c * Nn + n];
}

// ---------------- FPS: one block per batch, 512 threads, 8 pts/thread -----------
// Value-only max scan + monotone-uint atomicMax + rare equality pass.
// Point cache lives in DYNAMIC smem (48KB) to dodge the static-smem ceiling.
__global__ __launch_bounds__(512) void fps_kernel(const float* __restrict__ pos) {
    extern __shared__ float dyn[];
    float* sx = dyn;
    float* sy = dyn + Nn;
    float* sz = dyn + 2 * Nn;

    __shared__ unsigned s_bv[2];
    __shared__ int      s_nxt[2];

    int b = blockIdx.x;
    const float* P = pos + b * 3 * Nn;
    int t = threadIdx.x;

    float px[8], py[8], pz[8], cum[8];
#pragma unroll
    for (int k = 0; k < 8; k++) {
        int n = t + 512 * k;
        px[k] = P[n];
        py[k] = P[Nn + n];
        pz[k] = P[2 * Nn + n];
        sx[n] = px[k]; sy[n] = py[k]; sz[n] = pz[k];
        cum[k] = 0.f;
    }

    const float NEG = -3.4e38f;
    if (t == 0) {
        cum[0] = NEG;                              // point 0 pre-selected
        float* c = &g_centers[(b * Ss) * 3];
        c[0] = px[0]; c[1] = py[0]; c[2] = pz[0];
        s_bv[0] = 0u; s_bv[1] = 0u;
        s_nxt[0] = 0x7fffffff; s_nxt[1] = 0x7fffffff;
    }
    __syncthreads();

    int cur = 0;
    for (int step = 1; step < Ss; step++) {
        int par = step & 1;
        float cx = sx[cur], cy = sy[cur], cz = sz[cur];

        float m = NEG;
#pragma unroll
        for (int k = 0; k < 8; k++) {
            float dx = px[k] - cx, dy = py[k] - cy, dz = pz[k] - cz;
            float sqd = dx * dx + dy * dy + dz * dz;
            cum[k] = cum[k] + sqd;
            m = fmaxf(m, cum[k]);
        }
        // warp max (all lanes end with warp max)
#pragma unroll
        for (int off = 16; off; off >>= 1)
            m = fmaxf(m, __shfl_xor_sync(0xffffffffu, m, off));

        // monotone float->uint encode
        unsigned um = __float_as_uint(m);
        um = (um & 0x80000000u) ? ~um : (um | 0x80000000u);
        if ((t & 31) == 0) atomicMax(&s_bv[par], um);
        __syncthreads();                           // A

        if (t == 0) { s_bv[par ^ 1] = 0u; s_nxt[par ^ 1] = 0x7fffffff; }

        unsigned bu = s_bv[par];
        if (um == bu) {                            // warp-uniform: only winning warp(s)
            int idx = 0x7fffffff;
#pragma unroll
            for (int k = 0; k < 8; k++)
                if (cum[k] == m) idx = min(idx, t + 512 * k);
            if (idx != 0x7fffffff) atomicMin(&s_nxt[par], idx);
        }
        __syncthreads();                           // B

        cur = s_nxt[par];
        if ((cur & 511) == t) cum[cur >> 9] = NEG; // permanently mask winner
        if (t == 0) {
            float* c = &g_centers[(b * Ss + step) * 3];
            c[0] = sx[cur]; c[1] = sy[cur]; c[2] = sz[cur];
        }
    }
}

// ---------------- ball query: 8 warps/block, pos tile in SMEM -------------------
__global__ __launch_bounds__(256) void ballquery_kernel(const float* __restrict__ pos) {
    extern __shared__ float dynq[];
    float* sx = dynq;
    float* sy = dynq + Nn;
    float* sz = dynq + 2 * Nn;

    int b  = blockIdx.x >> 7;
    int s0 = (blockIdx.x & 127) * 8;
    const float* P = pos + b * 3 * Nn;
    for (int i = threadIdx.x; i < Nn; i += 256) {
        sx[i] = P[i]; sy[i] = P[Nn + i]; sz[i] = P[2 * Nn + i];
    }
    __syncthreads();

    int warp = threadIdx.x >> 5, lane = threadIdx.x & 31;
    int bs = b * Ss + s0 + warp;
    float cx = g_centers[bs * 3 + 0];
    float cy = g_centers[bs * 3 + 1];
    float cz = g_centers[bs * 3 + 2];
    float csq = cx * cx + cy * cy + cz * cz;

    int cnt = 0, first = 0;
    int* G = &g_gi[bs * Kk];
    unsigned lanemask = (1u << lane) - 1u;
    for (int j0 = 0; j0 < Nn; j0 += 32) {
        int j = j0 + lane;
        float x = sx[j], y = sy[j], z = sz[j];
        float dot = cx * x + cy * y + cz * z;
        float psq = x * x + y * y + z * z;
        float d = -2.0f * dot + csq + psq;
        bool ok = !(d > RAD2);
        unsigned m = __ballot_sync(0xffffffffu, ok);
        if (cnt == 0 && m) first = j0 + __ffs(m) - 1;
        int p = cnt + __popc(m & lanemask);
        if (ok && p < Kk) G[p] = j;
        cnt += __popc(m);
        if (cnt >= Kk) break;
    }
    for (int p = cnt + lane; p < Kk; p += 32) G[p] = first;
}

// ---------------- conv0: gather(67ch) -> 64, + BN stats -------------------------
__global__ __launch_bounds__(256) void conv0_kernel(const float* __restrict__ pos,
                                                    const float* __restrict__ w0,
                                                    const float* __restrict__ b0) {
    __shared__ float wT[67 * 64];
    __shared__ float xs[2][32][68];
    __shared__ int   sgi[64];
    __shared__ float sc[2][3];
    __shared__ float ssum[64], ssq[64];

    int t = threadIdx.x;
    int bs0 = blockIdx.x * 2;
    for (int e = t; e < 67 * 64; e += 256) {
        int o = e & 63, i = e >> 6;
        wT[i * 64 + o] = w0[o * 67 + i];
    }
    if (t < 64) sgi[t] = g_gi[bs0 * Kk + t];
    if (t < 6)  sc[t / 3][t % 3] = g_centers[bs0 * 3 + t];
    if (t < 64) { ssum[t] = 0.f; ssq[t] = 0.f; }
    __syncthreads();

    int b = bs0 >> 10;
    const float* Pb = pos + b * 3 * Nn;
    for (int e = t; e < 2 * 32 * 67; e += 256) {
        int g = e / (32 * 67);
        int r = e - g * (32 * 67);
        int h = r / 67;
        int i = r - h * 67;
        int idx = sgi[g * 32 + h];
        float v;
        if (i < 3) v = Pb[i * Nn + idx] - sc[g][i];
        else       v = g_featT[(b * Nn + idx) * 64 + (i - 3)];
        xs[g][h][i] = v;
    }
    __syncthreads();

    int om = (t & 15) * 4;
    int hg = t >> 4;
    int g  = hg >> 3;
    int h4 = (hg & 7) * 4;

    float acc[4][4];
#pragma unroll
    for (int a = 0; a < 4; a++)
#pragma unroll
        for (int j = 0; j < 4; j++) acc[a][j] = 0.f;

    for (int i = 0; i < 67; i++) {
        float4 wv = *(const float4*)&wT[i * 64 + om];
        float xr0 = xs[g][h4 + 0][i];
        float xr1 = xs[g][h4 + 1][i];
        float xr2 = xs[g][h4 + 2][i];
        float xr3 = xs[g][h4 + 3][i];
        acc[0][0] += xr0 * wv.x; acc[0][1] += xr0 * wv.y; acc[0][2] += xr0 * wv.z; acc[0][3] += xr0 * wv.w;
        acc[1][0] += xr1 * wv.x; acc[1][1] += xr1 * wv.y; acc[1][2] += xr1 * wv.z; acc[1][3] += xr1 * wv.w;
        acc[2][0] += xr2 * wv.x; acc[2][1] += xr2 * wv.y; acc[2][2] += xr2 * wv.z; acc[2][3] += xr2 * wv.w;
        acc[3][0] += xr3 * wv.x; acc[3][1] += xr3 * wv.y; acc[3][2] += xr3 * wv.z; acc[3][3] += xr3 * wv.w;
    }

    float4 bias4 = *(const float4*)&b0[om];
    float ls[4] = {0, 0, 0, 0}, lq[4] = {0, 0, 0, 0};
    int bs = bs0 + g;
#pragma unroll
    for (int hh = 0; hh < 4; hh++) {
        float4 v;
        v.x = acc[hh][0] + bias4.x;
        v.y = acc[hh][1] + bias4.y;
        v.z = acc[hh][2] + bias4.z;
        v.w = acc[hh][3] + bias4.w;
        ls[0] += v.x; lq[0] += v.x * v.x;
        ls[1] += v.y; lq[1] += v.y * v.y;
        ls[2] += v.z; lq[2] += v.z * v.z;
        ls[3] += v.w; lq[3] += v.w * v.w;
        *(float4*)&g_y0[(bs * 32 + h4 + hh) * 64 + om] = v;
    }
#pragma unroll
    for (int j = 0; j < 4; j++) {
        atomicAdd(&ssum[om + j], ls[j]);
        atomicAdd(&ssq[om + j],  lq[j]);
    }
    __syncthreads();
    if (t < 64) {
        atomicAdd(&g_sum0[t], ssum[t]);
        atomicAdd(&g_sq0[t],  ssq[t]);
    }
}

// ---------------- conv1: 64->64 with fused (inline) BN0+ReLU --------------------
__global__ __launch_bounds__(256) void conv1_kernel(const float* __restrict__ w1,
                                                    const float* __restrict__ b1,
                                                    const float* __restrict__ gam0,
                                                    const float* __restrict__ bet0) {
    __shared__ float wT[64 * 64];
    __shared__ float xs[2][32][64];
    __shared__ float ssum[64], ssq[64];
    __shared__ float s_scale[64], s_shift[64];

    int t = threadIdx.x;
    int bs0 = blockIdx.x * 2;
    for (int e = t; e < 64 * 64; e += 256) {
        int o = e & 63, i = e >> 6;
        wT[i * 64 + o] = w1[o * 64 + i];
    }
    if (t < 64) {
        ssum[t] = 0.f; ssq[t] = 0.f;
        float mean = g_sum0[t] * (1.0f / NELEM);
        float var  = g_sq0[t] * (1.0f / NELEM) - mean * mean;
        float s = gam0[t] * rsqrtf(var + 1e-5f);
        s_scale[t] = s;
        s_shift[t] = bet0[t] - mean * s;
    }
    __syncthreads();

    const float* Y = &g_y0[bs0 * 2048];
    float* xf = &xs[0][0][0];
    for (int e = t; e < 4096; e += 256) {
        int i = e & 63;
        float v = Y[e] * s_scale[i] + s_shift[i];
        xf[e] = fmaxf(v, 0.f);
    }
    __syncthreads();

    int om = (t & 15) * 4;
    int hg = t >> 4;
    int g  = hg >> 3;
    int h4 = (hg & 7) * 4;

    float acc[4][4];
#pragma unroll
    for (int a = 0; a < 4; a++)
#pragma unroll
        for (int j = 0; j < 4; j++) acc[a][j] = 0.f;

    for (int i = 0; i < 64; i++) {
        float4 wv = *(const float4*)&wT[i * 64 + om];
        float xr0 = xs[g][h4 + 0][i];
        float xr1 = xs[g][h4 + 1][i];
        float xr2 = xs[g][h4 + 2][i];
        float xr3 = xs[g][h4 + 3][i];
        acc[0][0] += xr0 * wv.x; acc[0][1] += xr0 * wv.y; acc[0][2] += xr0 * wv.z; acc[0][3] += xr0 * wv.w;
        acc[1][0] += xr1 * wv.x; acc[1][1] += xr1 * wv.y; acc[1][2] += xr1 * wv.z; acc[1][3] += xr1 * wv.w;
        acc[2][0] += xr2 * wv.x; acc[2][1] += xr2 * wv.y; acc[2][2] += xr2 * wv.z; acc[2][3] += xr2 * wv.w;
        acc[3][0] += xr3 * wv.x; acc[3][1] += xr3 * wv.y; acc[3][2] += xr3 * wv.z; acc[3][3] += xr3 * wv.w;
    }

    float4 bias4 = *(const float4*)&b1[om];
    float ls[4] = {0, 0, 0, 0}, lq[4] = {0, 0, 0, 0};
    int bs = bs0 + g;
#pragma unroll
    for (int hh = 0; hh < 4; hh++) {
        float4 v;
        v.x = acc[hh][0] + bias4.x;
        v.y = acc[hh][1] + bias4.y;
        v.z = acc[hh][2] + bias4.z;
        v.w = acc[hh][3] + bias4.w;
        ls[0] += v.x; lq[0] += v.x * v.x;
        ls[1] += v.y; lq[1] += v.y * v.y;
        ls[2] += v.z; lq[2] += v.z * v.z;
        ls[3] += v.w; lq[3] += v.w * v.w;
        *(float4*)&g_y1[(bs * 32 + h4 + hh) * 64 + om] = v;
    }
#pragma unroll
    for (int j = 0; j < 4; j++) {
        atomicAdd(&ssum[om + j], ls[j]);
        atomicAdd(&ssq[om + j],  lq[j]);
    }
    __syncthreads();
    if (t < 64) {
        atomicAdd(&g_sum1[t], ssum[t]);
        atomicAdd(&g_sq1[t],  ssq[t]);
    }
}

// ---------------- conv2: 64->128 with fused (inline) BN1+ReLU -------------------
__global__ __launch_bounds__(256) void conv2_kernel(const float* __restrict__ w2,
                                                    const float* __restrict__ b2,
                                                    const float* __restrict__ gam1,
                                                    const float* __restrict__ bet1) {
    __shared__ float wT[64 * 128];
    __shared__ float xs[32][64];
    __shared__ float ssum[128], ssq[128];
    __shared__ float s_scale[64], s_shift[64];

    int t = threadIdx.x;
    int bs = blockIdx.x;
    for (int e = t; e < 64 * 128; e += 256) {
        int o = e & 127, i = e >> 7;
        wT[i * 128 + o] = w2[o * 64 + i];
    }
    if (t < 128) { ssum[t] = 0.f; ssq[t] = 0.f; }
    if (t < 64) {
        float mean = g_sum1[t] * (1.0f / NELEM);
        float var  = g_sq1[t] * (1.0f / NELEM) - mean * mean;
        float s = gam1[t] * rsqrtf(var + 1e-5f);
        s_scale[t] = s;
        s_shift[t] = bet1[t] - mean * s;
    }
    __syncthreads();

    const float* Y = &g_y1[bs * 2048];
    float* xf = &xs[0][0];
    for (int e = t; e < 2048; e += 256) {
        int i = e & 63;
        float v = Y[e] * s_scale[i] + s_shift[i];
        xf[e] = fmaxf(v, 0.f);
    }
    __syncthreads();

    int om = (t & 31) * 4;
    int h4 = (t >> 5) * 4;

    float acc[4][4];
#pragma unroll
    for (int a = 0; a < 4; a++)
#pragma unroll
        for (int j = 0; j < 4; j++) acc[a][j] = 0.f;

    for (int i = 0; i < 64; i++) {
        float4 wv = *(const float4*)&wT[i * 128 + om];
        float xr0 = xs[h4 + 0][i];
        float xr1 = xs[h4 + 1][i];
        float xr2 = xs[h4 + 2][i];
        float xr3 = xs[h4 + 3][i];
        acc[0][0] += xr0 * wv.x; acc[0][1] += xr0 * wv.y; acc[0][2] += xr0 * wv.z; acc[0][3] += xr0 * wv.w;
        acc[1][0] += xr1 * wv.x; acc[1][1] += xr1 * wv.y; acc[1][2] += xr1 * wv.z; acc[1][3] += xr1 * wv.w;
        acc[2][0] += xr2 * wv.x; acc[2][1] += xr2 * wv.y; acc[2][2] += xr2 * wv.z; acc[2][3] += xr2 * wv.w;
        acc[3][0] += xr3 * wv.x; acc[3][1] += xr3 * wv.y; acc[3][2] += xr3 * wv.z; acc[3][3] += xr3 * wv.w;
    }

    float4 bias4 = *(const float4*)&b2[om];
    float ls[4] = {0, 0, 0, 0}, lq[4] = {0, 0, 0, 0};
#pragma unroll
    for (int hh = 0; hh < 4; hh++) {
        float4 v;
        v.x = acc[hh][0] + bias4.x;
        v.y = acc[hh][1] + bias4.y;
        v.z = acc[hh][2] + bias4.z;
        v.w = acc[hh][3] + bias4.w;
        ls[0] += v.x; lq[0] += v.x * v.x;
        ls[1] += v.y; lq[1] += v.y * v.y;
        ls[2] += v.z; lq[2] += v.z * v.z;
        ls[3] += v.w; lq[3] += v.w * v.w;
        *(float4*)&g_y2[(bs * 32 + h4 + hh) * 128 + om] = v;
    }
#pragma unroll
    for (int j = 0; j < 4; j++) {
        atomicAdd(&ssum[om + j], ls[j]);
        atomicAdd(&ssq[om + j],  lq[j]);
    }
    __syncthreads();
    if (t < 128) {
        atomicAdd(&g_sum2[t], ssum[t]);
        atomicAdd(&g_sq2[t],  ssq[t]);
    }
}

// ---------------- final: inline BN2 + ReLU + max over samples -> feat_out --------
__global__ __launch_bounds__(256) void finalpool_kernel(float* __restrict__ out,
                                                        const float* __restrict__ gam2,
                                                        const float* __restrict__ bet2) {
    __shared__ float s_sc[128], s_sh[128];
    int t = threadIdx.x;
    if (t < 128) {
        float mean = g_sum2[t] * (1.0f / NELEM);
        float var  = g_sq2[t] * (1.0f / NELEM) - mean * mean;
        float s = gam2[t] * rsqrtf(var + 1e-5f);
        s_sc[t] = s;
        s_sh[t] = bet2[t] - mean * s;
    }
    __syncthreads();

    int gwarp = (blockIdx.x * blockDim.x + t) >> 5;   // bs
    int lane = t & 31;
    if (gwarp >= Bb * Ss) return;
    int bs = gwarp;
    int b = bs >> 10, s = bs & 1023;

    float scl[4], sft[4];
#pragma unroll
    for (int j = 0; j < 4; j++) {
        scl[j] = s_sc[lane + 32 * j];
        sft[j] = s_sh[lane + 32 * j];
    }
    float m[4] = {-3.4e38f, -3.4e38f, -3.4e38f, -3.4e38f};
    const float* Y = &g_y2[bs * 32 * 128];
    for (int h = 0; h < 32; h++) {
#pragma unroll
        for (int j = 0; j < 4; j++) {
            float v = Y[h * 128 + lane + 32 * j] * scl[j] + sft[j];
            v = fmaxf(v, 0.f);
            m[j] = fmaxf(m[j], v);
        }
    }
    float* F = out + Bb * 3 * Ss + b * 128 * Ss + s;
#pragma unroll
    for (int j = 0; j < 4; j++) F[(lane + 32 * j) * Ss] = m[j];
}

// ---------------- pos_out copy --------------------------------------------------
__global__ void poscopy_kernel(float* __restrict__ out) {
    int e = blockIdx.x * blockDim.x + threadIdx.x;
    if (e >= Bb * 3 * Ss) return;
    int b = e / (3 * Ss);
    int r = e - b * (3 * Ss);
    int c = r / Ss;
    int s = r - c * Ss;
    out[e] = g_centers[(b * Ss + s) * 3 + c];
}

// ---------------- launch --------------------------------------------------------
extern "C" void kernel_launch(void* const* d_in, const int* in_sizes, int n_in,
                              void* d_out, int out_size) {
    const float* pos  = (const float*)d_in[0];
    const float* feat = (const float*)d_in[1];
    const float* w0   = (const float*)d_in[2];
    const float* b0   = (const float*)d_in[3];
    const float* g0   = (const float*)d_in[4];
    const float* be0  = (const float*)d_in[5];
    const float* w1   = (const float*)d_in[6];
    const float* b1   = (const float*)d_in[7];
    const float* g1   = (const float*)d_in[8];
    const float* be1  = (const float*)d_in[9];
    const float* w2   = (const float*)d_in[10];
    const float* b2   = (const float*)d_in[11];
    const float* g2   = (const float*)d_in[12];
    const float* be2  = (const float*)d_in[13];
    float* out = (float*)d_out;

    const int DYN = 3 * Nn * (int)sizeof(float);   // 48KB dynamic smem
    cudaFuncSetAttribute(fps_kernel,       cudaFuncAttributeMaxDynamicSharedMemorySize, DYN);
    cudaFuncSetAttribute(ballquery_kernel, cudaFuncAttributeMaxDynamicSharedMemorySize, DYN);

    zero_stats_kernel<<<1, 128>>>();
    transpose_feat_kernel<<<(Bb * Nn * Dd) / 256, 256>>>(feat);
    fps_kernel<<<Bb, 512, DYN>>>(pos);
    ballquery_kernel<<<1024, 256, DYN>>>(pos);
    conv0_kernel<<<Bb * Ss / 2, 256>>>(pos, w0, b0);
    conv1_kernel<<<Bb * Ss / 2, 256>>>(w1, b1, g0, be0);
    conv2_kernel<<<Bb * Ss, 256>>>(w2, b2, g1, be1);
    finalpool_kernel<<<Bb * Ss / 8, 256>>>(out, g2, be2);
    poscopy_kernel<<<(Bb * 3 * Ss + 255) / 256, 256>>>(out);
}

// round 4
// speedup vs baseline: 1.3800x; 1.0390x over previous
#include <cuda_runtime.h>
#include <cuda_bf16.h>
#include <cstdint>

#define Bb 8
#define Nn 4096
#define Dd 64
#define Ss 1024
#define Kk 32
#define RAD2 0.04f
#define NELEM 262144.0f   // B*32*S elements per channel for BN

// ---------------- scratch (device globals; no allocation allowed) ----------------
__device__ float g_featT[Bb * Nn * Dd];            // [b][n][c] point-major features
__device__ float g_centers[Bb * Ss * 3];           // [bs][3]
__device__ int   g_gi[Bb * Ss * Kk];
__device__ float g_y0[Bb * Ss * Kk * 64];          // [bs][h][o]
__device__ float g_y1[Bb * Ss * Kk * 64];
__device__ float g_y2[Bb * Ss * Kk * 128];
__device__ float g_sum0[64],  g_sq0[64];
__device__ float g_sum1[64],  g_sq1[64];
__device__ float g_sum2[128], g_sq2[128];

// ---------------- packed f32x2 helpers ----------------
union FU { float2 f; unsigned long long u; };

__device__ __forceinline__ unsigned long long add2(unsigned long long a, unsigned long long b) {
    unsigned long long d;
    asm("add.rn.f32x2 %0, %1, %2;" : "=l"(d) : "l"(a), "l"(b));
    return d;
}
__device__ __forceinline__ unsigned long long mul2(unsigned long long a, unsigned long long b) {
    unsigned long long d;
    asm("mul.rn.f32x2 %0, %1, %2;" : "=l"(d) : "l"(a), "l"(b));
    return d;
}
__device__ __forceinline__ unsigned long long fma2(unsigned long long a, unsigned long long b,
                                                   unsigned long long c) {
    unsigned long long d;
    asm("fma.rn.f32x2 %0, %1, %2, %3;" : "=l"(d) : "l"(a), "l"(b), "l"(c));
    return d;
}

// ---------------- zero stats ----------------
__global__ void zero_stats_kernel() {
    int t = threadIdx.x;
    if (t < 64)  { g_sum0[t] = 0.f; g_sq0[t] = 0.f; g_sum1[t] = 0.f; g_sq1[t] = 0.f; }
    if (t < 128) { g_sum2[t] = 0.f; g_sq2[t] = 0.f; }
}

// ---------------- feature transpose: (B,64,N) -> (B,N,64) ----------------
__global__ void transpose_feat_kernel(const float* __restrict__ feat) {
    int e = blockIdx.x * blockDim.x + threadIdx.x;   // 2,097,152 elements
    if (e >= Bb * Nn * Dd) return;
    int c = e & 63;
    int n = (e >> 6) & (Nn - 1);
    int b = e >> 18;
    g_featT[e] = feat[b * (Dd * Nn) + c * Nn + n];
}

// ---------------- FPS: one block per batch, 256 threads, 16 pts/thread ----------
// Packed f32x2 scan + REDUX warp max + smem-array cross-warp max (no shared atomics
// on the hot path). Point cache in dynamic smem (48KB).
__global__ __launch_bounds__(256) void fps_kernel(const float* __restrict__ pos) {
    extern __shared__ float dyn[];
    float* sx = dyn;
    float* sy = dyn + Nn;
    float* sz = dyn + 2 * Nn;

    __shared__ unsigned s_mv[8];
    __shared__ int      s_nxt[2];

    int b = blockIdx.x;
    const float* P = pos + b * 3 * Nn;
    int t = threadIdx.x;
    int warp = t >> 5, lane = t & 31;

    // point n -> thread (n & 255), slot (n >> 8); pair j covers slots 2j (.x), 2j+1 (.y)
    FU px2[8], py2[8], pz2[8], cum[8];
#pragma unroll
    for (int j = 0; j < 8; j++) {
        int n0 = t + 256 * (2 * j);
        int n1 = n0 + 256;
        px2[j].f.x = P[n0];          px2[j].f.y = P[n1];
        py2[j].f.x = P[Nn + n0];     py2[j].f.y = P[Nn + n1];
        pz2[j].f.x = P[2 * Nn + n0]; pz2[j].f.y = P[2 * Nn + n1];
        sx[n0] = px2[j].f.x; sx[n1] = px2[j].f.y;
        sy[n0] = py2[j].f.x; sy[n1] = py2[j].f.y;
        sz[n0] = pz2[j].f.x; sz[n1] = pz2[j].f.y;
        cum[j].f.x = 0.f; cum[j].f.y = 0.f;
    }

    const float NEG = -3.4e38f;
    if (t == 0) {
        cum[0].f.x = NEG;                          // point 0 pre-selected
        float* c = &g_centers[(b * Ss) * 3];
        c[0] = px2[0].f.x; c[1] = py2[0].f.x; c[2] = pz2[0].f.x;
        s_nxt[0] = 0x7fffffff; s_nxt[1] = 0x7fffffff;
    }
    __syncthreads();

    int cur = 0;
    for (int step = 1; step < Ss; step++) {
        int par = step & 1;
        float cx = sx[cur], cy = sy[cur], cz = sz[cur];
        FU ncx, ncy, ncz;
        ncx.f.x = -cx; ncx.f.y = -cx;
        ncy.f.x = -cy; ncy.f.y = -cy;
        ncz.f.x = -cz; ncz.f.y = -cz;

        float m = NEG;
#pragma unroll
        for (int j = 0; j < 8; j++) {
            unsigned long long dx = add2(px2[j].u, ncx.u);
            unsigned long long dy = add2(py2[j].u, ncy.u);
            unsigned long long dz = add2(pz2[j].u, ncz.u);
            unsigned long long s  = mul2(dy, dy);
            s = fma2(dx, dx, s);
            s = fma2(dz, dz, s);
            cum[j].u = add2(cum[j].u, s);
            m = fmaxf(m, cum[j].f.x);
            m = fmaxf(m, cum[j].f.y);
        }

        // monotone float->uint encode, then HW warp reduce
        unsigned um = __float_as_uint(m);
        um = (um & 0x80000000u) ? ~um : (um | 0x80000000u);
        unsigned uw = __reduce_max_sync(0xffffffffu, um);
        if (lane == 0) s_mv[warp] = uw;
        __syncthreads();                           // A

        if (t == 0) s_nxt[par ^ 1] = 0x7fffffff;

        unsigned bum = s_mv[0];
#pragma unroll
        for (int w = 1; w < 8; w++) bum = max(bum, s_mv[w]);

        if (uw == bum) {                           // winning warp(s) only
            unsigned xu = (bum & 0x80000000u) ? (bum & 0x7fffffffu) : ~bum;
            float mb = __uint_as_float(xu);
            int idx = 0x7fffffff;
#pragma unroll
            for (int j = 0; j < 8; j++) {
                if (cum[j].f.x == mb) idx = min(idx, t + 256 * (2 * j));
                if (cum[j].f.y == mb) idx = min(idx, t + 256 * (2 * j) + 256);
            }
            if (idx != 0x7fffffff) atomicMin(&s_nxt[par], idx);
        }
        __syncthreads();                           // B

        cur = s_nxt[par];
        if ((cur & 255) == t) {                    // single warp takes this branch
            int j0 = cur >> 9;
            int hi = (cur >> 8) & 1;
#pragma unroll
            for (int j = 0; j < 8; j++)
                if (j == j0) { if (hi) cum[j].f.y = NEG; else cum[j].f.x = NEG; }
            float* c = &g_centers[(b * Ss + step) * 3];
            c[0] = sx[cur]; c[1] = sy[cur]; c[2] = sz[cur];
        }
    }
}

// ---------------- ball query: 8 warps/block, pos tile in SMEM -------------------
__global__ __launch_bounds__(256) void ballquery_kernel(const float* __restrict__ pos) {
    extern __shared__ float dynq[];
    float* sx = dynq;
    float* sy = dynq + Nn;
    float* sz = dynq + 2 * Nn;

    int b  = blockIdx.x >> 7;
    int s0 = (blockIdx.x & 127) * 8;
    const float* P = pos + b * 3 * Nn;
    for (int i = threadIdx.x; i < Nn; i += 256) {
        sx[i] = P[i]; sy[i] = P[Nn + i]; sz[i] = P[2 * Nn + i];
    }
    __syncthreads();

    int warp = threadIdx.x >> 5, lane = threadIdx.x & 31;
    int bs = b * Ss + s0 + warp;
    float cx = g_centers[bs * 3 + 0];
    float cy = g_centers[bs * 3 + 1];
    float cz = g_centers[bs * 3 + 2];
    float csq = cx * cx + cy * cy + cz * cz;

    int cnt = 0, first = 0;
    int* G = &g_gi[bs * Kk];
    unsigned lanemask = (1u << lane) - 1u;
    for (int j0 = 0; j0 < Nn; j0 += 32) {
        int j = j0 + lane;
        float x = sx[j], y = sy[j], z = sz[j];
        float dot = cx * x + cy * y + cz * z;
        float psq = x * x + y * y + z * z;
        float d = -2.0f * dot + csq + psq;
        bool ok = !(d > RAD2);
        unsigned m = __ballot_sync(0xffffffffu, ok);
        if (cnt == 0 && m) first = j0 + __ffs(m) - 1;
        int p = cnt + __popc(m & lanemask);
        if (ok && p < Kk) G[p] = j;
        cnt += __popc(m);
        if (cnt >= Kk) break;
    }
    for (int p = cnt + lane; p < Kk; p += 32) G[p] = first;
}

// ---------------- conv0: gather(67ch) -> 64, + BN stats -------------------------
__global__ __launch_bounds__(256) void conv0_kernel(const float* __restrict__ pos,
                                                    const float* __restrict__ w0,
                                                    const float* __restrict__ b0) {
    __shared__ float wT[67 * 64];
    __shared__ float xs[2][32][68];
    __shared__ int   sgi[64];
    __shared__ float sc[2][3];
    __shared__ float ssum[64], ssq[64];

    int t = threadIdx.x;
    int bs0 = blockIdx.x * 2;
    for (int e = t; e < 67 * 64; e += 256) {
        int o = e & 63, i = e >> 6;
        wT[i * 64 + o] = w0[o * 67 + i];
    }
    if (t < 64) sgi[t] = g_gi[bs0 * Kk + t];
    if (t < 6)  sc[t / 3][t % 3] = g_centers[bs0 * 3 + t];
    if (t < 64) { ssum[t] = 0.f; ssq[t] = 0.f; }
    __syncthreads();

    int b = bs0 >> 10;
    const float* Pb = pos + b * 3 * Nn;
    for (int e = t; e < 2 * 32 * 67; e += 256) {
        int g = e / (32 * 67);
        int r = e - g * (32 * 67);
        int h = r / 67;
        int i = r - h * 67;
        int idx = sgi[g * 32 + h];
        float v;
        if (i < 3) v = Pb[i * Nn + idx] - sc[g][i];
        else       v = g_featT[(b * Nn + idx) * 64 + (i - 3)];
        xs[g][h][i] = v;
    }
    __syncthreads();

    int om = (t & 15) * 4;
    int hg = t >> 4;
    int g  = hg >> 3;
    int h4 = (hg & 7) * 4;

    float acc[4][4];
#pragma unroll
    for (int a = 0; a < 4; a++)
#pragma unroll
        for (int j = 0; j < 4; j++) acc[a][j] = 0.f;

    for (int i = 0; i < 67; i++) {
        float4 wv = *(const float4*)&wT[i * 64 + om];
        float xr0 = xs[g][h4 + 0][i];
        float xr1 = xs[g][h4 + 1][i];
        float xr2 = xs[g][h4 + 2][i];
        float xr3 = xs[g][h4 + 3][i];
        acc[0][0] += xr0 * wv.x; acc[0][1] += xr0 * wv.y; acc[0][2] += xr0 * wv.z; acc[0][3] += xr0 * wv.w;
        acc[1][0] += xr1 * wv.x; acc[1][1] += xr1 * wv.y; acc[1][2] += xr1 * wv.z; acc[1][3] += xr1 * wv.w;
        acc[2][0] += xr2 * wv.x; acc[2][1] += xr2 * wv.y; acc[2][2] += xr2 * wv.z; acc[2][3] += xr2 * wv.w;
        acc[3][0] += xr3 * wv.x; acc[3][1] += xr3 * wv.y; acc[3][2] += xr3 * wv.z; acc[3][3] += xr3 * wv.w;
    }

    float4 bias4 = *(const float4*)&b0[om];
    float ls[4] = {0, 0, 0, 0}, lq[4] = {0, 0, 0, 0};
    int bs = bs0 + g;
#pragma unroll
    for (int hh = 0; hh < 4; hh++) {
        float4 v;
        v.x = acc[hh][0] + bias4.x;
        v.y = acc[hh][1] + bias4.y;
        v.z = acc[hh][2] + bias4.z;
        v.w = acc[hh][3] + bias4.w;
        ls[0] += v.x; lq[0] += v.x * v.x;
        ls[1] += v.y; lq[1] += v.y * v.y;
        ls[2] += v.z; lq[2] += v.z * v.z;
        ls[3] += v.w; lq[3] += v.w * v.w;
        *(float4*)&g_y0[(bs * 32 + h4 + hh) * 64 + om] = v;
    }
#pragma unroll
    for (int j = 0; j < 4; j++) {
        atomicAdd(&ssum[om + j], ls[j]);
        atomicAdd(&ssq[om + j],  lq[j]);
    }
    __syncthreads();
    if (t < 64) {
        atomicAdd(&g_sum0[t], ssum[t]);
        atomicAdd(&g_sq0[t],  ssq[t]);
    }
}

// ---------------- conv1: 64->64 with fused (inline) BN0+ReLU --------------------
__global__ __launch_bounds__(256) void conv1_kernel(const float* __restrict__ w1,
                                                    const float* __restrict__ b1,
                                                    const float* __restrict__ gam0,
                                                    const float* __restrict__ bet0) {
    __shared__ float wT[64 * 64];
    __shared__ float xs[2][32][64];
    __shared__ float ssum[64], ssq[64];
    __shared__ float s_scale[64], s_shift[64];

    int t = threadIdx.x;
    int bs0 = blockIdx.x * 2;
    for (int e = t; e < 64 * 64; e += 256) {
        int o = e & 63, i = e >> 6;
        wT[i * 64 + o] = w1[o * 64 + i];
    }
    if (t < 64) {
        ssum[t] = 0.f; ssq[t] = 0.f;
        float mean = g_sum0[t] * (1.0f / NELEM);
        float var  = g_sq0[t] * (1.0f / NELEM) - mean * mean;
        float s = gam0[t] * rsqrtf(var + 1e-5f);
        s_scale[t] = s;
        s_shift[t] = bet0[t] - mean * s;
    }
    __syncthreads();

    const float* Y = &g_y0[bs0 * 2048];
    float* xf = &xs[0][0][0];
    for (int e = t; e < 4096; e += 256) {
        int i = e & 63;
        float v = Y[e] * s_scale[i] + s_shift[i];
        xf[e] = fmaxf(v, 0.f);
    }
    __syncthreads();

    int om = (t & 15) * 4;
    int hg = t >> 4;
    int g  = hg >> 3;
    int h4 = (hg & 7) * 4;

    float acc[4][4];
#pragma unroll
    for (int a = 0; a < 4; a++)
#pragma unroll
        for (int j = 0; j < 4; j++) acc[a][j] = 0.f;

    for (int i = 0; i < 64; i++) {
        float4 wv = *(const float4*)&wT[i * 64 + om];
        float xr0 = xs[g][h4 + 0][i];
        float xr1 = xs[g][h4 + 1][i];
        float xr2 = xs[g][h4 + 2][i];
        float xr3 = xs[g][h4 + 3][i];
        acc[0][0] += xr0 * wv.x; acc[0][1] += xr0 * wv.y; acc[0][2] += xr0 * wv.z; acc[0][3] += xr0 * wv.w;
        acc[1][0] += xr1 * wv.x; acc[1][1] += xr1 * wv.y; acc[1][2] += xr1 * wv.z; acc[1][3] += xr1 * wv.w;
        acc[2][0] += xr2 * wv.x; acc[2][1] += xr2 * wv.y; acc[2][2] += xr2 * wv.z; acc[2][3] += xr2 * wv.w;
        acc[3][0] += xr3 * wv.x; acc[3][1] += xr3 * wv.y; acc[3][2] += xr3 * wv.z; acc[3][3] += xr3 * wv.w;
    }

    float4 bias4 = *(const float4*)&b1[om];
    float ls[4] = {0, 0, 0, 0}, lq[4] = {0, 0, 0, 0};
    int bs = bs0 + g;
#pragma unroll
    for (int hh = 0; hh < 4; hh++) {
        float4 v;
        v.x = acc[hh][0] + bias4.x;
        v.y = acc[hh][1] + bias4.y;
        v.z = acc[hh][2] + bias4.z;
        v.w = acc[hh][3] + bias4.w;
        ls[0] += v.x; lq[0] += v.x * v.x;
        ls[1] += v.y; lq[1] += v.y * v.y;
        ls[2] += v.z; lq[2] += v.z * v.z;
        ls[3] += v.w; lq[3] += v.w * v.w;
        *(float4*)&g_y1[(bs * 32 + h4 + hh) * 64 + om] = v;
    }
#pragma unroll
    for (int j = 0; j < 4; j++) {
        atomicAdd(&ssum[om + j], ls[j]);
        atomicAdd(&ssq[om + j],  lq[j]);
    }
    __syncthreads();
    if (t < 64) {
        atomicAdd(&g_sum1[t], ssum[t]);
        atomicAdd(&g_sq1[t],  ssq[t]);
    }
}

// ---------------- conv2: 64->128 with fused (inline) BN1+ReLU -------------------
__global__ __launch_bounds__(256) void conv2_kernel(const float* __restrict__ w2,
                                                    const float* __restrict__ b2,
                                                    const float* __restrict__ gam1,
                                                    const float* __restrict__ bet1) {
    __shared__ float wT[64 * 128];
    __shared__ float xs[32][64];
    __shared__ float ssum[128], ssq[128];
    __shared__ float s_scale[64], s_shift[64];

    int t = threadIdx.x;
    int bs = blockIdx.x;
    for (int e = t; e < 64 * 128; e += 256) {
        int o = e & 127, i = e >> 7;
        wT[i * 128 + o] = w2[o * 64 + i];
    }
    if (t < 128) { ssum[t] = 0.f; ssq[t] = 0.f; }
    if (t < 64) {
        float mean = g_sum1[t] * (1.0f / NELEM);
        float var  = g_sq1[t] * (1.0f / NELEM) - mean * mean;
        float s = gam1[t] * rsqrtf(var + 1e-5f);
        s_scale[t] = s;
        s_shift[t] = bet1[t] - mean * s;
    }
    __syncthreads();

    const float* Y = &g_y1[bs * 2048];
    float* xf = &xs[0][0];
    for (int e = t; e < 2048; e += 256) {
        int i = e & 63;
        float v = Y[e] * s_scale[i] + s_shift[i];
        xf[e] = fmaxf(v, 0.f);
    }
    __syncthreads();

    int om = (t & 31) * 4;
    int h4 = (t >> 5) * 4;

    float acc[4][4];
#pragma unroll
    for (int a = 0; a < 4; a++)
#pragma unroll
        for (int j = 0; j < 4; j++) acc[a][j] = 0.f;

    for (int i = 0; i < 64; i++) {
        float4 wv = *(const float4*)&wT[i * 128 + om];
        float xr0 = xs[h4 + 0][i];
        float xr1 = xs[h4 + 1][i];
        float xr2 = xs[h4 + 2][i];
        float xr3 = xs[h4 + 3][i];
        acc[0][0] += xr0 * wv.x; acc[0][1] += xr0 * wv.y; acc[0][2] += xr0 * wv.z; acc[0][3] += xr0 * wv.w;
        acc[1][0] += xr1 * wv.x; acc[1][1] += xr1 * wv.y; acc[1][2] += xr1 * wv.z; acc[1][3] += xr1 * wv.w;
        acc[2][0] += xr2 * wv.x; acc[2][1] += xr2 * wv.y; acc[2][2] += xr2 * wv.z; acc[2][3] += xr2 * wv.w;
        acc[3][0] += xr3 * wv.x; acc[3][1] += xr3 * wv.y; acc[3][2] += xr3 * wv.z; acc[3][3] += xr3 * wv.w;
    }

    float4 bias4 = *(const float4*)&b2[om];
    float ls[4] = {0, 0, 0, 0}, lq[4] = {0, 0, 0, 0};
#pragma unroll
    for (int hh = 0; hh < 4; hh++) {
        float4 v;
        v.x = acc[hh][0] + bias4.x;
        v.y = acc[hh][1] + bias4.y;
        v.z = acc[hh][2] + bias4.z;
        v.w = acc[hh][3] + bias4.w;
        ls[0] += v.x; lq[0] += v.x * v.x;
        ls[1] += v.y; lq[1] += v.y * v.y;
        ls[2] += v.z; lq[2] += v.z * v.z;
        ls[3] += v.w; lq[3] += v.w * v.w;
        *(float4*)&g_y2[(bs * 32 + h4 + hh) * 128 + om] = v;
    }
#pragma unroll
    for (int j = 0; j < 4; j++) {
        atomicAdd(&ssum[om + j], ls[j]);
        atomicAdd(&ssq[om + j],  lq[j]);
    }
    __syncthreads();
    if (t < 128) {
        atomicAdd(&g_sum2[t], ssum[t]);
        atomicAdd(&g_sq2[t],  ssq[t]);
    }
}

// ---------------- final: inline BN2 + ReLU + max over samples -> feat_out --------
__global__ __launch_bounds__(256) void finalpool_kernel(float* __restrict__ out,
                                                        const float* __restrict__ gam2,
                                                        const float* __restrict__ bet2) {
    __shared__ float s_sc[128], s_sh[128];
    int t = threadIdx.x;
    if (t < 128) {
        float mean = g_sum2[t] * (1.0f / NELEM);
        float var  = g_sq2[t] * (1.0f / NELEM) - mean * mean;
        float s = gam2[t] * rsqrtf(var + 1e-5f);
        s_sc[t] = s;
        s_sh[t] = bet2[t] - mean * s;
    }
    __syncthreads();

    int gwarp = (blockIdx.x * blockDim.x + t) >> 5;   // bs
    int lane = t & 31;
    if (gwarp >= Bb * Ss) return;
    int bs = gwarp;
    int b = bs >> 10, s = bs & 1023;

    float scl[4], sft[4];
#pragma unroll
    for (int j = 0; j < 4; j++) {
        scl[j] = s_sc[lane + 32 * j];
        sft[j] = s_sh[lane + 32 * j];
    }
    float m[4] = {-3.4e38f, -3.4e38f, -3.4e38f, -3.4e38f};
    const float* Y = &g_y2[bs * 32 * 128];
    for (int h = 0; h < 32; h++) {
#pragma unroll
        for (int j = 0; j < 4; j++) {
            float v = Y[h * 128 + lane + 32 * j] * scl[j] + sft[j];
            v = fmaxf(v, 0.f);
            m[j] = fmaxf(m[j], v);
        }
    }
    float* F = out + Bb * 3 * Ss + b * 128 * Ss + s;
#pragma unroll
    for (int j = 0; j < 4; j++) F[(lane + 32 * j) * Ss] = m[j];
}

// ---------------- pos_out copy --------------------------------------------------
__global__ void poscopy_kernel(float* __restrict__ out) {
    int e = blockIdx.x * blockDim.x + threadIdx.x;
    if (e >= Bb * 3 * Ss) return;
    int b = e / (3 * Ss);
    int r = e - b * (3 * Ss);
    int c = r / Ss;
    int s = r - c * Ss;
    out[e] = g_centers[(b * Ss + s) * 3 + c];
}

// ---------------- launch --------------------------------------------------------
extern "C" void kernel_launch(void* const* d_in, const int* in_sizes, int n_in,
                              void* d_out, int out_size) {
    const float* pos  = (const float*)d_in[0];
    const float* feat = (const float*)d_in[1];
    const float* w0   = (const float*)d_in[2];
    const float* b0   = (const float*)d_in[3];
    const float* g0   = (const float*)d_in[4];
    const float* be0  = (const float*)d_in[5];
    const float* w1   = (const float*)d_in[6];
    const float* b1   = (const float*)d_in[7];
    const float* g1   = (const float*)d_in[8];
    const float* be1  = (const float*)d_in[9];
    const float* w2   = (const float*)d_in[10];
    const float* b2   = (const float*)d_in[11];
    const float* g2   = (const float*)d_in[12];
    const float* be2  = (const float*)d_in[13];
    float* out = (float*)d_out;

    const int DYN = 3 * Nn * (int)sizeof(float);   // 48KB dynamic smem
    cudaFuncSetAttribute(fps_kernel,       cudaFuncAttributeMaxDynamicSharedMemorySize, DYN);
    cudaFuncSetAttribute(ballquery_kernel, cudaFuncAttributeMaxDynamicSharedMemorySize, DYN);

    zero_stats_kernel<<<1, 128>>>();
    transpose_feat_kernel<<<(Bb * Nn * Dd) / 256, 256>>>(feat);
    fps_kernel<<<Bb, 256, DYN>>>(pos);
    ballquery_kernel<<<1024, 256, DYN>>>(pos);
    conv0_kernel<<<Bb * Ss / 2, 256>>>(pos, w0, b0);
    conv1_kernel<<<Bb * Ss / 2, 256>>>(w1, b1, g0, be0);
    conv2_kernel<<<Bb * Ss, 256>>>(w2, b2, g1, be1);
    finalpool_kernel<<<Bb * Ss / 8, 256>>>(out, g2, be2);
    poscopy_kernel<<<(Bb * 3 * Ss + 255) / 256, 256>>>(out);
}

// round 5
// speedup vs baseline: 1.4451x; 1.0472x over previous
#include <cuda_runtime.h>
#include <cuda_bf16.h>
#include <cstdint>

#define Bb 8
#define Nn 4096
#define Dd 64
#define Ss 1024
#define Kk 32
#define RAD2 0.04f
#define NELEM 262144.0f   // B*32*S elements per channel for BN

// ---------------- scratch (device globals; no allocation allowed) ----------------
__device__ float g_featT[Bb * Nn * Dd];            // [b][n][c] point-major features
__device__ float g_centers[Bb * Ss * 3];           // [bs][3]
__device__ int   g_gi[Bb * Ss * Kk];
__device__ float g_y0[Bb * Ss * Kk * 64];          // [bs][h][o]
__device__ float g_y1[Bb * Ss * Kk * 64];
__device__ float g_y2[Bb * Ss * Kk * 128];
__device__ float g_sum0[64],  g_sq0[64];
__device__ float g_sum1[64],  g_sq1[64];
__device__ float g_sum2[128], g_sq2[128];

// ---------------- zero stats ----------------
__global__ void zero_stats_kernel() {
    int t = threadIdx.x;
    if (t < 64)  { g_sum0[t] = 0.f; g_sq0[t] = 0.f; g_sum1[t] = 0.f; g_sq1[t] = 0.f; }
    if (t < 128) { g_sum2[t] = 0.f; g_sq2[t] = 0.f; }
}

// ---------------- feature transpose: (B,64,N) -> (B,N,64) ----------------
__global__ void transpose_feat_kernel(const float* __restrict__ feat) {
    int e = blockIdx.x * blockDim.x + threadIdx.x;   // 2,097,152 elements
    if (e >= Bb * Nn * Dd) return;
    int c = e & 63;
    int n = (e >> 6) & (Nn - 1);
    int b = e >> 18;
    g_featT[e] = feat[b * (Dd * Nn) + c * Nn + n];
}

// ---------------- FPS: one block per batch, 1024 threads, 4 pts/thread ----------
// 32 warps (8/SMSP) hide fp latency; scan runs near the fma-pipe issue floor.
// Per-warp REDUX max -> s_mv[32] -> one LDS+REDUX cross-warp max -> equality pass.
__global__ __launch_bounds__(1024) void fps_kernel(const float* __restrict__ pos) {
    extern __shared__ float dyn[];
    float* sx = dyn;
    float* sy = dyn + Nn;
    float* sz = dyn + 2 * Nn;

    __shared__ unsigned s_mv[32];
    __shared__ int      s_nxt[2];

    int b = blockIdx.x;
    const float* P = pos + b * 3 * Nn;
    int t = threadIdx.x;
    int warp = t >> 5, lane = t & 31;

    float px[4], py[4], pz[4], cum[4];
#pragma unroll
    for (int j = 0; j < 4; j++) {
        int n = t + 1024 * j;
        px[j] = P[n];
        py[j] = P[Nn + n];
        pz[j] = P[2 * Nn + n];
        sx[n] = px[j]; sy[n] = py[j]; sz[n] = pz[j];
        cum[j] = 0.f;
    }

    const float NEG = -3.4e38f;
    if (t == 0) {
        cum[0] = NEG;                              // point 0 pre-selected
        float* c = &g_centers[(b * Ss) * 3];
        c[0] = px[0]; c[1] = py[0]; c[2] = pz[0];
        s_nxt[0] = 0x7fffffff; s_nxt[1] = 0x7fffffff;
    }
    __syncthreads();

    int cur = 0;
    for (int step = 1; step < Ss; step++) {
        int par = step & 1;
        float cx = sx[cur], cy = sy[cur], cz = sz[cur];

        float m = NEG;
#pragma unroll
        for (int j = 0; j < 4; j++) {
            float dx = px[j] - cx, dy = py[j] - cy, dz = pz[j] - cz;
            float sqd = dx * dx + dy * dy + dz * dz;
            cum[j] = cum[j] + sqd;
            m = fmaxf(m, cum[j]);
        }

        // monotone float->uint encode, HW warp reduce
        unsigned um = __float_as_uint(m);
        um = (um & 0x80000000u) ? ~um : (um | 0x80000000u);
        unsigned uw = __reduce_max_sync(0xffffffffu, um);
        if (lane == 0) s_mv[warp] = uw;
        __syncthreads();                           // A

        if (t == 0) s_nxt[par ^ 1] = 0x7fffffff;

        // cross-warp max: every warp loads all 32 partials (1 LDS) + 1 REDUX
        unsigned bum = __reduce_max_sync(0xffffffffu, s_mv[lane]);

        if (uw == bum) {                           // winning warp(s) only
            unsigned xu = (bum & 0x80000000u) ? (bum & 0x7fffffffu) : ~bum;
            float mb = __uint_as_float(xu);
            int idx = 0x7fffffff;
#pragma unroll
            for (int j = 0; j < 4; j++)
                if (cum[j] == mb) idx = min(idx, t + 1024 * j);
            if (idx != 0x7fffffff) atomicMin(&s_nxt[par], idx);
        }
        __syncthreads();                           // B

        cur = s_nxt[par];
        if ((cur & 1023) == t) {                   // winner thread only
            int j0 = cur >> 10;
#pragma unroll
            for (int j = 0; j < 4; j++)
                if (j == j0) cum[j] = NEG;         // permanently mask winner
            float* c = &g_centers[(b * Ss + step) * 3];
            c[0] = sx[cur]; c[1] = sy[cur]; c[2] = sz[cur];
        }
    }
}

// ---------------- ball query: 16 warps/block, pos tile in SMEM ------------------
__global__ __launch_bounds__(512) void ballquery_kernel(const float* __restrict__ pos) {
    extern __shared__ float dynq[];
    float* sx = dynq;
    float* sy = dynq + Nn;
    float* sz = dynq + 2 * Nn;

    int b  = blockIdx.x >> 6;
    int s0 = (blockIdx.x & 63) * 16;
    const float* P = pos + b * 3 * Nn;
    for (int i = threadIdx.x; i < Nn; i += 512) {
        sx[i] = P[i]; sy[i] = P[Nn + i]; sz[i] = P[2 * Nn + i];
    }
    __syncthreads();

    int warp = threadIdx.x >> 5, lane = threadIdx.x & 31;
    int bs = b * Ss + s0 + warp;
    float cx = g_centers[bs * 3 + 0];
    float cy = g_centers[bs * 3 + 1];
    float cz = g_centers[bs * 3 + 2];
    float csq = cx * cx + cy * cy + cz * cz;

    int cnt = 0, first = 0;
    int* G = &g_gi[bs * Kk];
    unsigned lanemask = (1u << lane) - 1u;
    for (int j0 = 0; j0 < Nn; j0 += 32) {
        int j = j0 + lane;
        float x = sx[j], y = sy[j], z = sz[j];
        float dot = cx * x + cy * y + cz * z;
        float psq = x * x + y * y + z * z;
        float d = -2.0f * dot + csq + psq;
        bool ok = !(d > RAD2);
        unsigned m = __ballot_sync(0xffffffffu, ok);
        if (cnt == 0 && m) first = j0 + __ffs(m) - 1;
        int p = cnt + __popc(m & lanemask);
        if (ok && p < Kk) G[p] = j;
        cnt += __popc(m);
        if (cnt >= Kk) break;
    }
    for (int p = cnt + lane; p < Kk; p += 32) G[p] = first;
}

// ---------------- conv0: gather(67ch) -> 64, + BN stats -------------------------
__global__ __launch_bounds__(256) void conv0_kernel(const float* __restrict__ pos,
                                                    const float* __restrict__ w0,
                                                    const float* __restrict__ b0) {
    __shared__ float wT[67 * 64];
    __shared__ float xs[2][32][68];
    __shared__ int   sgi[64];
    __shared__ float sc[2][3];
    __shared__ float ssum[64], ssq[64];

    int t = threadIdx.x;
    int bs0 = blockIdx.x * 2;
    for (int e = t; e < 67 * 64; e += 256) {
        int o = e & 63, i = e >> 6;
        wT[i * 64 + o] = w0[o * 67 + i];
    }
    if (t < 64) sgi[t] = g_gi[bs0 * Kk + t];
    if (t < 6)  sc[t / 3][t % 3] = g_centers[bs0 * 3 + t];
    if (t < 64) { ssum[t] = 0.f; ssq[t] = 0.f; }
    __syncthreads();

    int b = bs0 >> 10;
    const float* Pb = pos + b * 3 * Nn;
    for (int e = t; e < 2 * 32 * 67; e += 256) {
        int g = e / (32 * 67);
        int r = e - g * (32 * 67);
        int h = r / 67;
        int i = r - h * 67;
        int idx = sgi[g * 32 + h];
        float v;
        if (i < 3) v = Pb[i * Nn + idx] - sc[g][i];
        else       v = g_featT[(b * Nn + idx) * 64 + (i - 3)];
        xs[g][h][i] = v;
    }
    __syncthreads();

    int om = (t & 15) * 4;
    int hg = t >> 4;
    int g  = hg >> 3;
    int h4 = (hg & 7) * 4;

    float acc[4][4];
#pragma unroll
    for (int a = 0; a < 4; a++)
#pragma unroll
        for (int j = 0; j < 4; j++) acc[a][j] = 0.f;

    for (int i = 0; i < 67; i++) {
        float4 wv = *(const float4*)&wT[i * 64 + om];
        float xr0 = xs[g][h4 + 0][i];
        float xr1 = xs[g][h4 + 1][i];
        float xr2 = xs[g][h4 + 2][i];
        float xr3 = xs[g][h4 + 3][i];
        acc[0][0] += xr0 * wv.x; acc[0][1] += xr0 * wv.y; acc[0][2] += xr0 * wv.z; acc[0][3] += xr0 * wv.w;
        acc[1][0] += xr1 * wv.x; acc[1][1] += xr1 * wv.y; acc[1][2] += xr1 * wv.z; acc[1][3] += xr1 * wv.w;
        acc[2][0] += xr2 * wv.x; acc[2][1] += xr2 * wv.y; acc[2][2] += xr2 * wv.z; acc[2][3] += xr2 * wv.w;
        acc[3][0] += xr3 * wv.x; acc[3][1] += xr3 * wv.y; acc[3][2] += xr3 * wv.z; acc[3][3] += xr3 * wv.w;
    }

    float4 bias4 = *(const float4*)&b0[om];
    float ls[4] = {0, 0, 0, 0}, lq[4] = {0, 0, 0, 0};
    int bs = bs0 + g;
#pragma unroll
    for (int hh = 0; hh < 4; hh++) {
        float4 v;
        v.x = acc[hh][0] + bias4.x;
        v.y = acc[hh][1] + bias4.y;
        v.z = acc[hh][2] + bias4.z;
        v.w = acc[hh][3] + bias4.w;
        ls[0] += v.x; lq[0] += v.x * v.x;
        ls[1] += v.y; lq[1] += v.y * v.y;
        ls[2] += v.z; lq[2] += v.z * v.z;
        ls[3] += v.w; lq[3] += v.w * v.w;
        *(float4*)&g_y0[(bs * 32 + h4 + hh) * 64 + om] = v;
    }
#pragma unroll
    for (int j = 0; j < 4; j++) {
        atomicAdd(&ssum[om + j], ls[j]);
        atomicAdd(&ssq[om + j],  lq[j]);
    }
    __syncthreads();
    if (t < 64) {
        atomicAdd(&g_sum0[t], ssum[t]);
        atomicAdd(&g_sq0[t],  ssq[t]);
    }
}

// ---------------- conv1: 64->64 with fused (inline) BN0+ReLU --------------------
__global__ __launch_bounds__(256) void conv1_kernel(const float* __restrict__ w1,
                                                    const float* __restrict__ b1,
                                                    const float* __restrict__ gam0,
                                                    const float* __restrict__ bet0) {
    __shared__ float wT[64 * 64];
    __shared__ float xs[2][32][64];
    __shared__ float ssum[64], ssq[64];
    __shared__ float s_scale[64], s_shift[64];

    int t = threadIdx.x;
    int bs0 = blockIdx.x * 2;
    for (int e = t; e < 64 * 64; e += 256) {
        int o = e & 63, i = e >> 6;
        wT[i * 64 + o] = w1[o * 64 + i];
    }
    if (t < 64) {
        ssum[t] = 0.f; ssq[t] = 0.f;
        float mean = g_sum0[t] * (1.0f / NELEM);
        float var  = g_sq0[t] * (1.0f / NELEM) - mean * mean;
        float s = gam0[t] * rsqrtf(var + 1e-5f);
        s_scale[t] = s;
        s_shift[t] = bet0[t] - mean * s;
    }
    __syncthreads();

    const float* Y = &g_y0[bs0 * 2048];
    float* xf = &xs[0][0][0];
    for (int e = t; e < 4096; e += 256) {
        int i = e & 63;
        float v = Y[e] * s_scale[i] + s_shift[i];
        xf[e] = fmaxf(v, 0.f);
    }
    __syncthreads();

    int om = (t & 15) * 4;
    int hg = t >> 4;
    int g  = hg >> 3;
    int h4 = (hg & 7) * 4;

    float acc[4][4];
#pragma unroll
    for (int a = 0; a < 4; a++)
#pragma unroll
        for (int j = 0; j < 4; j++) acc[a][j] = 0.f;

    for (int i = 0; i < 64; i++) {
        float4 wv = *(const float4*)&wT[i * 64 + om];
        float xr0 = xs[g][h4 + 0][i];
        float xr1 = xs[g][h4 + 1][i];
        float xr2 = xs[g][h4 + 2][i];
        float xr3 = xs[g][h4 + 3][i];
        acc[0][0] += xr0 * wv.x; acc[0][1] += xr0 * wv.y; acc[0][2] += xr0 * wv.z; acc[0][3] += xr0 * wv.w;
        acc[1][0] += xr1 * wv.x; acc[1][1] += xr1 * wv.y; acc[1][2] += xr1 * wv.z; acc[1][3] += xr1 * wv.w;
        acc[2][0] += xr2 * wv.x; acc[2][1] += xr2 * wv.y; acc[2][2] += xr2 * wv.z; acc[2][3] += xr2 * wv.w;
        acc[3][0] += xr3 * wv.x; acc[3][1] += xr3 * wv.y; acc[3][2] += xr3 * wv.z; acc[3][3] += xr3 * wv.w;
    }

    float4 bias4 = *(const float4*)&b1[om];
    float ls[4] = {0, 0, 0, 0}, lq[4] = {0, 0, 0, 0};
    int bs = bs0 + g;
#pragma unroll
    for (int hh = 0; hh < 4; hh++) {
        float4 v;
        v.x = acc[hh][0] + bias4.x;
        v.y = acc[hh][1] + bias4.y;
        v.z = acc[hh][2] + bias4.z;
        v.w = acc[hh][3] + bias4.w;
        ls[0] += v.x; lq[0] += v.x * v.x;
        ls[1] += v.y; lq[1] += v.y * v.y;
        ls[2] += v.z; lq[2] += v.z * v.z;
        ls[3] += v.w; lq[3] += v.w * v.w;
        *(float4*)&g_y1[(bs * 32 + h4 + hh) * 64 + om] = v;
    }
#pragma unroll
    for (int j = 0; j < 4; j++) {
        atomicAdd(&ssum[om + j], ls[j]);
        atomicAdd(&ssq[om + j],  lq[j]);
    }
    __syncthreads();
    if (t < 64) {
        atomicAdd(&g_sum1[t], ssum[t]);
        atomicAdd(&g_sq1[t],  ssq[t]);
    }
}

// ---------------- conv2: 64->128 with fused (inline) BN1+ReLU -------------------
__global__ __launch_bounds__(256) void conv2_kernel(const float* __restrict__ w2,
                                                    const float* __restrict__ b2,
                                                    const float* __restrict__ gam1,
                                                    const float* __restrict__ bet1) {
    __shared__ float wT[64 * 128];
    __shared__ float xs[32][64];
    __shared__ float ssum[128], ssq[128];
    __shared__ float s_scale[64], s_shift[64];

    int t = threadIdx.x;
    int bs = blockIdx.x;
    for (int e = t; e < 64 * 128; e += 256) {
        int o = e & 127, i = e >> 7;
        wT[i * 128 + o] = w2[o * 64 + i];
    }
    if (t < 128) { ssum[t] = 0.f; ssq[t] = 0.f; }
    if (t < 64) {
        float mean = g_sum1[t] * (1.0f / NELEM);
        float var  = g_sq1[t] * (1.0f / NELEM) - mean * mean;
        float s = gam1[t] * rsqrtf(var + 1e-5f);
        s_scale[t] = s;
        s_shift[t] = bet1[t] - mean * s;
    }
    __syncthreads();

    const float* Y = &g_y1[bs * 2048];
    float* xf = &xs[0][0];
    for (int e = t; e < 2048; e += 256) {
        int i = e & 63;
        float v = Y[e] * s_scale[i] + s_shift[i];
        xf[e] = fmaxf(v, 0.f);
    }
    __syncthreads();

    int om = (t & 31) * 4;
    int h4 = (t >> 5) * 4;

    float acc[4][4];
#pragma unroll
    for (int a = 0; a < 4; a++)
#pragma unroll
        for (int j = 0; j < 4; j++) acc[a][j] = 0.f;

    for (int i = 0; i < 64; i++) {
        float4 wv = *(const float4*)&wT[i * 128 + om];
        float xr0 = xs[h4 + 0][i];
        float xr1 = xs[h4 + 1][i];
        float xr2 = xs[h4 + 2][i];
        float xr3 = xs[h4 + 3][i];
        acc[0][0] += xr0 * wv.x; acc[0][1] += xr0 * wv.y; acc[0][2] += xr0 * wv.z; acc[0][3] += xr0 * wv.w;
        acc[1][0] += xr1 * wv.x; acc[1][1] += xr1 * wv.y; acc[1][2] += xr1 * wv.z; acc[1][3] += xr1 * wv.w;
        acc[2][0] += xr2 * wv.x; acc[2][1] += xr2 * wv.y; acc[2][2] += xr2 * wv.z; acc[2][3] += xr2 * wv.w;
        acc[3][0] += xr3 * wv.x; acc[3][1] += xr3 * wv.y; acc[3][2] += xr3 * wv.z; acc[3][3] += xr3 * wv.w;
    }

    float4 bias4 = *(const float4*)&b2[om];
    float ls[4] = {0, 0, 0, 0}, lq[4] = {0, 0, 0, 0};
#pragma unroll
    for (int hh = 0; hh < 4; hh++) {
        float4 v;
        v.x = acc[hh][0] + bias4.x;
        v.y = acc[hh][1] + bias4.y;
        v.z = acc[hh][2] + bias4.z;
        v.w = acc[hh][3] + bias4.w;
        ls[0] += v.x; lq[0] += v.x * v.x;
        ls[1] += v.y; lq[1] += v.y * v.y;
        ls[2] += v.z; lq[2] += v.z * v.z;
        ls[3] += v.w; lq[3] += v.w * v.w;
        *(float4*)&g_y2[(bs * 32 + h4 + hh) * 128 + om] = v;
    }
#pragma unroll
    for (int j = 0; j < 4; j++) {
        atomicAdd(&ssum[om + j], ls[j]);
        atomicAdd(&ssq[om + j],  lq[j]);
    }
    __syncthreads();
    if (t < 128) {
        atomicAdd(&g_sum2[t], ssum[t]);
        atomicAdd(&g_sq2[t],  ssq[t]);
    }
}

// ---------------- final: inline BN2 + ReLU + max over samples -> feat_out --------
__global__ __launch_bounds__(256) void finalpool_kernel(float* __restrict__ out,
                                                        const float* __restrict__ gam2,
                                                        const float* __restrict__ bet2) {
    __shared__ float s_sc[128], s_sh[128];
    int t = threadIdx.x;
    if (t < 128) {
        float mean = g_sum2[t] * (1.0f / NELEM);
        float var  = g_sq2[t] * (1.0f / NELEM) - mean * mean;
        float s = gam2[t] * rsqrtf(var + 1e-5f);
        s_sc[t] = s;
        s_sh[t] = bet2[t] - mean * s;
    }
    __syncthreads();

    int gwarp = (blockIdx.x * blockDim.x + t) >> 5;   // bs
    int lane = t & 31;
    if (gwarp >= Bb * Ss) return;
    int bs = gwarp;
    int b = bs >> 10, s = bs & 1023;

    float scl[4], sft[4];
#pragma unroll
    for (int j = 0; j < 4; j++) {
        scl[j] = s_sc[lane + 32 * j];
        sft[j] = s_sh[lane + 32 * j];
    }
    float m[4] = {-3.4e38f, -3.4e38f, -3.4e38f, -3.4e38f};
    const float* Y = &g_y2[bs * 32 * 128];
    for (int h = 0; h < 32; h++) {
#pragma unroll
        for (int j = 0; j < 4; j++) {
            float v = Y[h * 128 + lane + 32 * j] * scl[j] + sft[j];
            v = fmaxf(v, 0.f);
            m[j] = fmaxf(m[j], v);
        }
    }
    float* F = out + Bb * 3 * Ss + b * 128 * Ss + s;
#pragma unroll
    for (int j = 0; j < 4; j++) F[(lane + 32 * j) * Ss] = m[j];
}

// ---------------- pos_out copy --------------------------------------------------
__global__ void poscopy_kernel(float* __restrict__ out) {
    int e = blockIdx.x * blockDim.x + threadIdx.x;
    if (e >= Bb * 3 * Ss) return;
    int b = e / (3 * Ss);
    int r = e - b * (3 * Ss);
    int c = r / Ss;
    int s = r - c * Ss;
    out[e] = g_centers[(b * Ss + s) * 3 + c];
}

// ---------------- launch --------------------------------------------------------
extern "C" void kernel_launch(void* const* d_in, const int* in_sizes, int n_in,
                              void* d_out, int out_size) {
    const float* pos  = (const float*)d_in[0];
    const float* feat = (const float*)d_in[1];
    const float* w0   = (const float*)d_in[2];
    const float* b0   = (const float*)d_in[3];
    const float* g0   = (const float*)d_in[4];
    const float* be0  = (const float*)d_in[5];
    const float* w1   = (const float*)d_in[6];
    const float* b1   = (const float*)d_in[7];
    const float* g1   = (const float*)d_in[8];
    const float* be1  = (const float*)d_in[9];
    const float* w2   = (const float*)d_in[10];
    const float* b2   = (const float*)d_in[11];
    const float* g2   = (const float*)d_in[12];
    const float* be2  = (const float*)d_in[13];
    float* out = (float*)d_out;

    const int DYN = 3 * Nn * (int)sizeof(float);   // 48KB dynamic smem
    cudaFuncSetAttribute(fps_kernel,       cudaFuncAttributeMaxDynamicSharedMemorySize, DYN);
    cudaFuncSetAttribute(ballquery_kernel, cudaFuncAttributeMaxDynamicSharedMemorySize, DYN);

    zero_stats_kernel<<<1, 128>>>();
    transpose_feat_kernel<<<(Bb * Nn * Dd) / 256, 256>>>(feat);
    fps_kernel<<<Bb, 1024, DYN>>>(pos);
    ballquery_kernel<<<512, 512, DYN>>>(pos);
    conv0_kernel<<<Bb * Ss / 2, 256>>>(pos, w0, b0);
    conv1_kernel<<<Bb * Ss / 2, 256>>>(w1, b1, g0, be0);
    conv2_kernel<<<Bb * Ss, 256>>>(w2, b2, g1, be1);
    finalpool_kernel<<<Bb * Ss / 8, 256>>>(out, g2, be2);
    poscopy_kernel<<<(Bb * 3 * Ss + 255) / 256, 256>>>(out);
}

// round 7
// speedup vs baseline: 1.4804x; 1.0244x over previous
#include <cuda_runtime.h>
#include <cuda_bf16.h>
#include <cstdint>

#define Bb 8
#define Nn 4096
#define Dd 64
#define Ss 1024
#define Kk 32
#define RAD2 0.04f
#define NELEM 262144.0f   // B*32*S elements per channel for BN

// ---------------- scratch (device globals; no allocation allowed) ----------------
__device__ float g_featT[Bb * Nn * Dd];            // [b][n][c] point-major features
__device__ float g_centers[Bb * Ss * 3];           // [bs][3]
__device__ int   g_gi[Bb * Ss * Kk];
__device__ float g_y0[Bb * Ss * Kk * 64];          // [bs][h][o]
__device__ float g_y1[Bb * Ss * Kk * 64];
__device__ float g_y2[Bb * Ss * Kk * 128];
__device__ float g_sum0[64],  g_sq0[64];
__device__ float g_sum1[64],  g_sq1[64];
__device__ float g_sum2[128], g_sq2[128];

// ---------------- zero stats ----------------
__global__ void zero_stats_kernel() {
    int t = threadIdx.x;
    if (t < 64)  { g_sum0[t] = 0.f; g_sq0[t] = 0.f; g_sum1[t] = 0.f; g_sq1[t] = 0.f; }
    if (t < 128) { g_sum2[t] = 0.f; g_sq2[t] = 0.f; }
}

// ---------------- feature transpose: (B,64,N) -> (B,N,64) ----------------
__global__ void transpose_feat_kernel(const float* __restrict__ feat) {
    int e = blockIdx.x * blockDim.x + threadIdx.x;   // 2,097,152 elements
    if (e >= Bb * Nn * Dd) return;
    int c = e & 63;
    int n = (e >> 6) & (Nn - 1);
    int b = e >> 18;
    g_featT[e] = feat[b * (Dd * Nn) + c * Nn + n];
}

// ---------------- FPS: one block per batch, 512 threads, 8 pts/thread -----------
// SINGLE barrier per step: per-warp (value, min-index) packed into 64 bits,
// double-buffered smem array, cross-warp reduction via LDS.64 + 2 REDUX.
__global__ __launch_bounds__(512) void fps_kernel(const float* __restrict__ pos) {
    extern __shared__ float dyn[];
    float* sx = dyn;
    float* sy = dyn + Nn;
    float* sz = dyn + 2 * Nn;

    __shared__ unsigned long long s_mv[2][16];

    int b = blockIdx.x;
    const float* P = pos + b * 3 * Nn;
    int t = threadIdx.x;
    int warp = t >> 5, lane = t & 31;

    float px[8], py[8], pz[8], cum[8];
#pragma unroll
    for (int j = 0; j < 8; j++) {
        int n = t + 512 * j;
        px[j] = P[n];
        py[j] = P[Nn + n];
        pz[j] = P[2 * Nn + n];
        sx[n] = px[j]; sy[n] = py[j]; sz[n] = pz[j];
        cum[j] = 0.f;
    }

    const float NEG = -3.4e38f;
    if (t == 0) {
        cum[0] = NEG;                              // point 0 pre-selected
        float* c = &g_centers[(b * Ss) * 3];
        c[0] = px[0]; c[1] = py[0]; c[2] = pz[0];
    }
    __syncthreads();

    int cur = 0;
    for (int step = 1; step < Ss; step++) {
        int par = step & 1;
        float cx = sx[cur], cy = sy[cur], cz = sz[cur];

        float m = NEG;
#pragma unroll
        for (int j = 0; j < 8; j++) {
            float dx = px[j] - cx, dy = py[j] - cy, dz = pz[j] - cz;
            float sqd = dx * dx + dy * dy + dz * dz;
            cum[j] = cum[j] + sqd;
            m = fmaxf(m, cum[j]);
        }

        // monotone float->uint encode; HW warp max
        unsigned um = __float_as_uint(m);
        um = (um & 0x80000000u) ? ~um : (um | 0x80000000u);
        unsigned uw = __reduce_max_sync(0xffffffffu, um);

        // warp-local min index among cum == warp max
        unsigned xu = (uw & 0x80000000u) ? (uw & 0x7fffffffu) : ~uw;
        float mw = __uint_as_float(xu);
        int idx = 0x7fffffff;
#pragma unroll
        for (int j = 0; j < 8; j++)
            if (cum[j] == mw) idx = min(idx, t + 512 * j);
        idx = __reduce_min_sync(0xffffffffu, idx);

        if (lane == 0)
            s_mv[par][warp] = ((unsigned long long)uw << 32) | (unsigned)(~idx);
        __syncthreads();                           // the ONLY barrier per step

        // cross-warp reduction: every warp reads all 16 packed entries
        unsigned long long pk = s_mv[par][lane & 15];
        unsigned hi = (unsigned)(pk >> 32);
        unsigned lo = (unsigned)pk;
        unsigned mh = __reduce_max_sync(0xffffffffu, hi);
        unsigned ml = __reduce_max_sync(0xffffffffu, (hi == mh) ? lo : 0u);
        cur = (int)(~ml);                          // global argmax (min index on ties)

        if ((cur & 511) == t) {                    // winner thread only
            int j0 = cur >> 9;
#pragma unroll
            for (int j = 0; j < 8; j++)
                if (j == j0) cum[j] = NEG;         // permanently mask winner
            float* c = &g_centers[(b * Ss + step) * 3];
            c[0] = sx[cur]; c[1] = sy[cur]; c[2] = sz[cur];
        }
    }
}

// ---------------- ball query: 16 warps/block, pos tile in SMEM ------------------
__global__ __launch_bounds__(512) void ballquery_kernel(const float* __restrict__ pos) {
    extern __shared__ float dynq[];
    float* sx = dynq;
    float* sy = dynq + Nn;
    float* sz = dynq + 2 * Nn;

    int b  = blockIdx.x >> 6;
    int s0 = (blockIdx.x & 63) * 16;
    const float* P = pos + b * 3 * Nn;
    for (int i = threadIdx.x; i < Nn; i += 512) {
        sx[i] = P[i]; sy[i] = P[Nn + i]; sz[i] = P[2 * Nn + i];
    }
    __syncthreads();

    int warp = threadIdx.x >> 5, lane = threadIdx.x & 31;
    int bs = b * Ss + s0 + warp;
    float cx = g_centers[bs * 3 + 0];
    float cy = g_centers[bs * 3 + 1];
    float cz = g_centers[bs * 3 + 2];
    float csq = cx * cx + cy * cy + cz * cz;

    int cnt = 0, first = 0;
    int* G = &g_gi[bs * Kk];
    unsigned lanemask = (1u << lane) - 1u;
    for (int j0 = 0; j0 < Nn; j0 += 32) {
        int j = j0 + lane;
        float x = sx[j], y = sy[j], z = sz[j];
        float dot = cx * x + cy * y + cz * z;
        float psq = x * x + y * y + z * z;
        float d = -2.0f * dot + csq + psq;
        bool ok = !(d > RAD2);
        unsigned m = __ballot_sync(0xffffffffu, ok);
        if (cnt == 0 && m) first = j0 + __ffs(m) - 1;
        int p = cnt + __popc(m & lanemask);
        if (ok && p < Kk) G[p] = j;
        cnt += __popc(m);
        if (cnt >= Kk) break;
    }
    for (int p = cnt + lane; p < Kk; p += 32) G[p] = first;
}

// ---------------- conv0: gather(67ch) -> 64, + BN stats -------------------------
__global__ __launch_bounds__(256) void conv0_kernel(const float* __restrict__ pos,
                                                    const float* __restrict__ w0,
                                                    const float* __restrict__ b0) {
    __shared__ float wT[67 * 64];
    __shared__ float xs[2][32][68];
    __shared__ int   sgi[64];
    __shared__ float sc[2][3];
    __shared__ float ssum[64], ssq[64];

    int t = threadIdx.x;
    int bs0 = blockIdx.x * 2;
    for (int e = t; e < 67 * 64; e += 256) {
        int o = e & 63, i = e >> 6;
        wT[i * 64 + o] = w0[o * 67 + i];
    }
    if (t < 64) sgi[t] = g_gi[bs0 * Kk + t];
    if (t < 6)  sc[t / 3][t % 3] = g_centers[bs0 * 3 + t];
    if (t < 64) { ssum[t] = 0.f; ssq[t] = 0.f; }
    __syncthreads();

    int b = bs0 >> 10;
    const float* Pb = pos + b * 3 * Nn;
    for (int e = t; e < 2 * 32 * 67; e += 256) {
        int g = e / (32 * 67);
        int r = e - g * (32 * 67);
        int h = r / 67;
        int i = r - h * 67;
        int idx = sgi[g * 32 + h];
        float v;
        if (i < 3) v = Pb[i * Nn + idx] - sc[g][i];
        else       v = g_featT[(b * Nn + idx) * 64 + (i - 3)];
        xs[g][h][i] = v;
    }
    __syncthreads();

    int om = (t & 15) * 4;
    int hg = t >> 4;
    int g  = hg >> 3;
    int h4 = (hg & 7) * 4;

    float acc[4][4];
#pragma unroll
    for (int a = 0; a < 4; a++)
#pragma unroll
        for (int j = 0; j < 4; j++) acc[a][j] = 0.f;

    for (int i = 0; i < 67; i++) {
        float4 wv = *(const float4*)&wT[i * 64 + om];
        float xr0 = xs[g][h4 + 0][i];
        float xr1 = xs[g][h4 + 1][i];
        float xr2 = xs[g][h4 + 2][i];
        float xr3 = xs[g][h4 + 3][i];
        acc[0][0] += xr0 * wv.x; acc[0][1] += xr0 * wv.y; acc[0][2] += xr0 * wv.z; acc[0][3] += xr0 * wv.w;
        acc[1][0] += xr1 * wv.x; acc[1][1] += xr1 * wv.y; acc[1][2] += xr1 * wv.z; acc[1][3] += xr1 * wv.w;
        acc[2][0] += xr2 * wv.x; acc[2][1] += xr2 * wv.y; acc[2][2] += xr2 * wv.z; acc[2][3] += xr2 * wv.w;
        acc[3][0] += xr3 * wv.x; acc[3][1] += xr3 * wv.y; acc[3][2] += xr3 * wv.z; acc[3][3] += xr3 * wv.w;
    }

    float4 bias4 = *(const float4*)&b0[om];
    float ls[4] = {0, 0, 0, 0}, lq[4] = {0, 0, 0, 0};
    int bs = bs0 + g;
#pragma unroll
    for (int hh = 0; hh < 4; hh++) {
        float4 v;
        v.x = acc[hh][0] + bias4.x;
        v.y = acc[hh][1] + bias4.y;
        v.z = acc[hh][2] + bias4.z;
        v.w = acc[hh][3] + bias4.w;
        ls[0] += v.x; lq[0] += v.x * v.x;
        ls[1] += v.y; lq[1] += v.y * v.y;
        ls[2] += v.z; lq[2] += v.z * v.z;
        ls[3] += v.w; lq[3] += v.w * v.w;
        *(float4*)&g_y0[(bs * 32 + h4 + hh) * 64 + om] = v;
    }
#pragma unroll
    for (int j = 0; j < 4; j++) {
        atomicAdd(&ssum[om + j], ls[j]);
        atomicAdd(&ssq[om + j],  lq[j]);
    }
    __syncthreads();
    if (t < 64) {
        atomicAdd(&g_sum0[t], ssum[t]);
        atomicAdd(&g_sq0[t],  ssq[t]);
    }
}

// ---------------- conv1: 64->64 with fused (inline) BN0+ReLU --------------------
__global__ __launch_bounds__(256) void conv1_kernel(const float* __restrict__ w1,
                                                    const float* __restrict__ b1,
                                                    const float* __restrict__ gam0,
                                                    const float* __restrict__ bet0) {
    __shared__ float wT[64 * 64];
    __shared__ float xs[2][32][64];
    __shared__ float ssum[64], ssq[64];
    __shared__ float s_scale[64], s_shift[64];

    int t = threadIdx.x;
    int bs0 = blockIdx.x * 2;
    for (int e = t; e < 64 * 64; e += 256) {
        int o = e & 63, i = e >> 6;
        wT[i * 64 + o] = w1[o * 64 + i];
    }
    if (t < 64) {
        ssum[t] = 0.f; ssq[t] = 0.f;
        float mean = g_sum0[t] * (1.0f / NELEM);
        float var  = g_sq0[t] * (1.0f / NELEM) - mean * mean;
        float s = gam0[t] * rsqrtf(var + 1e-5f);
        s_scale[t] = s;
        s_shift[t] = bet0[t] - mean * s;
    }
    __syncthreads();

    const float* Y = &g_y0[bs0 * 2048];
    float* xf = &xs[0][0][0];
    for (int e = t; e < 4096; e += 256) {
        int i = e & 63;
        float v = Y[e] * s_scale[i] + s_shift[i];
        xf[e] = fmaxf(v, 0.f);
    }
    __syncthreads();

    int om = (t & 15) * 4;
    int hg = t >> 4;
    int g  = hg >> 3;
    int h4 = (hg & 7) * 4;

    float acc[4][4];
#pragma unroll
    for (int a = 0; a < 4; a++)
#pragma unroll
        for (int j = 0; j < 4; j++) acc[a][j] = 0.f;

    for (int i = 0; i < 64; i++) {
        float4 wv = *(const float4*)&wT[i * 64 + om];
        float xr0 = xs[g][h4 + 0][i];
        float xr1 = xs[g][h4 + 1][i];
        float xr2 = xs[g][h4 + 2][i];
        float xr3 = xs[g][h4 + 3][i];
        acc[0][0] += xr0 * wv.x; acc[0][1] += xr0 * wv.y; acc[0][2] += xr0 * wv.z; acc[0][3] += xr0 * wv.w;
        acc[1][0] += xr1 * wv.x; acc[1][1] += xr1 * wv.y; acc[1][2] += xr1 * wv.z; acc[1][3] += xr1 * wv.w;
        acc[2][0] += xr2 * wv.x; acc[2][1] += xr2 * wv.y; acc[2][2] += xr2 * wv.z; acc[2][3] += xr2 * wv.w;
        acc[3][0] += xr3 * wv.x; acc[3][1] += xr3 * wv.y; acc[3][2] += xr3 * wv.z; acc[3][3] += xr3 * wv.w;
    }

    float4 bias4 = *(const float4*)&b1[om];
    float ls[4] = {0, 0, 0, 0}, lq[4] = {0, 0, 0, 0};
    int bs = bs0 + g;
#pragma unroll
    for (int hh = 0; hh < 4; hh++) {
        float4 v;
        v.x = acc[hh][0] + bias4.x;
        v.y = acc[hh][1] + bias4.y;
        v.z = acc[hh][2] + bias4.z;
        v.w = acc[hh][3] + bias4.w;
        ls[0] += v.x; lq[0] += v.x * v.x;
        ls[1] += v.y; lq[1] += v.y * v.y;
        ls[2] += v.z; lq[2] += v.z * v.z;
        ls[3] += v.w; lq[3] += v.w * v.w;
        *(float4*)&g_y1[(bs * 32 + h4 + hh) * 64 + om] = v;
    }
#pragma unroll
    for (int j = 0; j < 4; j++) {
        atomicAdd(&ssum[om + j], ls[j]);
        atomicAdd(&ssq[om + j],  lq[j]);
    }
    __syncthreads();
    if (t < 64) {
        atomicAdd(&g_sum1[t], ssum[t]);
        atomicAdd(&g_sq1[t],  ssq[t]);
    }
}

// ---------------- conv2: 64->128 with fused (inline) BN1+ReLU -------------------
__global__ __launch_bounds__(256) void conv2_kernel(const float* __restrict__ w2,
                                                    const float* __restrict__ b2,
                                                    const float* __restrict__ gam1,
                                                    const float* __restrict__ bet1) {
    __shared__ float wT[64 * 128];
    __shared__ float xs[32][64];
    __shared__ float ssum[128], ssq[128];
    __shared__ float s_scale[64], s_shift[64];

    int t = threadIdx.x;
    int bs = blockIdx.x;
    for (int e = t; e < 64 * 128; e += 256) {
        int o = e & 127, i = e >> 7;
        wT[i * 128 + o] = w2[o * 64 + i];
    }
    if (t < 128) { ssum[t] = 0.f; ssq[t] = 0.f; }
    if (t < 64) {
        float mean = g_sum1[t] * (1.0f / NELEM);
        float var  = g_sq1[t] * (1.0f / NELEM) - mean * mean;
        float s = gam1[t] * rsqrtf(var + 1e-5f);
        s_scale[t] = s;
        s_shift[t] = bet1[t] - mean * s;
    }
    __syncthreads();

    const float* Y = &g_y1[bs * 2048];
    float* xf = &xs[0][0];
    for (int e = t; e < 2048; e += 256) {
        int i = e & 63;
        float v = Y[e] * s_scale[i] + s_shift[i];
        xf[e] = fmaxf(v, 0.f);
    }
    __syncthreads();

    int om = (t & 31) * 4;
    int h4 = (t >> 5) * 4;

    float acc[4][4];
#pragma unroll
    for (int a = 0; a < 4; a++)
#pragma unroll
        for (int j = 0; j < 4; j++) acc[a][j] = 0.f;

    for (int i = 0; i < 64; i++) {
        float4 wv = *(const float4*)&wT[i * 128 + om];
        float xr0 = xs[h4 + 0][i];
        float xr1 = xs[h4 + 1][i];
        float xr2 = xs[h4 + 2][i];
        float xr3 = xs[h4 + 3][i];
        acc[0][0] += xr0 * wv.x; acc[0][1] += xr0 * wv.y; acc[0][2] += xr0 * wv.z; acc[0][3] += xr0 * wv.w;
        acc[1][0] += xr1 * wv.x; acc[1][1] += xr1 * wv.y; acc[1][2] += xr1 * wv.z; acc[1][3] += xr1 * wv.w;
        acc[2][0] += xr2 * wv.x; acc[2][1] += xr2 * wv.y; acc[2][2] += xr2 * wv.z; acc[2][3] += xr2 * wv.w;
        acc[3][0] += xr3 * wv.x; acc[3][1] += xr3 * wv.y; acc[3][2] += xr3 * wv.z; acc[3][3] += xr3 * wv.w;
    }

    float4 bias4 = *(const float4*)&b2[om];
    float ls[4] = {0, 0, 0, 0}, lq[4] = {0, 0, 0, 0};
#pragma unroll
    for (int hh = 0; hh < 4; hh++) {
        float4 v;
        v.x = acc[hh][0] + bias4.x;
        v.y = acc[hh][1] + bias4.y;
        v.z = acc[hh][2] + bias4.z;
        v.w = acc[hh][3] + bias4.w;
        ls[0] += v.x; lq[0] += v.x * v.x;
        ls[1] += v.y; lq[1] += v.y * v.y;
        ls[2] += v.z; lq[2] += v.z * v.z;
        ls[3] += v.w; lq[3] += v.w * v.w;
        *(float4*)&g_y2[(bs * 32 + h4 + hh) * 128 + om] = v;
    }
#pragma unroll
    for (int j = 0; j < 4; j++) {
        atomicAdd(&ssum[om + j], ls[j]);
        atomicAdd(&ssq[om + j],  lq[j]);
    }
    __syncthreads();
    if (t < 128) {
        atomicAdd(&g_sum2[t], ssum[t]);
        atomicAdd(&g_sq2[t],  ssq[t]);
    }
}

// ---------------- final: inline BN2 + ReLU + max over samples -> feat_out --------
__global__ __launch_bounds__(256) void finalpool_kernel(float* __restrict__ out,
                                                        const float* __restrict__ gam2,
                                                        const float* __restrict__ bet2) {
    __shared__ float s_sc[128], s_sh[128];
    int t = threadIdx.x;
    if (t < 128) {
        float mean = g_sum2[t] * (1.0f / NELEM);
        float var  = g_sq2[t] * (1.0f / NELEM) - mean * mean;
        float s = gam2[t] * rsqrtf(var + 1e-5f);
        s_sc[t] = s;
        s_sh[t] = bet2[t] - mean * s;
    }
    __syncthreads();

    int gwarp = (blockIdx.x * blockDim.x + t) >> 5;   // bs
    int lane = t & 31;
    if (gwarp >= Bb * Ss) return;
    int bs = gwarp;
    int b = bs >> 10, s = bs & 1023;

    float scl[4], sft[4];
#pragma unroll
    for (int j = 0; j < 4; j++) {
        scl[j] = s_sc[lane + 32 * j];
        sft[j] = s_sh[lane + 32 * j];
    }
    float m[4] = {-3.4e38f, -3.4e38f, -3.4e38f, -3.4e38f};
    const float* Y = &g_y2[bs * 32 * 128];
    for (int h = 0; h < 32; h++) {
#pragma unroll
        for (int j = 0; j < 4; j++) {
            float v = Y[h * 128 + lane + 32 * j] * scl[j] + sft[j];
            v = fmaxf(v, 0.f);
            m[j] = fmaxf(m[j], v);
        }
    }
    float* F = out + Bb * 3 * Ss + b * 128 * Ss + s;
#pragma unroll
    for (int j = 0; j < 4; j++) F[(lane + 32 * j) * Ss] = m[j];
}

// ---------------- pos_out copy --------------------------------------------------
__global__ void poscopy_kernel(float* __restrict__ out) {
    int e = blockIdx.x * blockDim.x + threadIdx.x;
    if (e >= Bb * 3 * Ss) return;
    int b = e / (3 * Ss);
    int r = e - b * (3 * Ss);
    int c = r / Ss;
    int s = r - c * Ss;
    out[e] = g_centers[(b * Ss + s) * 3 + c];
}

// ---------------- launch --------------------------------------------------------
extern "C" void kernel_launch(void* const* d_in, const int* in_sizes, int n_in,
                              void* d_out, int out_size) {
    const float* pos  = (const float*)d_in[0];
    const float* feat = (const float*)d_in[1];
    const float* w0   = (const float*)d_in[2];
    const float* b0   = (const float*)d_in[3];
    const float* g0   = (const float*)d_in[4];
    const float* be0  = (const float*)d_in[5];
    const float* w1   = (const float*)d_in[6];
    const float* b1   = (const float*)d_in[7];
    const float* g1   = (const float*)d_in[8];
    const float* be1  = (const float*)d_in[9];
    const float* w2   = (const float*)d_in[10];
    const float* b2   = (const float*)d_in[11];
    const float* g2   = (const float*)d_in[12];
    const float* be2  = (const float*)d_in[13];
    float* out = (float*)d_out;

    const int DYN = 3 * Nn * (int)sizeof(float);   // 48KB dynamic smem
    cudaFuncSetAttribute(fps_kernel,       cudaFuncAttributeMaxDynamicSharedMemorySize, DYN);
    cudaFuncSetAttribute(ballquery_kernel, cudaFuncAttributeMaxDynamicSharedMemorySize, DYN);

    zero_stats_kernel<<<1, 128>>>();
    transpose_feat_kernel<<<(Bb * Nn * Dd) / 256, 256>>>(feat);
    fps_kernel<<<Bb, 512, DYN>>>(pos);
    ballquery_kernel<<<512, 512, DYN>>>(pos);
    conv0_kernel<<<Bb * Ss / 2, 256>>>(pos, w0, b0);
    conv1_kernel<<<Bb * Ss / 2, 256>>>(w1, b1, g0, be0);
    conv2_kernel<<<Bb * Ss, 256>>>(w2, b2, g1, be1);
    finalpool_kernel<<<Bb * Ss / 8, 256>>>(out, g2, be2);
    poscopy_kernel<<<(Bb * 3 * Ss + 255) / 256, 256>>>(out);
}

// round 8
// speedup vs baseline: 1.5074x; 1.0182x over previous
#include <cuda_runtime.h>
#include <cuda_bf16.h>
#include <cstdint>

#define Bb 8
#define Nn 4096
#define Dd 64
#define Ss 1024
#define Kk 32
#define RAD2 0.04f
#define NELEM 262144.0f   // B*32*S elements per channel for BN

// ---------------- scratch (device globals; no allocation allowed) ----------------
__device__ float g_featT[Bb * Nn * Dd];            // [b][n][c] point-major features
__device__ float g_centers[Bb * Ss * 3];           // [bs][3]
__device__ int   g_gi[Bb * Ss * Kk];
__device__ float g_y0[Bb * Ss * Kk * 64];          // [bs][h][o]
__device__ float g_y1[Bb * Ss * Kk * 64];
__device__ float g_y2[Bb * Ss * Kk * 128];
__device__ float g_sum0[64],  g_sq0[64];
__device__ float g_sum1[64],  g_sq1[64];
__device__ float g_sum2[128], g_sq2[128];

// ---------------- zero stats ----------------
__global__ void zero_stats_kernel() {
    int t = threadIdx.x;
    if (t < 64)  { g_sum0[t] = 0.f; g_sq0[t] = 0.f; g_sum1[t] = 0.f; g_sq1[t] = 0.f; }
    if (t < 128) { g_sum2[t] = 0.f; g_sq2[t] = 0.f; }
}

// ---------------- feature transpose: (B,64,N) -> (B,N,64), half per launch ------
__global__ void transpose_feat_kernel(const float* __restrict__ feat, int base) {
    int e = base + blockIdx.x * blockDim.x + threadIdx.x;
    int c = e & 63;
    int n = (e >> 6) & (Nn - 1);
    int b = e >> 18;
    g_featT[e] = feat[b * (Dd * Nn) + c * Nn + n];
}

// ---------------- FPS: one block per batch, 512 threads, 8 pts/thread -----------
// Single barrier per step; branchless winner handling (predicated selects, no
// divergent branch body); centers written one step late from registers.
__global__ __launch_bounds__(512) void fps_kernel(const float* __restrict__ pos) {
    extern __shared__ float dyn[];
    float* sx = dyn;
    float* sy = dyn + Nn;
    float* sz = dyn + 2 * Nn;

    __shared__ unsigned long long s_mv[2][16];

    int b = blockIdx.x;
    const float* P = pos + b * 3 * Nn;
    int t = threadIdx.x;
    int warp = t >> 5, lane = t & 31;

    float px[8], py[8], pz[8], cum[8];
#pragma unroll
    for (int j = 0; j < 8; j++) {
        int n = t + 512 * j;
        px[j] = P[n];
        py[j] = P[Nn + n];
        pz[j] = P[2 * Nn + n];
        sx[n] = px[j]; sy[n] = py[j]; sz[n] = pz[j];
        cum[j] = 0.f;
    }

    const float NEG = -3.4e38f;
    if (t == 0) cum[0] = NEG;                      // point 0 pre-selected
    __syncthreads();

    int cur = 0;
    for (int step = 1; step < Ss; step++) {
        int par = step & 1;
        float cx = sx[cur], cy = sy[cur], cz = sz[cur];

        // write center for selection (step-1) from registers (step 1 rewrites
        // nothing wrong: centers[0] gets point 0 = correct)
        if (t == 0) {
            float* c = &g_centers[(b * Ss + step - 1) * 3];
            c[0] = cx; c[1] = cy; c[2] = cz;
        }

        float m = NEG;
#pragma unroll
        for (int j = 0; j < 8; j++) {
            float dx = px[j] - cx, dy = py[j] - cy, dz = pz[j] - cz;
            float sqd = dx * dx + dy * dy + dz * dz;
            cum[j] = cum[j] + sqd;
            m = fmaxf(m, cum[j]);
        }

        // monotone float->uint encode; HW warp max
        unsigned um = __float_as_uint(m);
        um = (um & 0x80000000u) ? ~um : (um | 0x80000000u);
        unsigned uw = __reduce_max_sync(0xffffffffu, um);

        // warp-local min index among cum == warp max
        unsigned xu = (uw & 0x80000000u) ? (uw & 0x7fffffffu) : ~uw;
        float mw = __uint_as_float(xu);
        int idx = 0x7fffffff;
#pragma unroll
        for (int j = 0; j < 8; j++)
            if (cum[j] == mw) idx = min(idx, t + 512 * j);
        idx = __reduce_min_sync(0xffffffffu, idx);

        if (lane == 0)
            s_mv[par][warp] = ((unsigned long long)uw << 32) | (unsigned)(~idx);
        __syncthreads();                           // the ONLY barrier per step

        // cross-warp reduction: every warp reads all 16 packed entries
        unsigned long long pk = s_mv[par][lane & 15];
        unsigned hi = (unsigned)(pk >> 32);
        unsigned lo = (unsigned)pk;
        unsigned mh = __reduce_max_sync(0xffffffffu, hi);
        unsigned ml = __reduce_max_sync(0xffffffffu, (hi == mh) ? lo : 0u);
        cur = (int)(~ml);                          // global argmax (min index on ties)

        // branchless poison: exactly one thread owns cur
#pragma unroll
        for (int j = 0; j < 8; j++)
            if (cur == t + 512 * j) cum[j] = NEG;
    }

    if (t == 0) {                                  // last selection's center
        float* c = &g_centers[(b * Ss + Ss - 1) * 3];
        c[0] = sx[cur]; c[1] = sy[cur]; c[2] = sz[cur];
    }
}

// ---------------- ball query: 16 warps/block, pos tile in SMEM ------------------
__global__ __launch_bounds__(512) void ballquery_kernel(const float* __restrict__ pos) {
    extern __shared__ float dynq[];
    float* sx = dynq;
    float* sy = dynq + Nn;
    float* sz = dynq + 2 * Nn;

    int b  = blockIdx.x >> 6;
    int s0 = (blockIdx.x & 63) * 16;
    const float* P = pos + b * 3 * Nn;
    for (int i = threadIdx.x; i < Nn; i += 512) {
        sx[i] = P[i]; sy[i] = P[Nn + i]; sz[i] = P[2 * Nn + i];
    }
    __syncthreads();

    int warp = threadIdx.x >> 5, lane = threadIdx.x & 31;
    int bs = b * Ss + s0 + warp;
    float cx = g_centers[bs * 3 + 0];
    float cy = g_centers[bs * 3 + 1];
    float cz = g_centers[bs * 3 + 2];
    float csq = cx * cx + cy * cy + cz * cz;

    int cnt = 0, first = 0;
    int* G = &g_gi[bs * Kk];
    unsigned lanemask = (1u << lane) - 1u;
    for (int j0 = 0; j0 < Nn; j0 += 32) {
        int j = j0 + lane;
        float x = sx[j], y = sy[j], z = sz[j];
        float dot = cx * x + cy * y + cz * z;
        float psq = x * x + y * y + z * z;
        float d = -2.0f * dot + csq + psq;
        bool ok = !(d > RAD2);
        unsigned m = __ballot_sync(0xffffffffu, ok);
        if (cnt == 0 && m) first = j0 + __ffs(m) - 1;
        int p = cnt + __popc(m & lanemask);
        if (ok && p < Kk) G[p] = j;
        cnt += __popc(m);
        if (cnt >= Kk) break;
    }
    for (int p = cnt + lane; p < Kk; p += 32) G[p] = first;
}

// ---------------- conv0: gather(67ch) -> 64, + BN stats -------------------------
__global__ __launch_bounds__(256) void conv0_kernel(const float* __restrict__ pos,
                                                    const float* __restrict__ w0,
                                                    const float* __restrict__ b0) {
    __shared__ float wT[67 * 64];
    __shared__ float xs[2][32][68];
    __shared__ int   sgi[64];
    __shared__ float sc[2][3];
    __shared__ float ssum[64], ssq[64];

    int t = threadIdx.x;
    int bs0 = blockIdx.x * 2;
    for (int e = t; e < 67 * 64; e += 256) {
        int o = e & 63, i = e >> 6;
        wT[i * 64 + o] = w0[o * 67 + i];
    }
    if (t < 64) sgi[t] = g_gi[bs0 * Kk + t];
    if (t < 6)  sc[t / 3][t % 3] = g_centers[bs0 * 3 + t];
    if (t < 64) { ssum[t] = 0.f; ssq[t] = 0.f; }
    __syncthreads();

    int b = bs0 >> 10;
    const float* Pb = pos + b * 3 * Nn;
    for (int e = t; e < 2 * 32 * 67; e += 256) {
        int g = e / (32 * 67);
        int r = e - g * (32 * 67);
        int h = r / 67;
        int i = r - h * 67;
        int idx = sgi[g * 32 + h];
        float v;
        if (i < 3) v = Pb[i * Nn + idx] - sc[g][i];
        else       v = g_featT[(b * Nn + idx) * 64 + (i - 3)];
        xs[g][h][i] = v;
    }
    __syncthreads();

    int om = (t & 15) * 4;
    int hg = t >> 4;
    int g  = hg >> 3;
    int h4 = (hg & 7) * 4;

    float acc[4][4];
#pragma unroll
    for (int a = 0; a < 4; a++)
#pragma unroll
        for (int j = 0; j < 4; j++) acc[a][j] = 0.f;

    for (int i = 0; i < 67; i++) {
        float4 wv = *(const float4*)&wT[i * 64 + om];
        float xr0 = xs[g][h4 + 0][i];
        float xr1 = xs[g][h4 + 1][i];
        float xr2 = xs[g][h4 + 2][i];
        float xr3 = xs[g][h4 + 3][i];
        acc[0][0] += xr0 * wv.x; acc[0][1] += xr0 * wv.y; acc[0][2] += xr0 * wv.z; acc[0][3] += xr0 * wv.w;
        acc[1][0] += xr1 * wv.x; acc[1][1] += xr1 * wv.y; acc[1][2] += xr1 * wv.z; acc[1][3] += xr1 * wv.w;
        acc[2][0] += xr2 * wv.x; acc[2][1] += xr2 * wv.y; acc[2][2] += xr2 * wv.z; acc[2][3] += xr2 * wv.w;
        acc[3][0] += xr3 * wv.x; acc[3][1] += xr3 * wv.y; acc[3][2] += xr3 * wv.z; acc[3][3] += xr3 * wv.w;
    }

    float4 bias4 = *(const float4*)&b0[om];
    float ls[4] = {0, 0, 0, 0}, lq[4] = {0, 0, 0, 0};
    int bs = bs0 + g;
#pragma unroll
    for (int hh = 0; hh < 4; hh++) {
        float4 v;
        v.x = acc[hh][0] + bias4.x;
        v.y = acc[hh][1] + bias4.y;
        v.z = acc[hh][2] + bias4.z;
        v.w = acc[hh][3] + bias4.w;
        ls[0] += v.x; lq[0] += v.x * v.x;
        ls[1] += v.y; lq[1] += v.y * v.y;
        ls[2] += v.z; lq[2] += v.z * v.z;
        ls[3] += v.w; lq[3] += v.w * v.w;
        *(float4*)&g_y0[(bs * 32 + h4 + hh) * 64 + om] = v;
    }
#pragma unroll
    for (int j = 0; j < 4; j++) {
        atomicAdd(&ssum[om + j], ls[j]);
        atomicAdd(&ssq[om + j],  lq[j]);
    }
    __syncthreads();
    if (t < 64) {
        atomicAdd(&g_sum0[t], ssum[t]);
        atomicAdd(&g_sq0[t],  ssq[t]);
    }
}

// ---------------- conv1: 64->64 with fused (inline) BN0+ReLU --------------------
__global__ __launch_bounds__(256) void conv1_kernel(const float* __restrict__ w1,
                                                    const float* __restrict__ b1,
                                                    const float* __restrict__ gam0,
                                                    const float* __restrict__ bet0) {
    __shared__ float wT[64 * 64];
    __shared__ float xs[2][32][64];
    __shared__ float ssum[64], ssq[64];
    __shared__ float s_scale[64], s_shift[64];

    int t = threadIdx.x;
    int bs0 = blockIdx.x * 2;
    for (int e = t; e < 64 * 64; e += 256) {
        int o = e & 63, i = e >> 6;
        wT[i * 64 + o] = w1[o * 64 + i];
    }
    if (t < 64) {
        ssum[t] = 0.f; ssq[t] = 0.f;
        float mean = g_sum0[t] * (1.0f / NELEM);
        float var  = g_sq0[t] * (1.0f / NELEM) - mean * mean;
        float s = gam0[t] * rsqrtf(var + 1e-5f);
        s_scale[t] = s;
        s_shift[t] = bet0[t] - mean * s;
    }
    __syncthreads();

    const float* Y = &g_y0[bs0 * 2048];
    float* xf = &xs[0][0][0];
    for (int e = t; e < 4096; e += 256) {
        int i = e & 63;
        float v = Y[e] * s_scale[i] + s_shift[i];
        xf[e] = fmaxf(v, 0.f);
    }
    __syncthreads();

    int om = (t & 15) * 4;
    int hg = t >> 4;
    int g  = hg >> 3;
    int h4 = (hg & 7) * 4;

    float acc[4][4];
#pragma unroll
    for (int a = 0; a < 4; a++)
#pragma unroll
        for (int j = 0; j < 4; j++) acc[a][j] = 0.f;

    for (int i = 0; i < 64; i++) {
        float4 wv = *(const float4*)&wT[i * 64 + om];
        float xr0 = xs[g][h4 + 0][i];
        float xr1 = xs[g][h4 + 1][i];
        float xr2 = xs[g][h4 + 2][i];
        float xr3 = xs[g][h4 + 3][i];
        acc[0][0] += xr0 * wv.x; acc[0][1] += xr0 * wv.y; acc[0][2] += xr0 * wv.z; acc[0][3] += xr0 * wv.w;
        acc[1][0] += xr1 * wv.x; acc[1][1] += xr1 * wv.y; acc[1][2] += xr1 * wv.z; acc[1][3] += xr1 * wv.w;
        acc[2][0] += xr2 * wv.x; acc[2][1] += xr2 * wv.y; acc[2][2] += xr2 * wv.z; acc[2][3] += xr2 * wv.w;
        acc[3][0] += xr3 * wv.x; acc[3][1] += xr3 * wv.y; acc[3][2] += xr3 * wv.z; acc[3][3] += xr3 * wv.w;
    }

    float4 bias4 = *(const float4*)&b1[om];
    float ls[4] = {0, 0, 0, 0}, lq[4] = {0, 0, 0, 0};
    int bs = bs0 + g;
#pragma unroll
    for (int hh = 0; hh < 4; hh++) {
        float4 v;
        v.x = acc[hh][0] + bias4.x;
        v.y = acc[hh][1] + bias4.y;
        v.z = acc[hh][2] + bias4.z;
        v.w = acc[hh][3] + bias4.w;
        ls[0] += v.x; lq[0] += v.x * v.x;
        ls[1] += v.y; lq[1] += v.y * v.y;
        ls[2] += v.z; lq[2] += v.z * v.z;
        ls[3] += v.w; lq[3] += v.w * v.w;
        *(float4*)&g_y1[(bs * 32 + h4 + hh) * 64 + om] = v;
    }
#pragma unroll
    for (int j = 0; j < 4; j++) {
        atomicAdd(&ssum[om + j], ls[j]);
        atomicAdd(&ssq[om + j],  lq[j]);
    }
    __syncthreads();
    if (t < 64) {
        atomicAdd(&g_sum1[t], ssum[t]);
        atomicAdd(&g_sq1[t],  ssq[t]);
    }
}

// ---------------- conv2: 64->128, 2 centers/block, weights in dynamic smem ------
__global__ __launch_bounds__(512) void conv2_kernel(const float* __restrict__ w2,
                                                    const float* __restrict__ b2,
                                                    const float* __restrict__ gam1,
                                                    const float* __restrict__ bet1) {
    extern __shared__ float wT[];                  // 64*128 floats = 32KB
    __shared__ float xs[2][32][64];
    __shared__ float ssum[128], ssq[128];
    __shared__ float s_scale[64], s_shift[64];

    int t = threadIdx.x;
    int bs0 = blockIdx.x * 2;
    for (int e = t; e < 64 * 128; e += 512) {
        int o = e & 127, i = e >> 7;
        wT[i * 128 + o] = w2[o * 64 + i];
    }
    if (t < 128) { ssum[t] = 0.f; ssq[t] = 0.f; }
    if (t < 64) {
        float mean = g_sum1[t] * (1.0f / NELEM);
        float var  = g_sq1[t] * (1.0f / NELEM) - mean * mean;
        float s = gam1[t] * rsqrtf(var + 1e-5f);
        s_scale[t] = s;
        s_shift[t] = bet1[t] - mean * s;
    }
    __syncthreads();

    const float* Y = &g_y1[bs0 * 2048];
    float* xf = &xs[0][0][0];
    for (int e = t; e < 4096; e += 512) {
        int i = e & 63;
        float v = Y[e] * s_scale[i] + s_shift[i];
        xf[e] = fmaxf(v, 0.f);
    }
    __syncthreads();

    int om = (t & 31) * 4;
    int hg = t >> 5;          // 0..15
    int g  = hg >> 3;
    int h4 = (hg & 7) * 4;

    float acc[4][4];
#pragma unroll
    for (int a = 0; a < 4; a++)
#pragma unroll
        for (int j = 0; j < 4; j++) acc[a][j] = 0.f;

    for (int i = 0; i < 64; i++) {
        float4 wv = *(const float4*)&wT[i * 128 + om];
        float xr0 = xs[g][h4 + 0][i];
        float xr1 = xs[g][h4 + 1][i];
        float xr2 = xs[g][h4 + 2][i];
        float xr3 = xs[g][h4 + 3][i];
        acc[0][0] += xr0 * wv.x; acc[0][1] += xr0 * wv.y; acc[0][2] += xr0 * wv.z; acc[0][3] += xr0 * wv.w;
        acc[1][0] += xr1 * wv.x; acc[1][1] += xr1 * wv.y; acc[1][2] += xr1 * wv.z; acc[1][3] += xr1 * wv.w;
        acc[2][0] += xr2 * wv.x; acc[2][1] += xr2 * wv.y; acc[2][2] += xr2 * wv.z; acc[2][3] += xr2 * wv.w;
        acc[3][0] += xr3 * wv.x; acc[3][1] += xr3 * wv.y; acc[3][2] += xr3 * wv.z; acc[3][3] += xr3 * wv.w;
    }

    float4 bias4 = *(const float4*)&b2[om];
    float ls[4] = {0, 0, 0, 0}, lq[4] = {0, 0, 0, 0};
    int bs = bs0 + g;
#pragma unroll
    for (int hh = 0; hh < 4; hh++) {
        float4 v;
        v.x = acc[hh][0] + bias4.x;
        v.y = acc[hh][1] + bias4.y;
        v.z = acc[hh][2] + bias4.z;
        v.w = acc[hh][3] + bias4.w;
        ls[0] += v.x; lq[0] += v.x * v.x;
        ls[1] += v.y; lq[1] += v.y * v.y;
        ls[2] += v.z; lq[2] += v.z * v.z;
        ls[3] += v.w; lq[3] += v.w * v.w;
        *(float4*)&g_y2[(bs * 32 + h4 + hh) * 128 + om] = v;
    }
#pragma unroll
    for (int j = 0; j < 4; j++) {
        atomicAdd(&ssum[om + j], ls[j]);
        atomicAdd(&ssq[om + j],  lq[j]);
    }
    __syncthreads();
    if (t < 128) {
        atomicAdd(&g_sum2[t], ssum[t]);
        atomicAdd(&g_sq2[t],  ssq[t]);
    }
}

// ---------------- final: inline BN2 + ReLU + max pool + poscopy -----------------
__global__ __launch_bounds__(256) void finalpool_kernel(float* __restrict__ out,
                                                        const float* __restrict__ gam2,
                                                        const float* __restrict__ bet2) {
    __shared__ float s_sc[128], s_sh[128];
    int t = threadIdx.x;
    if (t < 128) {
        float mean = g_sum2[t] * (1.0f / NELEM);
        float var  = g_sq2[t] * (1.0f / NELEM) - mean * mean;
        float s = gam2[t] * rsqrtf(var + 1e-5f);
        s_sc[t] = s;
        s_sh[t] = bet2[t] - mean * s;
    }
    __syncthreads();

    int gwarp = (blockIdx.x * blockDim.x + t) >> 5;   // bs
    int lane = t & 31;
    {
        int bs = gwarp;
        int b = bs >> 10, s = bs & 1023;

        float scl[4], sft[4];
#pragma unroll
        for (int j = 0; j < 4; j++) {
            scl[j] = s_sc[lane + 32 * j];
            sft[j] = s_sh[lane + 32 * j];
        }
        float m[4] = {-3.4e38f, -3.4e38f, -3.4e38f, -3.4e38f};
        const float* Y = &g_y2[bs * 32 * 128];
        for (int h = 0; h < 32; h++) {
#pragma unroll
            for (int j = 0; j < 4; j++) {
                float v = Y[h * 128 + lane + 32 * j] * scl[j] + sft[j];
                v = fmaxf(v, 0.f);
                m[j] = fmaxf(m[j], v);
            }
        }
        float* F = out + Bb * 3 * Ss + b * 128 * Ss + s;
#pragma unroll
        for (int j = 0; j < 4; j++) F[(lane + 32 * j) * Ss] = m[j];
    }

    // fused poscopy: first 24576 global threads copy pos_out
    int e = blockIdx.x * blockDim.x + t;
    if (e < Bb * 3 * Ss) {
        int b2_ = e / (3 * Ss);
        int r = e - b2_ * (3 * Ss);
        int c = r / Ss;
        int s2 = r - c * Ss;
        out[e] = g_centers[(b2_ * Ss + s2) * 3 + c];
    }
}

// ---------------- launch --------------------------------------------------------
extern "C" void kernel_launch(void* const* d_in, const int* in_sizes, int n_in,
                              void* d_out, int out_size) {
    const float* pos  = (const float*)d_in[0];
    const float* feat = (const float*)d_in[1];
    const float* w0   = (const float*)d_in[2];
    const float* b0   = (const float*)d_in[3];
    const float* g0   = (const float*)d_in[4];
    const float* be0  = (const float*)d_in[5];
    const float* w1   = (const float*)d_in[6];
    const float* b1   = (const float*)d_in[7];
    const float* g1   = (const float*)d_in[8];
    const float* be1  = (const float*)d_in[9];
    const float* w2   = (const float*)d_in[10];
    const float* b2   = (const float*)d_in[11];
    const float* g2   = (const float*)d_in[12];
    const float* be2  = (const float*)d_in[13];
    float* out = (float*)d_out;

    const int DYN = 3 * Nn * (int)sizeof(float);   // 48KB dynamic smem
    cudaFuncSetAttribute(fps_kernel,       cudaFuncAttributeMaxDynamicSharedMemorySize, DYN);
    cudaFuncSetAttribute(ballquery_kernel, cudaFuncAttributeMaxDynamicSharedMemorySize, DYN);
    cudaFuncSetAttribute(conv2_kernel,     cudaFuncAttributeMaxDynamicSharedMemorySize, 64 * 128 * 4);

    const int HALF = (Bb * Nn * Dd) / 2;
    transpose_feat_kernel<<<HALF / 256, 256>>>(feat, 0);       // 1
    transpose_feat_kernel<<<HALF / 256, 256>>>(feat, HALF);    // 2
    zero_stats_kernel<<<1, 128>>>();                           // 3
    fps_kernel<<<Bb, 512, DYN>>>(pos);                         // 4  <- ncu capture slot
    ballquery_kernel<<<512, 512, DYN>>>(pos);                  // 5
    conv0_kernel<<<Bb * Ss / 2, 256>>>(pos, w0, b0);           // 6
    conv1_kernel<<<Bb * Ss / 2, 256>>>(w1, b1, g0, be0);       // 7
    conv2_kernel<<<Bb * Ss / 2, 512, 64 * 128 * 4>>>(w2, b2, g1, be1); // 8
    finalpool_kernel<<<Bb * Ss / 8, 256>>>(out, g2, be2);      // 9
}

// round 9
// speedup vs baseline: 1.6592x; 1.1008x over previous
#include <cuda_runtime.h>
#include <cuda_bf16.h>
#include <cstdint>

#define Bb 8
#define Nn 4096
#define Dd 64
#define Ss 1024
#define Kk 32
#define RAD2 0.04f
#define NELEM 262144.0f   // B*32*S elements per channel for BN

// ---------------- scratch (device globals; no allocation allowed) ----------------
__device__ float g_featT[Bb * Nn * Dd];            // [b][n][c] point-major features
__device__ float g_centers[Bb * Ss * 3];           // [bs][3]
__device__ int   g_prog[Bb];                       // FPS progress (centers published)
__device__ float g_y0[Bb * Ss * Kk * 64];          // [bs][h][o]
__device__ float g_y1[Bb * Ss * Kk * 64];
__device__ float g_y2[Bb * Ss * Kk * 128];
__device__ float g_sum0[64],  g_sq0[64];
__device__ float g_sum1[64],  g_sq1[64];
__device__ float g_sum2[128], g_sq2[128];

// ---------------- zero stats + progress ----------------
__global__ void zero_stats_kernel() {
    int t = threadIdx.x;
    if (t < 64)  { g_sum0[t] = 0.f; g_sq0[t] = 0.f; g_sum1[t] = 0.f; g_sq1[t] = 0.f; }
    if (t < 128) { g_sum2[t] = 0.f; g_sq2[t] = 0.f; }
    if (t < Bb)  g_prog[t] = 0;
}

// ---------------- feature transpose: (B,64,N) -> (B,N,64), half per launch ------
__global__ void transpose_feat_kernel(const float* __restrict__ feat, int base) {
    int e = base + blockIdx.x * blockDim.x + threadIdx.x;
    int c = e & 63;
    int n = (e >> 6) & (Nn - 1);
    int b = e >> 18;
    g_featT[e] = feat[b * (Dd * Nn) + c * Nn + n];
}

// =====================================================================
// FUSED persistent kernel, grid = 148 (one wave, all co-resident):
//   blocks 0..7   : FPS producer (identical selection math to R8)
//   blocks 8..147 : workers: per-batch smem pos tile; for each squad of 4
//                   centers: wait progress -> ballquery (4 warps) ->
//                   conv0 GEMM (16 warps) + BN stats
// Dynamic smem: tile 12288 f | wT 4288 f | xs 8704 f  = 101120 bytes
// =====================================================================
__global__ __launch_bounds__(512) void fused_kernel(const float* __restrict__ pos,
                                                    const float* __restrict__ w0,
                                                    const float* __restrict__ b0) {
    extern __shared__ float dyn[];
    float* tile = dyn;                       // [x:4096][y:4096][z:4096]
    int t = threadIdx.x;
    int warp = t >> 5, lane = t & 31;

    if (blockIdx.x < 8) {
        // ------------------- FPS producer -------------------
        float* sx = tile;
        float* sy = tile + Nn;
        float* sz = tile + 2 * Nn;
        __shared__ unsigned long long s_mv[2][16];

        int b = blockIdx.x;
        const float* P = pos + b * 3 * Nn;

        float px[8], py[8], pz[8], cum[8];
#pragma unroll
        for (int j = 0; j < 8; j++) {
            int n = t + 512 * j;
            px[j] = P[n];
            py[j] = P[Nn + n];
            pz[j] = P[2 * Nn + n];
            sx[n] = px[j]; sy[n] = py[j]; sz[n] = pz[j];
            cum[j] = 0.f;
        }

        const float NEG = -3.4e38f;
        if (t == 0) cum[0] = NEG;            // point 0 pre-selected
        __syncthreads();

        int cur = 0;
        for (int step = 1; step < Ss; step++) {
            int par = step & 1;
            float cx = sx[cur], cy = sy[cur], cz = sz[cur];

            if (t == 0) {
                float* c = &g_centers[(b * Ss + step - 1) * 3];
                c[0] = cx; c[1] = cy; c[2] = cz;
                if ((step & 31) == 0) {
                    __threadfence();
                    atomicExch(&g_prog[b], step);   // centers [0, step) published
                }
            }

            float m = NEG;
#pragma unroll
            for (int j = 0; j < 8; j++) {
                float dx = px[j] - cx, dy = py[j] - cy, dz = pz[j] - cz;
                float sqd = dx * dx + dy * dy + dz * dz;
                cum[j] = cum[j] + sqd;
                m = fmaxf(m, cum[j]);
            }

            unsigned um = __float_as_uint(m);
            um = (um & 0x80000000u) ? ~um : (um | 0x80000000u);
            unsigned uw = __reduce_max_sync(0xffffffffu, um);

            unsigned xu = (uw & 0x80000000u) ? (uw & 0x7fffffffu) : ~uw;
            float mw = __uint_as_float(xu);
            int idx = 0x7fffffff;
#pragma unroll
            for (int j = 0; j < 8; j++)
                if (cum[j] == mw) idx = min(idx, t + 512 * j);
            idx = __reduce_min_sync(0xffffffffu, idx);

            if (lane == 0)
                s_mv[par][warp] = ((unsigned long long)uw << 32) | (unsigned)(~idx);
            __syncthreads();

            unsigned long long pk = s_mv[par][lane & 15];
            unsigned hi = (unsigned)(pk >> 32);
            unsigned lo = (unsigned)pk;
            unsigned mh = __reduce_max_sync(0xffffffffu, hi);
            unsigned ml = __reduce_max_sync(0xffffffffu, (hi == mh) ? lo : 0u);
            cur = (int)(~ml);

#pragma unroll
            for (int j = 0; j < 8; j++)
                if (cur == t + 512 * j) cum[j] = NEG;
        }

        if (t == 0) {
            float* c = &g_centers[(b * Ss + Ss - 1) * 3];
            c[0] = sx[cur]; c[1] = sy[cur]; c[2] = sz[cur];
            __threadfence();
            atomicExch(&g_prog[b], Ss);
        }
        return;
    }

    // ------------------- worker -------------------
    float* wT = dyn + 3 * Nn;                // 67*64 floats
    float* xs = wT + 67 * 64;                // 4*32*68 floats
    __shared__ int   sgi[128];
    __shared__ float sc3[12];
    __shared__ float ssum[64], ssq[64];

    int w  = blockIdx.x - 8;                 // 0..139
    int b  = w & 7;
    int wi = w >> 3;                         // 0..17
    int nb = (b < 4) ? 18 : 17;              // workers serving this batch

    const float* P = pos + b * 3 * Nn;
    for (int i = t; i < 3 * Nn; i += 512) tile[i] = P[i];
    for (int e = t; e < 67 * 64; e += 512) {
        int o = e & 63, i = e >> 6;
        wT[i * 64 + o] = w0[o * 67 + i];
    }
    if (t < 64) { ssum[t] = 0.f; ssq[t] = 0.f; }
    __syncthreads();

    for (int squad = wi; squad < 256; squad += nb) {
        int s0 = squad * 4;

        if (t == 0) {
            while (*((volatile int*)&g_prog[b]) < s0 + 4) __nanosleep(64);
        }
        __syncthreads();

        // ---- ballquery: warp k handles center s0+k (identical logic) ----
        if (warp < 4) {
            int bs = b * Ss + s0 + warp;
            volatile float* C = (volatile float*)&g_centers[bs * 3];
            float cx = C[0], cy = C[1], cz = C[2];
            if (lane == 0) { sc3[warp * 3] = cx; sc3[warp * 3 + 1] = cy; sc3[warp * 3 + 2] = cz; }
            float csq = cx * cx + cy * cy + cz * cz;

            int cnt = 0, first = 0;
            int* G = &sgi[warp * 32];
            unsigned lanemask = (1u << lane) - 1u;
            for (int j0 = 0; j0 < Nn; j0 += 32) {
                int j = j0 + lane;
                float x = tile[j], y = tile[Nn + j], z = tile[2 * Nn + j];
                float dot = cx * x + cy * y + cz * z;
                float psq = x * x + y * y + z * z;
                float d = -2.0f * dot + csq + psq;
                bool ok = !(d > RAD2);
                unsigned m = __ballot_sync(0xffffffffu, ok);
                if (cnt == 0 && m) first = j0 + __ffs(m) - 1;
                int p = cnt + __popc(m & lanemask);
                if (ok && p < Kk) G[p] = j;
                cnt += __popc(m);
                if (cnt >= Kk) break;
            }
            for (int p = cnt + lane; p < Kk; p += 32) G[p] = first;
        }
        __syncthreads();

        // ---- gather 4 groups x 32 samples x 67 channels into xs ----
        for (int e = t; e < 4 * 32 * 67; e += 512) {
            int g = e / 2144;
            int r = e - g * 2144;
            int h = r / 67;
            int i = r - h * 67;
            int idx = sgi[g * 32 + h];
            float v;
            if (i < 3) v = tile[i * Nn + idx] - sc3[g * 3 + i];
            else       v = g_featT[(b * Nn + idx) * 64 + (i - 3)];
            xs[(g * 32 + h) * 68 + i] = v;
        }
        __syncthreads();

        // ---- conv0 GEMM: 512 threads, 4 groups ----
        int om = (t & 15) * 4;
        int hg = t >> 4;                     // 0..31
        int g  = hg >> 3;                    // 0..3
        int h4 = (hg & 7) * 4;

        float acc[4][4];
#pragma unroll
        for (int a = 0; a < 4; a++)
#pragma unroll
            for (int j = 0; j < 4; j++) acc[a][j] = 0.f;

        const float* xrow0 = &xs[(g * 32 + h4 + 0) * 68];
        const float* xrow1 = &xs[(g * 32 + h4 + 1) * 68];
        const float* xrow2 = &xs[(g * 32 + h4 + 2) * 68];
        const float* xrow3 = &xs[(g * 32 + h4 + 3) * 68];
        for (int i = 0; i < 67; i++) {
            float4 wv = *(const float4*)&wT[i * 64 + om];
            float xr0 = xrow0[i], xr1 = xrow1[i], xr2 = xrow2[i], xr3 = xrow3[i];
            acc[0][0] += xr0 * wv.x; acc[0][1] += xr0 * wv.y; acc[0][2] += xr0 * wv.z; acc[0][3] += xr0 * wv.w;
            acc[1][0] += xr1 * wv.x; acc[1][1] += xr1 * wv.y; acc[1][2] += xr1 * wv.z; acc[1][3] += xr1 * wv.w;
            acc[2][0] += xr2 * wv.x; acc[2][1] += xr2 * wv.y; acc[2][2] += xr2 * wv.z; acc[2][3] += xr2 * wv.w;
            acc[3][0] += xr3 * wv.x; acc[3][1] += xr3 * wv.y; acc[3][2] += xr3 * wv.z; acc[3][3] += xr3 * wv.w;
        }

        float4 bias4 = *(const float4*)&b0[om];
        float ls[4] = {0, 0, 0, 0}, lq[4] = {0, 0, 0, 0};
        int bs = b * Ss + s0 + g;
#pragma unroll
        for (int hh = 0; hh < 4; hh++) {
            float4 v;
            v.x = acc[hh][0] + bias4.x;
            v.y = acc[hh][1] + bias4.y;
            v.z = acc[hh][2] + bias4.z;
            v.w = acc[hh][3] + bias4.w;
            ls[0] += v.x; lq[0] += v.x * v.x;
            ls[1] += v.y; lq[1] += v.y * v.y;
            ls[2] += v.z; lq[2] += v.z * v.z;
            ls[3] += v.w; lq[3] += v.w * v.w;
            *(float4*)&g_y0[(bs * 32 + h4 + hh) * 64 + om] = v;
        }
#pragma unroll
        for (int j = 0; j < 4; j++) {
            atomicAdd(&ssum[om + j], ls[j]);
            atomicAdd(&ssq[om + j],  lq[j]);
        }
        __syncthreads();                     // protect xs/sgi for next task
    }

    if (t < 64) {
        atomicAdd(&g_sum0[t], ssum[t]);
        atomicAdd(&g_sq0[t],  ssq[t]);
    }
}

// ---------------- conv1: 64->64 with fused (inline) BN0+ReLU --------------------
__global__ __launch_bounds__(256) void conv1_kernel(const float* __restrict__ w1,
                                                    const float* __restrict__ b1,
                                                    const float* __restrict__ gam0,
                                                    const float* __restrict__ bet0) {
    __shared__ float wT[64 * 64];
    __shared__ float xs[2][32][64];
    __shared__ float ssum[64], ssq[64];
    __shared__ float s_scale[64], s_shift[64];

    int t = threadIdx.x;
    int bs0 = blockIdx.x * 2;
    for (int e = t; e < 64 * 64; e += 256) {
        int o = e & 63, i = e >> 6;
        wT[i * 64 + o] = w1[o * 64 + i];
    }
    if (t < 64) {
        ssum[t] = 0.f; ssq[t] = 0.f;
        float mean = g_sum0[t] * (1.0f / NELEM);
        float var  = g_sq0[t] * (1.0f / NELEM) - mean * mean;
        float s = gam0[t] * rsqrtf(var + 1e-5f);
        s_scale[t] = s;
        s_shift[t] = bet0[t] - mean * s;
    }
    __syncthreads();

    const float* Y = &g_y0[bs0 * 2048];
    float* xf = &xs[0][0][0];
    for (int e = t; e < 4096; e += 256) {
        int i = e & 63;
        float v = Y[e] * s_scale[i] + s_shift[i];
        xf[e] = fmaxf(v, 0.f);
    }
    __syncthreads();

    int om = (t & 15) * 4;
    int hg = t >> 4;
    int g  = hg >> 3;
    int h4 = (hg & 7) * 4;

    float acc[4][4];
#pragma unroll
    for (int a = 0; a < 4; a++)
#pragma unroll
        for (int j = 0; j < 4; j++) acc[a][j] = 0.f;

    for (int i = 0; i < 64; i++) {
        float4 wv = *(const float4*)&wT[i * 64 + om];
        float xr0 = xs[g][h4 + 0][i];
        float xr1 = xs[g][h4 + 1][i];
        float xr2 = xs[g][h4 + 2][i];
        float xr3 = xs[g][h4 + 3][i];
        acc[0][0] += xr0 * wv.x; acc[0][1] += xr0 * wv.y; acc[0][2] += xr0 * wv.z; acc[0][3] += xr0 * wv.w;
        acc[1][0] += xr1 * wv.x; acc[1][1] += xr1 * wv.y; acc[1][2] += xr1 * wv.z; acc[1][3] += xr1 * wv.w;
        acc[2][0] += xr2 * wv.x; acc[2][1] += xr2 * wv.y; acc[2][2] += xr2 * wv.z; acc[2][3] += xr2 * wv.w;
        acc[3][0] += xr3 * wv.x; acc[3][1] += xr3 * wv.y; acc[3][2] += xr3 * wv.z; acc[3][3] += xr3 * wv.w;
    }

    float4 bias4 = *(const float4*)&b1[om];
    float ls[4] = {0, 0, 0, 0}, lq[4] = {0, 0, 0, 0};
    int bs = bs0 + g;
#pragma unroll
    for (int hh = 0; hh < 4; hh++) {
        float4 v;
        v.x = acc[hh][0] + bias4.x;
        v.y = acc[hh][1] + bias4.y;
        v.z = acc[hh][2] + bias4.z;
        v.w = acc[hh][3] + bias4.w;
        ls[0] += v.x; lq[0] += v.x * v.x;
        ls[1] += v.y; lq[1] += v.y * v.y;
        ls[2] += v.z; lq[2] += v.z * v.z;
        ls[3] += v.w; lq[3] += v.w * v.w;
        *(float4*)&g_y1[(bs * 32 + h4 + hh) * 64 + om] = v;
    }
#pragma unroll
    for (int j = 0; j < 4; j++) {
        atomicAdd(&ssum[om + j], ls[j]);
        atomicAdd(&ssq[om + j],  lq[j]);
    }
    __syncthreads();
    if (t < 64) {
        atomicAdd(&g_sum1[t], ssum[t]);
        atomicAdd(&g_sq1[t],  ssq[t]);
    }
}

// ---------------- conv2: 64->128, 2 centers/block, weights in dynamic smem ------
__global__ __launch_bounds__(512) void conv2_kernel(const float* __restrict__ w2,
                                                    const float* __restrict__ b2,
                                                    const float* __restrict__ gam1,
                                                    const float* __restrict__ bet1) {
    extern __shared__ float wT[];                  // 64*128 floats = 32KB
    __shared__ float xs[2][32][64];
    __shared__ float ssum[128], ssq[128];
    __shared__ float s_scale[64], s_shift[64];

    int t = threadIdx.x;
    int bs0 = blockIdx.x * 2;
    for (int e = t; e < 64 * 128; e += 512) {
        int o = e & 127, i = e >> 7;
        wT[i * 128 + o] = w2[o * 64 + i];
    }
    if (t < 128) { ssum[t] = 0.f; ssq[t] = 0.f; }
    if (t < 64) {
        float mean = g_sum1[t] * (1.0f / NELEM);
        float var  = g_sq1[t] * (1.0f / NELEM) - mean * mean;
        float s = gam1[t] * rsqrtf(var + 1e-5f);
        s_scale[t] = s;
        s_shift[t] = bet1[t] - mean * s;
    }
    __syncthreads();

    const float* Y = &g_y1[bs0 * 2048];
    float* xf = &xs[0][0][0];
    for (int e = t; e < 4096; e += 512) {
        int i = e & 63;
        float v = Y[e] * s_scale[i] + s_shift[i];
        xf[e] = fmaxf(v, 0.f);
    }
    __syncthreads();

    int om = (t & 31) * 4;
    int hg = t >> 5;          // 0..15
    int g  = hg >> 3;
    int h4 = (hg & 7) * 4;

    float acc[4][4];
#pragma unroll
    for (int a = 0; a < 4; a++)
#pragma unroll
        for (int j = 0; j < 4; j++) acc[a][j] = 0.f;

    for (int i = 0; i < 64; i++) {
        float4 wv = *(const float4*)&wT[i * 128 + om];
        float xr0 = xs[g][h4 + 0][i];
        float xr1 = xs[g][h4 + 1][i];
        float xr2 = xs[g][h4 + 2][i];
        float xr3 = xs[g][h4 + 3][i];
        acc[0][0] += xr0 * wv.x; acc[0][1] += xr0 * wv.y; acc[0][2] += xr0 * wv.z; acc[0][3] += xr0 * wv.w;
        acc[1][0] += xr1 * wv.x; acc[1][1] += xr1 * wv.y; acc[1][2] += xr1 * wv.z; acc[1][3] += xr1 * wv.w;
        acc[2][0] += xr2 * wv.x; acc[2][1] += xr2 * wv.y; acc[2][2] += xr2 * wv.z; acc[2][3] += xr2 * wv.w;
        acc[3][0] += xr3 * wv.x; acc[3][1] += xr3 * wv.y; acc[3][2] += xr3 * wv.z; acc[3][3] += xr3 * wv.w;
    }

    float4 bias4 = *(const float4*)&b2[om];
    float ls[4] = {0, 0, 0, 0}, lq[4] = {0, 0, 0, 0};
    int bs = bs0 + g;
#pragma unroll
    for (int hh = 0; hh < 4; hh++) {
        float4 v;
        v.x = acc[hh][0] + bias4.x;
        v.y = acc[hh][1] + bias4.y;
        v.z = acc[hh][2] + bias4.z;
        v.w = acc[hh][3] + bias4.w;
        ls[0] += v.x; lq[0] += v.x * v.x;
        ls[1] += v.y; lq[1] += v.y * v.y;
        ls[2] += v.z; lq[2] += v.z * v.z;
        ls[3] += v.w; lq[3] += v.w * v.w;
        *(float4*)&g_y2[(bs * 32 + h4 + hh) * 128 + om] = v;
    }
#pragma unroll
    for (int j = 0; j < 4; j++) {
        atomicAdd(&ssum[om + j], ls[j]);
        atomicAdd(&ssq[om + j],  lq[j]);
    }
    __syncthreads();
    if (t < 128) {
        atomicAdd(&g_sum2[t], ssum[t]);
        atomicAdd(&g_sq2[t],  ssq[t]);
    }
}

// ---------------- final: inline BN2 + ReLU + max pool + poscopy -----------------
__global__ __launch_bounds__(256) void finalpool_kernel(float* __restrict__ out,
                                                        const float* __restrict__ gam2,
                                                        const float* __restrict__ bet2) {
    __shared__ float s_sc[128], s_sh[128];
    int t = threadIdx.x;
    if (t < 128) {
        float mean = g_sum2[t] * (1.0f / NELEM);
        float var  = g_sq2[t] * (1.0f / NELEM) - mean * mean;
        float s = gam2[t] * rsqrtf(var + 1e-5f);
        s_sc[t] = s;
        s_sh[t] = bet2[t] - mean * s;
    }
    __syncthreads();

    int gwarp = (blockIdx.x * blockDim.x + t) >> 5;   // bs
    int lane = t & 31;
    {
        int bs = gwarp;
        int b = bs >> 10, s = bs & 1023;

        float scl[4], sft[4];
#pragma unroll
        for (int j = 0; j < 4; j++) {
            scl[j] = s_sc[lane + 32 * j];
            sft[j] = s_sh[lane + 32 * j];
        }
        float m[4] = {-3.4e38f, -3.4e38f, -3.4e38f, -3.4e38f};
        const float* Y = &g_y2[bs * 32 * 128];
        for (int h = 0; h < 32; h++) {
#pragma unroll
            for (int j = 0; j < 4; j++) {
                float v = Y[h * 128 + lane + 32 * j] * scl[j] + sft[j];
                v = fmaxf(v, 0.f);
                m[j] = fmaxf(m[j], v);
            }
        }
        float* F = out + Bb * 3 * Ss + b * 128 * Ss + s;
#pragma unroll
        for (int j = 0; j < 4; j++) F[(lane + 32 * j) * Ss] = m[j];
    }

    // fused poscopy: first 24576 global threads copy pos_out
    int e = blockIdx.x * blockDim.x + t;
    if (e < Bb * 3 * Ss) {
        int b2_ = e / (3 * Ss);
        int r = e - b2_ * (3 * Ss);
        int c = r / Ss;
        int s2 = r - c * Ss;
        out[e] = g_centers[(b2_ * Ss + s2) * 3 + c];
    }
}

// ---------------- launch --------------------------------------------------------
extern "C" void kernel_launch(void* const* d_in, const int* in_sizes, int n_in,
                              void* d_out, int out_size) {
    const float* pos  = (const float*)d_in[0];
    const float* feat = (const float*)d_in[1];
    const float* w0   = (const float*)d_in[2];
    const float* b0   = (const float*)d_in[3];
    const float* g0   = (const float*)d_in[4];
    const float* be0  = (const float*)d_in[5];
    const float* w1   = (const float*)d_in[6];
    const float* b1   = (const float*)d_in[7];
    const float* g1   = (const float*)d_in[8];
    const float* be1  = (const float*)d_in[9];
    const float* w2   = (const float*)d_in[10];
    const float* b2   = (const float*)d_in[11];
    const float* g2   = (const float*)d_in[12];
    const float* be2  = (const float*)d_in[13];
    float* out = (float*)d_out;

    const int FUSED_DYN = (3 * Nn + 67 * 64 + 4 * 32 * 68) * (int)sizeof(float); // 101120
    cudaFuncSetAttribute(fused_kernel, cudaFuncAttributeMaxDynamicSharedMemorySize, FUSED_DYN);
    cudaFuncSetAttribute(conv2_kernel, cudaFuncAttributeMaxDynamicSharedMemorySize, 64 * 128 * 4);

    const int HALF = (Bb * Nn * Dd) / 2;
    transpose_feat_kernel<<<HALF / 256, 256>>>(feat, 0);        // 1
    transpose_feat_kernel<<<HALF / 256, 256>>>(feat, HALF);     // 2
    zero_stats_kernel<<<1, 128>>>();                            // 3
    fused_kernel<<<148, 512, FUSED_DYN>>>(pos, w0, b0);         // 4 <- ncu capture slot
    conv1_kernel<<<Bb * Ss / 2, 256>>>(w1, b1, g0, be0);        // 5
    conv2_kernel<<<Bb * Ss / 2, 512, 64 * 128 * 4>>>(w2, b2, g1, be1); // 6
    finalpool_kernel<<<Bb * Ss / 8, 256>>>(out, g2, be2);       // 7
}

// round 10
// speedup vs baseline: 1.7092x; 1.0301x over previous
#include <cuda_runtime.h>
#include <cuda_bf16.h>
#include <cstdint>

#define Bb 8
#define Nn 4096
#define Dd 64
#define Ss 1024
#define Kk 32
#define RAD2 0.04f
#define NELEM 262144.0f   // B*32*S elements per channel for BN

// ---------------- scratch (device globals; no allocation allowed) ----------------
__device__ float g_featT[Bb * Nn * Dd];            // [b][n][c] point-major features
__device__ float g_centers[Bb * Ss * 3];           // [bs][3]
__device__ int   g_prog[Bb];                       // FPS progress (centers published)
__device__ int   g_tdone[Bb];                      // workers done transposing
__device__ float g_y0[Bb * Ss * Kk * 64];          // [bs][h][o]
__device__ float g_y1[Bb * Ss * Kk * 64];
__device__ float g_y2[Bb * Ss * Kk * 128];
__device__ float g_sum0[64],  g_sq0[64];
__device__ float g_sum1[64],  g_sq1[64];
__device__ float g_sum2[128], g_sq2[128];

// ---------------- zero stats + progress ----------------
__global__ void zero_stats_kernel() {
    int t = threadIdx.x;
    if (t < 64)  { g_sum0[t] = 0.f; g_sq0[t] = 0.f; g_sum1[t] = 0.f; g_sq1[t] = 0.f; }
    if (t < 128) { g_sum2[t] = 0.f; g_sq2[t] = 0.f; }
    if (t < Bb)  { g_prog[t] = 0; g_tdone[t] = 0; }
}

// =====================================================================
// FUSED persistent kernel, grid = 148 (one wave, all co-resident):
//   blocks 0..7   : FPS producer (identical selection math)
//   blocks 8..147 : workers: transpose feat slice -> per-batch barrier;
//                   then per squad of 4 centers: wait progress ->
//                   ballquery (4 warps) -> conv0 GEMM + BN stats
// Dynamic smem: tile 12288 f | wT 4288 f | xs 8704 f  = 101120 bytes
// =====================================================================
__global__ __launch_bounds__(512) void fused_kernel(const float* __restrict__ pos,
                                                    const float* __restrict__ feat,
                                                    const float* __restrict__ w0,
                                                    const float* __restrict__ b0) {
    extern __shared__ __align__(16) float dyn[];
    float* tile = dyn;                       // [x:4096][y:4096][z:4096]
    int t = threadIdx.x;
    int warp = t >> 5, lane = t & 31;

    if (blockIdx.x < 8) {
        // ------------------- FPS producer -------------------
        float* sx = tile;
        float* sy = tile + Nn;
        float* sz = tile + 2 * Nn;
        __shared__ unsigned long long s_mv[2][16];

        int b = blockIdx.x;
        const float* P = pos + b * 3 * Nn;

        float px[8], py[8], pz[8], cum[8];
#pragma unroll
        for (int j = 0; j < 8; j++) {
            int n = t + 512 * j;
            px[j] = P[n];
            py[j] = P[Nn + n];
            pz[j] = P[2 * Nn + n];
            sx[n] = px[j]; sy[n] = py[j]; sz[n] = pz[j];
            cum[j] = 0.f;
        }

        const float NEG = -3.4e38f;
        if (t == 0) cum[0] = NEG;            // point 0 pre-selected
        __syncthreads();

        int cur = 0;
        for (int step = 1; step < Ss; step++) {
            int par = step & 1;
            float cx = sx[cur], cy = sy[cur], cz = sz[cur];

            if (t == 0) {
                float* c = &g_centers[(b * Ss + step - 1) * 3];
                c[0] = cx; c[1] = cy; c[2] = cz;
                if ((step & 31) == 0) {
                    __threadfence();
                    atomicExch(&g_prog[b], step);   // centers [0, step) published
                }
            }

            float m = NEG;
#pragma unroll
            for (int j = 0; j < 8; j++) {
                float dx = px[j] - cx, dy = py[j] - cy, dz = pz[j] - cz;
                float sqd = dx * dx + dy * dy + dz * dz;
                cum[j] = cum[j] + sqd;
                m = fmaxf(m, cum[j]);
            }

            unsigned um = __float_as_uint(m);
            um = (um & 0x80000000u) ? ~um : (um | 0x80000000u);
            unsigned uw = __reduce_max_sync(0xffffffffu, um);

            unsigned xu = (uw & 0x80000000u) ? (uw & 0x7fffffffu) : ~uw;
            float mw = __uint_as_float(xu);
            int idx = 0x7fffffff;
#pragma unroll
            for (int j = 0; j < 8; j++)
                if (cum[j] == mw) idx = min(idx, t + 512 * j);
            idx = __reduce_min_sync(0xffffffffu, idx);

            if (lane == 0)
                s_mv[par][warp] = ((unsigned long long)uw << 32) | (unsigned)(~idx);
            __syncthreads();

            unsigned long long pk = s_mv[par][lane & 15];
            unsigned hi = (unsigned)(pk >> 32);
            unsigned lo = (unsigned)pk;
            unsigned mh = __reduce_max_sync(0xffffffffu, hi);
            unsigned ml = __reduce_max_sync(0xffffffffu, (hi == mh) ? lo : 0u);
            cur = (int)(~ml);

#pragma unroll
            for (int j = 0; j < 8; j++)
                if (cur == t + 512 * j) cum[j] = NEG;
        }

        if (t == 0) {
            float* c = &g_centers[(b * Ss + Ss - 1) * 3];
            c[0] = sx[cur]; c[1] = sy[cur]; c[2] = sz[cur];
            __threadfence();
            atomicExch(&g_prog[b], Ss);
        }
        return;
    }

    // ------------------- worker -------------------
    float* wT = dyn + 3 * Nn;                // 67*64 floats
    float* xs = wT + 67 * 64;                // 8704 floats
    __shared__ int   sgi[128];
    __shared__ float sc3[12];
    __shared__ float ssum[64], ssq[64];

    int w  = blockIdx.x - 8;                 // 0..139
    int b  = w & 7;
    int wi = w >> 3;                         // 0..17
    int nb = (b < 4) ? 18 : 17;              // workers serving this batch

    const float* P = pos + b * 3 * Nn;
    for (int i = t; i < 3 * Nn; i += 512) tile[i] = P[i];
    for (int e = t; e < 67 * 64; e += 512) {
        int o = e & 63, i = e >> 6;
        wT[i * 64 + o] = w0[o * 67 + i];
    }
    if (t < 64) { ssum[t] = 0.f; ssq[t] = 0.f; }
    __syncthreads();

    // ---- cooperative feature transpose (hidden under FPS) ----
    const float* Fb = feat + b * (Dd * Nn);
    for (int tt = wi; tt < 128; tt += nb) {
        int n0 = tt * 32;
        for (int e = t; e < 2048; e += 512) {
            int c = e >> 5, i2 = e & 31;
            xs[i2 * 65 + c] = Fb[c * Nn + n0 + i2];      // coalesced read
        }
        __syncthreads();
        for (int e = t; e < 2048; e += 512) {
            int n = e >> 6, c = e & 63;
            g_featT[(b * Nn + n0 + n) * 64 + c] = xs[n * 65 + c];  // coalesced write
        }
        __syncthreads();
    }
    __threadfence();
    if (t == 0) {
        atomicAdd(&g_tdone[b], 1);
        while (*((volatile int*)&g_tdone[b]) < nb) __nanosleep(128);
    }
    __syncthreads();

    for (int squad = wi; squad < 256; squad += nb) {
        int s0 = squad * 4;

        if (t == 0) {
            while (*((volatile int*)&g_prog[b]) < s0 + 4) __nanosleep(64);
        }
        __syncthreads();

        // ---- ballquery: warp k handles center s0+k (identical logic) ----
        if (warp < 4) {
            int bs = b * Ss + s0 + warp;
            volatile float* C = (volatile float*)&g_centers[bs * 3];
            float cx = C[0], cy = C[1], cz = C[2];
            if (lane == 0) { sc3[warp * 3] = cx; sc3[warp * 3 + 1] = cy; sc3[warp * 3 + 2] = cz; }
            float csq = cx * cx + cy * cy + cz * cz;

            int cnt = 0, first = 0;
            int* G = &sgi[warp * 32];
            unsigned lanemask = (1u << lane) - 1u;
            for (int j0 = 0; j0 < Nn; j0 += 32) {
                int j = j0 + lane;
                float x = tile[j], y = tile[Nn + j], z = tile[2 * Nn + j];
                float dot = cx * x + cy * y + cz * z;
                float psq = x * x + y * y + z * z;
                float d = -2.0f * dot + csq + psq;
                bool ok = !(d > RAD2);
                unsigned m = __ballot_sync(0xffffffffu, ok);
                if (cnt == 0 && m) first = j0 + __ffs(m) - 1;
                int p = cnt + __popc(m & lanemask);
                if (ok && p < Kk) G[p] = j;
                cnt += __popc(m);
                if (cnt >= Kk) break;
            }
            for (int p = cnt + lane; p < Kk; p += 32) G[p] = first;
        }
        __syncthreads();

        // ---- gather 4 groups x 32 samples x 67 channels into xs ----
        for (int e = t; e < 4 * 32 * 67; e += 512) {
            int g = e / 2144;
            int r = e - g * 2144;
            int h = r / 67;
            int i = r - h * 67;
            int idx = sgi[g * 32 + h];
            float v;
            if (i < 3) v = tile[i * Nn + idx] - sc3[g * 3 + i];
            else       v = g_featT[(b * Nn + idx) * 64 + (i - 3)];
            xs[(g * 32 + h) * 68 + i] = v;
        }
        __syncthreads();

        // ---- conv0 GEMM: 512 threads, 4 groups ----
        int om = (t & 15) * 4;
        int hg = t >> 4;                     // 0..31
        int g  = hg >> 3;                    // 0..3
        int h4 = (hg & 7) * 4;

        float acc[4][4];
#pragma unroll
        for (int a = 0; a < 4; a++)
#pragma unroll
            for (int j = 0; j < 4; j++) acc[a][j] = 0.f;

        const float* xrow0 = &xs[(g * 32 + h4 + 0) * 68];
        const float* xrow1 = &xs[(g * 32 + h4 + 1) * 68];
        const float* xrow2 = &xs[(g * 32 + h4 + 2) * 68];
        const float* xrow3 = &xs[(g * 32 + h4 + 3) * 68];
        for (int i = 0; i < 67; i++) {
            float4 wv = *(const float4*)&wT[i * 64 + om];
            float xr0 = xrow0[i], xr1 = xrow1[i], xr2 = xrow2[i], xr3 = xrow3[i];
            acc[0][0] += xr0 * wv.x; acc[0][1] += xr0 * wv.y; acc[0][2] += xr0 * wv.z; acc[0][3] += xr0 * wv.w;
            acc[1][0] += xr1 * wv.x; acc[1][1] += xr1 * wv.y; acc[1][2] += xr1 * wv.z; acc[1][3] += xr1 * wv.w;
            acc[2][0] += xr2 * wv.x; acc[2][1] += xr2 * wv.y; acc[2][2] += xr2 * wv.z; acc[2][3] += xr2 * wv.w;
            acc[3][0] += xr3 * wv.x; acc[3][1] += xr3 * wv.y; acc[3][2] += xr3 * wv.z; acc[3][3] += xr3 * wv.w;
        }

        float4 bias4 = *(const float4*)&b0[om];
        float ls[4] = {0, 0, 0, 0}, lq[4] = {0, 0, 0, 0};
        int bs = b * Ss + s0 + g;
#pragma unroll
        for (int hh = 0; hh < 4; hh++) {
            float4 v;
            v.x = acc[hh][0] + bias4.x;
            v.y = acc[hh][1] + bias4.y;
            v.z = acc[hh][2] + bias4.z;
            v.w = acc[hh][3] + bias4.w;
            ls[0] += v.x; lq[0] += v.x * v.x;
            ls[1] += v.y; lq[1] += v.y * v.y;
            ls[2] += v.z; lq[2] += v.z * v.z;
            ls[3] += v.w; lq[3] += v.w * v.w;
            *(float4*)&g_y0[(bs * 32 + h4 + hh) * 64 + om] = v;
        }
#pragma unroll
        for (int j = 0; j < 4; j++) {
            atomicAdd(&ssum[om + j], ls[j]);
            atomicAdd(&ssq[om + j],  lq[j]);
        }
        __syncthreads();                     // protect xs/sgi for next task
    }

    if (t < 64) {
        atomicAdd(&g_sum0[t], ssum[t]);
        atomicAdd(&g_sq0[t],  ssq[t]);
    }
}

// ---------------- conv1: 64->64 with fused BN0+ReLU, float4 inner loop ----------
__global__ __launch_bounds__(256) void conv1_kernel(const float* __restrict__ w1,
                                                    const float* __restrict__ b1,
                                                    const float* __restrict__ gam0,
                                                    const float* __restrict__ bet0) {
    __shared__ __align__(16) float wT[64 * 64];
    __shared__ __align__(16) float xs[2][32][64];
    __shared__ float ssum[64], ssq[64];
    __shared__ float s_scale[64], s_shift[64];

    int t = threadIdx.x;
    int bs0 = blockIdx.x * 2;
    for (int e = t; e < 64 * 64; e += 256) {
        int o = e & 63, i = e >> 6;
        wT[i * 64 + o] = w1[o * 64 + i];
    }
    if (t < 64) {
        ssum[t] = 0.f; ssq[t] = 0.f;
        float mean = g_sum0[t] * (1.0f / NELEM);
        float var  = g_sq0[t] * (1.0f / NELEM) - mean * mean;
        float s = gam0[t] * rsqrtf(var + 1e-5f);
        s_scale[t] = s;
        s_shift[t] = bet0[t] - mean * s;
    }
    __syncthreads();

    const float* Y = &g_y0[bs0 * 2048];
    float* xf = &xs[0][0][0];
    for (int e = t; e < 4096; e += 256) {
        int i = e & 63;
        float v = Y[e] * s_scale[i] + s_shift[i];
        xf[e] = fmaxf(v, 0.f);
    }
    __syncthreads();

    int om = (t & 15) * 4;
    int hg = t >> 4;
    int g  = hg >> 3;
    int h4 = (hg & 7) * 4;

    float acc[4][4];
#pragma unroll
    for (int a = 0; a < 4; a++)
#pragma unroll
        for (int j = 0; j < 4; j++) acc[a][j] = 0.f;

    for (int i = 0; i < 64; i += 4) {
        float4 wv0 = *(const float4*)&wT[(i + 0) * 64 + om];
        float4 wv1 = *(const float4*)&wT[(i + 1) * 64 + om];
        float4 wv2 = *(const float4*)&wT[(i + 2) * 64 + om];
        float4 wv3 = *(const float4*)&wT[(i + 3) * 64 + om];
#pragma unroll
        for (int r = 0; r < 4; r++) {
            float4 xv = *(const float4*)&xs[g][h4 + r][i];
            acc[r][0] += xv.x * wv0.x; acc[r][1] += xv.x * wv0.y; acc[r][2] += xv.x * wv0.z; acc[r][3] += xv.x * wv0.w;
            acc[r][0] += xv.y * wv1.x; acc[r][1] += xv.y * wv1.y; acc[r][2] += xv.y * wv1.z; acc[r][3] += xv.y * wv1.w;
            acc[r][0] += xv.z * wv2.x; acc[r][1] += xv.z * wv2.y; acc[r][2] += xv.z * wv2.z; acc[r][3] += xv.z * wv2.w;
            acc[r][0] += xv.w * wv3.x; acc[r][1] += xv.w * wv3.y; acc[r][2] += xv.w * wv3.z; acc[r][3] += xv.w * wv3.w;
        }
    }

    float4 bias4 = *(const float4*)&b1[om];
    float ls[4] = {0, 0, 0, 0}, lq[4] = {0, 0, 0, 0};
    int bs = bs0 + g;
#pragma unroll
    for (int hh = 0; hh < 4; hh++) {
        float4 v;
        v.x = acc[hh][0] + bias4.x;
        v.y = acc[hh][1] + bias4.y;
        v.z = acc[hh][2] + bias4.z;
        v.w = acc[hh][3] + bias4.w;
        ls[0] += v.x; lq[0] += v.x * v.x;
        ls[1] += v.y; lq[1] += v.y * v.y;
        ls[2] += v.z; lq[2] += v.z * v.z;
        ls[3] += v.w; lq[3] += v.w * v.w;
        *(float4*)&g_y1[(bs * 32 + h4 + hh) * 64 + om] = v;
    }
#pragma unroll
    for (int j = 0; j < 4; j++) {
        atomicAdd(&ssum[om + j], ls[j]);
        atomicAdd(&ssq[om + j],  lq[j]);
    }
    __syncthreads();
    if (t < 64) {
        atomicAdd(&g_sum1[t], ssum[t]);
        atomicAdd(&g_sq1[t],  ssq[t]);
    }
}

// ---------------- conv2: 64->128, 2 centers/block, float4 inner loop ------------
__global__ __launch_bounds__(512) void conv2_kernel(const float* __restrict__ w2,
                                                    const float* __restrict__ b2,
                                                    const float* __restrict__ gam1,
                                                    const float* __restrict__ bet1) {
    extern __shared__ __align__(16) float wT2[];   // 64*128 floats = 32KB
    __shared__ __align__(16) float xs[2][32][64];
    __shared__ float ssum[128], ssq[128];
    __shared__ float s_scale[64], s_shift[64];

    int t = threadIdx.x;
    int bs0 = blockIdx.x * 2;
    for (int e = t; e < 64 * 128; e += 512) {
        int o = e & 127, i = e >> 7;
        wT2[i * 128 + o] = w2[o * 64 + i];
    }
    if (t < 128) { ssum[t] = 0.f; ssq[t] = 0.f; }
    if (t < 64) {
        float mean = g_sum1[t] * (1.0f / NELEM);
        float var  = g_sq1[t] * (1.0f / NELEM) - mean * mean;
        float s = gam1[t] * rsqrtf(var + 1e-5f);
        s_scale[t] = s;
        s_shift[t] = bet1[t] - mean * s;
    }
    __syncthreads();

    const float* Y = &g_y1[bs0 * 2048];
    float* xf = &xs[0][0][0];
    for (int e = t; e < 4096; e += 512) {
        int i = e & 63;
        float v = Y[e] * s_scale[i] + s_shift[i];
        xf[e] = fmaxf(v, 0.f);
    }
    __syncthreads();

    int om = (t & 31) * 4;
    int hg = t >> 5;          // 0..15
    int g  = hg >> 3;
    int h4 = (hg & 7) * 4;

    float acc[4][4];
#pragma unroll
    for (int a = 0; a < 4; a++)
#pragma unroll
        for (int j = 0; j < 4; j++) acc[a][j] = 0.f;

    for (int i = 0; i < 64; i += 4) {
        float4 wv0 = *(const float4*)&wT2[(i + 0) * 128 + om];
        float4 wv1 = *(const float4*)&wT2[(i + 1) * 128 + om];
        float4 wv2 = *(const float4*)&wT2[(i + 2) * 128 + om];
        float4 wv3 = *(const float4*)&wT2[(i + 3) * 128 + om];
#pragma unroll
        for (int r = 0; r < 4; r++) {
            float4 xv = *(const float4*)&xs[g][h4 + r][i];
            acc[r][0] += xv.x * wv0.x; acc[r][1] += xv.x * wv0.y; acc[r][2] += xv.x * wv0.z; acc[r][3] += xv.x * wv0.w;
            acc[r][0] += xv.y * wv1.x; acc[r][1] += xv.y * wv1.y; acc[r][2] += xv.y * wv1.z; acc[r][3] += xv.y * wv1.w;
            acc[r][0] += xv.z * wv2.x; acc[r][1] += xv.z * wv2.y; acc[r][2] += xv.z * wv2.z; acc[r][3] += xv.z * wv2.w;
            acc[r][0] += xv.w * wv3.x; acc[r][1] += xv.w * wv3.y; acc[r][2] += xv.w * wv3.z; acc[r][3] += xv.w * wv3.w;
        }
    }

    float4 bias4 = *(const float4*)&b2[om];
    float ls[4] = {0, 0, 0, 0}, lq[4] = {0, 0, 0, 0};
    int bs = bs0 + g;
#pragma unroll
    for (int hh = 0; hh < 4; hh++) {
        float4 v;
        v.x = acc[hh][0] + bias4.x;
        v.y = acc[hh][1] + bias4.y;
        v.z = acc[hh][2] + bias4.z;
        v.w = acc[hh][3] + bias4.w;
        ls[0] += v.x; lq[0] += v.x * v.x;
        ls[1] += v.y; lq[1] += v.y * v.y;
        ls[2] += v.z; lq[2] += v.z * v.z;
        ls[3] += v.w; lq[3] += v.w * v.w;
        *(float4*)&g_y2[(bs * 32 + h4 + hh) * 128 + om] = v;
    }
#pragma unroll
    for (int j = 0; j < 4; j++) {
        atomicAdd(&ssum[om + j], ls[j]);
        atomicAdd(&ssq[om + j],  lq[j]);
    }
    __syncthreads();
    if (t < 128) {
        atomicAdd(&g_sum2[t], ssum[t]);
        atomicAdd(&g_sq2[t],  ssq[t]);
    }
}

// ---------------- final: inline BN2 + ReLU + max pool + poscopy -----------------
__global__ __launch_bounds__(256) void finalpool_kernel(float* __restrict__ out,
                                                        const float* __restrict__ gam2,
                                                        const float* __restrict__ bet2) {
    __shared__ float s_sc[128], s_sh[128];
    int t = threadIdx.x;
    if (t < 128) {
        float mean = g_sum2[t] * (1.0f / NELEM);
        float var  = g_sq2[t] * (1.0f / NELEM) - mean * mean;
        float s = gam2[t] * rsqrtf(var + 1e-5f);
        s_sc[t] = s;
        s_sh[t] = bet2[t] - mean * s;
    }
    __syncthreads();

    int gwarp = (blockIdx.x * blockDim.x + t) >> 5;   // bs
    int lane = t & 31;
    {
        int bs = gwarp;
        int b = bs >> 10, s = bs & 1023;

        float scl[4], sft[4];
#pragma unroll
        for (int j = 0; j < 4; j++) {
            scl[j] = s_sc[lane + 32 * j];
            sft[j] = s_sh[lane + 32 * j];
        }
        float m[4] = {-3.4e38f, -3.4e38f, -3.4e38f, -3.4e38f};
        const float* Y = &g_y2[bs * 32 * 128];
        for (int h = 0; h < 32; h++) {
#pragma unroll
            for (int j = 0; j < 4; j++) {
                float v = Y[h * 128 + lane + 32 * j] * scl[j] + sft[j];
                v = fmaxf(v, 0.f);
                m[j] = fmaxf(m[j], v);
            }
        }
        float* F = out + Bb * 3 * Ss + b * 128 * Ss + s;
#pragma unroll
        for (int j = 0; j < 4; j++) F[(lane + 32 * j) * Ss] = m[j];
    }

    // fused poscopy: first 24576 global threads copy pos_out
    int e = blockIdx.x * blockDim.x + t;
    if (e < Bb * 3 * Ss) {
        int b2_ = e / (3 * Ss);
        int r = e - b2_ * (3 * Ss);
        int c = r / Ss;
        int s2 = r - c * Ss;
        out[e] = g_centers[(b2_ * Ss + s2) * 3 + c];
    }
}

// ---------------- launch --------------------------------------------------------
extern "C" void kernel_launch(void* const* d_in, const int* in_sizes, int n_in,
                              void* d_out, int out_size) {
    const float* pos  = (const float*)d_in[0];
    const float* feat = (const float*)d_in[1];
    const float* w0   = (const float*)d_in[2];
    const float* b0   = (const float*)d_in[3];
    const float* g0   = (const float*)d_in[4];
    const float* be0  = (const float*)d_in[5];
    const float* w1   = (const float*)d_in[6];
    const float* b1   = (const float*)d_in[7];
    const float* g1   = (const float*)d_in[8];
    const float* be1  = (const float*)d_in[9];
    const float* w2   = (const float*)d_in[10];
    const float* b2   = (const float*)d_in[11];
    const float* g2   = (const float*)d_in[12];
    const float* be2  = (const float*)d_in[13];
    float* out = (float*)d_out;

    const int FUSED_DYN = (3 * Nn + 67 * 64 + 4 * 32 * 68) * (int)sizeof(float); // 101120
    cudaFuncSetAttribute(fused_kernel, cudaFuncAttributeMaxDynamicSharedMemorySize, FUSED_DYN);
    cudaFuncSetAttribute(conv2_kernel, cudaFuncAttributeMaxDynamicSharedMemorySize, 64 * 128 * 4);

    zero_stats_kernel<<<1, 128>>>();                             // 1
    fused_kernel<<<148, 512, FUSED_DYN>>>(pos, feat, w0, b0);    // 2
    conv1_kernel<<<Bb * Ss / 2, 256>>>(w1, b1, g0, be0);         // 3
    conv2_kernel<<<Bb * Ss / 2, 512, 64 * 128 * 4>>>(w2, b2, g1, be1); // 4
    finalpool_kernel<<<Bb * Ss / 8, 256>>>(out, g2, be2);        // 5
}

// round 11
// speedup vs baseline: 1.8297x; 1.0705x over previous
#include <cuda_runtime.h>
#include <cuda_bf16.h>
#include <cstdint>

#define Bb 8
#define Nn 4096
#define Dd 64
#define Ss 1024
#define Kk 32
#define RAD2 0.04f
#define NELEM 262144.0f   // B*32*S elements per channel for BN

// ---------------- scratch (device globals; no allocation allowed) ----------------
__device__ float g_featT[Bb * Nn * Dd];            // [b][n][c] point-major features
__device__ float g_centers[Bb * Ss * 3];           // [bs][3]
__device__ int   g_prog[Bb];                       // FPS progress (centers published)
__device__ int   g_tdone[Bb];                      // workers done transposing
__device__ float g_y0[Bb * Ss * Kk * 64];          // [bs][h][o]
__device__ float g_y1[Bb * Ss * Kk * 64];
__device__ float g_y2[Bb * Ss * Kk * 128];
__device__ float g_sum0[64],  g_sq0[64];
__device__ float g_sum1[64],  g_sq1[64];
__device__ float g_sum2[128], g_sq2[128];

// ---------------- zero stats + progress ----------------
__global__ void zero_stats_kernel() {
    int t = threadIdx.x;
    if (t < 64)  { g_sum0[t] = 0.f; g_sq0[t] = 0.f; g_sum1[t] = 0.f; g_sq1[t] = 0.f; }
    if (t < 128) { g_sum2[t] = 0.f; g_sq2[t] = 0.f; }
    if (t < Bb)  { g_prog[t] = 0; g_tdone[t] = 0; }
}

// =====================================================================
// FUSED persistent kernel, grid = 148 (one wave, all co-resident):
//   blocks 0..7   : FPS producer (identical selection math)
//   blocks 8..147 : workers: transpose feat slice -> per-batch barrier;
//                   then per squad of 4 centers: wait progress ->
//                   ballquery (4 warps) -> conv0 GEMM + BN stats
// =====================================================================
__global__ __launch_bounds__(512) void fused_kernel(const float* __restrict__ pos,
                                                    const float* __restrict__ feat,
                                                    const float* __restrict__ w0,
                                                    const float* __restrict__ b0) {
    extern __shared__ __align__(16) float dyn[];
    float* tile = dyn;                       // [x:4096][y:4096][z:4096]
    int t = threadIdx.x;
    int warp = t >> 5, lane = t & 31;

    if (blockIdx.x < 8) {
        // ------------------- FPS producer -------------------
        float* sx = tile;
        float* sy = tile + Nn;
        float* sz = tile + 2 * Nn;
        __shared__ unsigned long long s_mv[2][16];

        int b = blockIdx.x;
        const float* P = pos + b * 3 * Nn;

        float px[8], py[8], pz[8], cum[8];
#pragma unroll
        for (int j = 0; j < 8; j++) {
            int n = t + 512 * j;
            px[j] = P[n];
            py[j] = P[Nn + n];
            pz[j] = P[2 * Nn + n];
            sx[n] = px[j]; sy[n] = py[j]; sz[n] = pz[j];
            cum[j] = 0.f;
        }

        const float NEG = -3.4e38f;
        if (t == 0) cum[0] = NEG;            // point 0 pre-selected
        __syncthreads();

        int cur = 0;
        for (int step = 1; step < Ss; step++) {
            int par = step & 1;
            float cx = sx[cur], cy = sy[cur], cz = sz[cur];

            if (t == 0) {
                float* c = &g_centers[(b * Ss + step - 1) * 3];
                c[0] = cx; c[1] = cy; c[2] = cz;
                if ((step & 31) == 0) {
                    __threadfence();
                    atomicExch(&g_prog[b], step);   // centers [0, step) published
                }
            }

            float m = NEG;
#pragma unroll
            for (int j = 0; j < 8; j++) {
                float dx = px[j] - cx, dy = py[j] - cy, dz = pz[j] - cz;
                float sqd = dx * dx + dy * dy + dz * dz;
                cum[j] = cum[j] + sqd;
                m = fmaxf(m, cum[j]);
            }

            unsigned um = __float_as_uint(m);
            um = (um & 0x80000000u) ? ~um : (um | 0x80000000u);
            unsigned uw = __reduce_max_sync(0xffffffffu, um);

            unsigned xu = (uw & 0x80000000u) ? (uw & 0x7fffffffu) : ~uw;
            float mw = __uint_as_float(xu);
            int idx = 0x7fffffff;
#pragma unroll
            for (int j = 0; j < 8; j++)
                if (cum[j] == mw) idx = min(idx, t + 512 * j);
            idx = __reduce_min_sync(0xffffffffu, idx);

            if (lane == 0)
                s_mv[par][warp] = ((unsigned long long)uw << 32) | (unsigned)(~idx);
            __syncthreads();

            unsigned long long pk = s_mv[par][lane & 15];
            unsigned hi = (unsigned)(pk >> 32);
            unsigned lo = (unsigned)pk;
            unsigned mh = __reduce_max_sync(0xffffffffu, hi);
            unsigned ml = __reduce_max_sync(0xffffffffu, (hi == mh) ? lo : 0u);
            cur = (int)(~ml);

#pragma unroll
            for (int j = 0; j < 8; j++)
                if (cur == t + 512 * j) cum[j] = NEG;
        }

        if (t == 0) {
            float* c = &g_centers[(b * Ss + Ss - 1) * 3];
            c[0] = sx[cur]; c[1] = sy[cur]; c[2] = sz[cur];
            __threadfence();
            atomicExch(&g_prog[b], Ss);
        }
        return;
    }

    // ------------------- worker -------------------
    float* wT = dyn + 3 * Nn;                // 67*64 floats
    float* xs = dyn + 3 * Nn + 67 * 64;      // 8704 floats
    __shared__ int   sgi[128];
    __shared__ float sc3[12];
    __shared__ float ssum[64], ssq[64];

    int w  = blockIdx.x - 8;                 // 0..139
    int b  = w & 7;
    int wi = w >> 3;                         // 0..17
    int nb = (b < 4) ? 18 : 17;              // workers serving this batch

    const float* P = pos + b * 3 * Nn;
    for (int i = t; i < 3 * Nn; i += 512) tile[i] = P[i];
    for (int e = t; e < 67 * 64; e += 512) {
        int o = e & 63, i = e >> 6;
        wT[i * 64 + o] = w0[o * 67 + i];
    }
    if (t < 64) { ssum[t] = 0.f; ssq[t] = 0.f; }
    __syncthreads();

    // ---- cooperative feature transpose (hidden under FPS) ----
    const float* Fb = feat + b * (Dd * Nn);
    for (int tt = wi; tt < 128; tt += nb) {
        int n0 = tt * 32;
        for (int e = t; e < 2048; e += 512) {
            int c = e >> 5, i2 = e & 31;
            xs[i2 * 65 + c] = Fb[c * Nn + n0 + i2];      // coalesced read
        }
        __syncthreads();
        for (int e = t; e < 2048; e += 512) {
            int n = e >> 6, c = e & 63;
            g_featT[(b * Nn + n0 + n) * 64 + c] = xs[n * 65 + c];  // coalesced write
        }
        __syncthreads();
    }
    __threadfence();
    if (t == 0) {
        atomicAdd(&g_tdone[b], 1);
        while (*((volatile int*)&g_tdone[b]) < nb) __nanosleep(128);
    }
    __syncthreads();

    for (int squad = wi; squad < 256; squad += nb) {
        int s0 = squad * 4;

        if (t == 0) {
            while (*((volatile int*)&g_prog[b]) < s0 + 4) __nanosleep(64);
        }
        __syncthreads();

        // ---- ballquery: warp k handles center s0+k (identical logic) ----
        if (warp < 4) {
            int bs = b * Ss + s0 + warp;
            volatile float* C = (volatile float*)&g_centers[bs * 3];
            float cx = C[0], cy = C[1], cz = C[2];
            if (lane == 0) { sc3[warp * 3] = cx; sc3[warp * 3 + 1] = cy; sc3[warp * 3 + 2] = cz; }
            float csq = cx * cx + cy * cy + cz * cz;

            int cnt = 0, first = 0;
            int* G = &sgi[warp * 32];
            unsigned lanemask = (1u << lane) - 1u;
            for (int j0 = 0; j0 < Nn; j0 += 32) {
                int j = j0 + lane;
                float x = tile[j], y = tile[Nn + j], z = tile[2 * Nn + j];
                float dot = cx * x + cy * y + cz * z;
                float psq = x * x + y * y + z * z;
                float d = -2.0f * dot + csq + psq;
                bool ok = !(d > RAD2);
                unsigned m = __ballot_sync(0xffffffffu, ok);
                if (cnt == 0 && m) first = j0 + __ffs(m) - 1;
                int p = cnt + __popc(m & lanemask);
                if (ok && p < Kk) G[p] = j;
                cnt += __popc(m);
                if (cnt >= Kk) break;
            }
            for (int p = cnt + lane; p < Kk; p += 32) G[p] = first;
        }
        __syncthreads();

        // ---- gather 4 groups x 32 samples x 67 channels into xs ----
        for (int e = t; e < 4 * 32 * 67; e += 512) {
            int g = e / 2144;
            int r = e - g * 2144;
            int h = r / 67;
            int i = r - h * 67;
            int idx = sgi[g * 32 + h];
            float v;
            if (i < 3) v = tile[i * Nn + idx] - sc3[g * 3 + i];
            else       v = g_featT[(b * Nn + idx) * 64 + (i - 3)];
            xs[(g * 32 + h) * 68 + i] = v;
        }
        __syncthreads();

        // ---- conv0 GEMM: 512 threads, 4 groups ----
        int om = (t & 15) * 4;
        int hg = t >> 4;                     // 0..31
        int g  = hg >> 3;                    // 0..3
        int h4 = (hg & 7) * 4;

        float acc[4][4];
#pragma unroll
        for (int a = 0; a < 4; a++)
#pragma unroll
            for (int j = 0; j < 4; j++) acc[a][j] = 0.f;

        const float* xrow0 = &xs[(g * 32 + h4 + 0) * 68];
        const float* xrow1 = &xs[(g * 32 + h4 + 1) * 68];
        const float* xrow2 = &xs[(g * 32 + h4 + 2) * 68];
        const float* xrow3 = &xs[(g * 32 + h4 + 3) * 68];
        for (int i = 0; i < 67; i++) {
            float4 wv = *(const float4*)&wT[i * 64 + om];
            float xr0 = xrow0[i], xr1 = xrow1[i], xr2 = xrow2[i], xr3 = xrow3[i];
            acc[0][0] += xr0 * wv.x; acc[0][1] += xr0 * wv.y; acc[0][2] += xr0 * wv.z; acc[0][3] += xr0 * wv.w;
            acc[1][0] += xr1 * wv.x; acc[1][1] += xr1 * wv.y; acc[1][2] += xr1 * wv.z; acc[1][3] += xr1 * wv.w;
            acc[2][0] += xr2 * wv.x; acc[2][1] += xr2 * wv.y; acc[2][2] += xr2 * wv.z; acc[2][3] += xr2 * wv.w;
            acc[3][0] += xr3 * wv.x; acc[3][1] += xr3 * wv.y; acc[3][2] += xr3 * wv.z; acc[3][3] += xr3 * wv.w;
        }

        float4 bias4 = *(const float4*)&b0[om];
        float ls[4] = {0, 0, 0, 0}, lq[4] = {0, 0, 0, 0};
        int bs = b * Ss + s0 + g;
#pragma unroll
        for (int hh = 0; hh < 4; hh++) {
            float4 v;
            v.x = acc[hh][0] + bias4.x;
            v.y = acc[hh][1] + bias4.y;
            v.z = acc[hh][2] + bias4.z;
            v.w = acc[hh][3] + bias4.w;
            ls[0] += v.x; lq[0] += v.x * v.x;
            ls[1] += v.y; lq[1] += v.y * v.y;
            ls[2] += v.z; lq[2] += v.z * v.z;
            ls[3] += v.w; lq[3] += v.w * v.w;
            *(float4*)&g_y0[(bs * 32 + h4 + hh) * 64 + om] = v;
        }
#pragma unroll
        for (int j = 0; j < 4; j++) {
            atomicAdd(&ssum[om + j], ls[j]);
            atomicAdd(&ssq[om + j],  lq[j]);
        }
        __syncthreads();                     // protect xs/sgi for next task
    }

    if (t < 64) {
        atomicAdd(&g_sum0[t], ssum[t]);
        atomicAdd(&g_sq0[t],  ssq[t]);
    }
}

// ---------------- conv1: 64->64, 4 centers/block, 8x4 register tile -------------
__global__ __launch_bounds__(256) void conv1_kernel(const float* __restrict__ w1,
                                                    const float* __restrict__ b1,
                                                    const float* __restrict__ gam0,
                                                    const float* __restrict__ bet0) {
    extern __shared__ __align__(16) float dsm1[];
    float* wT = dsm1;                         // 64*64 = 4096 floats
    float* xs = dsm1 + 4096;                  // 4*32*64 = 8192 floats
    __shared__ float ssum[64], ssq[64];
    __shared__ float s_scale[64], s_shift[64];

    int t = threadIdx.x;
    int bs0 = blockIdx.x * 4;
    for (int e = t; e < 64 * 64; e += 256) {
        int o = e & 63, i = e >> 6;
        wT[i * 64 + o] = w1[o * 64 + i];
    }
    if (t < 64) {
        ssum[t] = 0.f; ssq[t] = 0.f;
        float mean = g_sum0[t] * (1.0f / NELEM);
        float var  = g_sq0[t] * (1.0f / NELEM) - mean * mean;
        float s = gam0[t] * rsqrtf(var + 1e-5f);
        s_scale[t] = s;
        s_shift[t] = bet0[t] - mean * s;
    }
    __syncthreads();

    const float* Y = &g_y0[bs0 * 2048];
    for (int e = t; e < 8192; e += 256) {
        int i = e & 63;
        float v = Y[e] * s_scale[i] + s_shift[i];
        xs[e] = fmaxf(v, 0.f);
    }
    __syncthreads();

    int om = (t & 15) * 4;
    int hg = t >> 4;                          // 0..15
    int g  = hg >> 2;                         // 0..3 (center)
    int h8 = (hg & 3) * 8;                    // 0,8,16,24

    float acc[8][4];
#pragma unroll
    for (int a = 0; a < 8; a++)
#pragma unroll
        for (int j = 0; j < 4; j++) acc[a][j] = 0.f;

    const float* xbase = &xs[(g * 32 + h8) * 64];
    for (int i = 0; i < 64; i += 4) {
        float4 wv0 = *(const float4*)&wT[(i + 0) * 64 + om];
        float4 wv1 = *(const float4*)&wT[(i + 1) * 64 + om];
        float4 wv2 = *(const float4*)&wT[(i + 2) * 64 + om];
        float4 wv3 = *(const float4*)&wT[(i + 3) * 64 + om];
#pragma unroll
        for (int r = 0; r < 8; r++) {
            float4 xv = *(const float4*)&xbase[r * 64 + i];
            acc[r][0] += xv.x * wv0.x; acc[r][1] += xv.x * wv0.y; acc[r][2] += xv.x * wv0.z; acc[r][3] += xv.x * wv0.w;
            acc[r][0] += xv.y * wv1.x; acc[r][1] += xv.y * wv1.y; acc[r][2] += xv.y * wv1.z; acc[r][3] += xv.y * wv1.w;
            acc[r][0] += xv.z * wv2.x; acc[r][1] += xv.z * wv2.y; acc[r][2] += xv.z * wv2.z; acc[r][3] += xv.z * wv2.w;
            acc[r][0] += xv.w * wv3.x; acc[r][1] += xv.w * wv3.y; acc[r][2] += xv.w * wv3.z; acc[r][3] += xv.w * wv3.w;
        }
    }

    float4 bias4 = *(const float4*)&b1[om];
    float ls[4] = {0, 0, 0, 0}, lq[4] = {0, 0, 0, 0};
    int bs = bs0 + g;
#pragma unroll
    for (int hh = 0; hh < 8; hh++) {
        float4 v;
        v.x = acc[hh][0] + bias4.x;
        v.y = acc[hh][1] + bias4.y;
        v.z = acc[hh][2] + bias4.z;
        v.w = acc[hh][3] + bias4.w;
        ls[0] += v.x; lq[0] += v.x * v.x;
        ls[1] += v.y; lq[1] += v.y * v.y;
        ls[2] += v.z; lq[2] += v.z * v.z;
        ls[3] += v.w; lq[3] += v.w * v.w;
        *(float4*)&g_y1[(bs * 32 + h8 + hh) * 64 + om] = v;
    }
#pragma unroll
    for (int j = 0; j < 4; j++) {
        atomicAdd(&ssum[om + j], ls[j]);
        atomicAdd(&ssq[om + j],  lq[j]);
    }
    __syncthreads();
    if (t < 64) {
        atomicAdd(&g_sum1[t], ssum[t]);
        atomicAdd(&g_sq1[t],  ssq[t]);
    }
}

// ---------------- conv2: 64->128, 2 centers/block, 8x4 register tile ------------
__global__ __launch_bounds__(256) void conv2_kernel(const float* __restrict__ w2,
                                                    const float* __restrict__ b2,
                                                    const float* __restrict__ gam1,
                                                    const float* __restrict__ bet1) {
    extern __shared__ __align__(16) float dsm2[];
    float* wT = dsm2;                         // 64*128 = 8192 floats
    float* xs = dsm2 + 8192;                  // 2*32*64 = 4096 floats
    __shared__ float ssum[128], ssq[128];
    __shared__ float s_scale[64], s_shift[64];

    int t = threadIdx.x;
    int bs0 = blockIdx.x * 2;
    for (int e = t; e < 64 * 128; e += 256) {
        int o = e & 127, i = e >> 7;
        wT[i * 128 + o] = w2[o * 64 + i];
    }
    if (t < 128) { ssum[t] = 0.f; ssq[t] = 0.f; }
    if (t < 64) {
        float mean = g_sum1[t] * (1.0f / NELEM);
        float var  = g_sq1[t] * (1.0f / NELEM) - mean * mean;
        float s = gam1[t] * rsqrtf(var + 1e-5f);
        s_scale[t] = s;
        s_shift[t] = bet1[t] - mean * s;
    }
    __syncthreads();

    const float* Y = &g_y1[bs0 * 2048];
    for (int e = t; e < 4096; e += 256) {
        int i = e & 63;
        float v = Y[e] * s_scale[i] + s_shift[i];
        xs[e] = fmaxf(v, 0.f);
    }
    __syncthreads();

    int om = (t & 31) * 4;
    int hg = t >> 5;                          // 0..7
    int g  = hg >> 2;                         // 0..1 (center)
    int h8 = (hg & 3) * 8;                    // 0,8,16,24

    float acc[8][4];
#pragma unroll
    for (int a = 0; a < 8; a++)
#pragma unroll
        for (int j = 0; j < 4; j++) acc[a][j] = 0.f;

    const float* xbase = &xs[(g * 32 + h8) * 64];
    for (int i = 0; i < 64; i += 4) {
        float4 wv0 = *(const float4*)&wT[(i + 0) * 128 + om];
        float4 wv1 = *(const float4*)&wT[(i + 1) * 128 + om];
        float4 wv2 = *(const float4*)&wT[(i + 2) * 128 + om];
        float4 wv3 = *(const float4*)&wT[(i + 3) * 128 + om];
#pragma unroll
        for (int r = 0; r < 8; r++) {
            float4 xv = *(const float4*)&xbase[r * 64 + i];
            acc[r][0] += xv.x * wv0.x; acc[r][1] += xv.x * wv0.y; acc[r][2] += xv.x * wv0.z; acc[r][3] += xv.x * wv0.w;
            acc[r][0] += xv.y * wv1.x; acc[r][1] += xv.y * wv1.y; acc[r][2] += xv.y * wv1.z; acc[r][3] += xv.y * wv1.w;
            acc[r][0] += xv.z * wv2.x; acc[r][1] += xv.z * wv2.y; acc[r][2] += xv.z * wv2.z; acc[r][3] += xv.z * wv2.w;
            acc[r][0] += xv.w * wv3.x; acc[r][1] += xv.w * wv3.y; acc[r][2] += xv.w * wv3.z; acc[r][3] += xv.w * wv3.w;
        }
    }

    float4 bias4 = *(const float4*)&b2[om];
    float ls[4] = {0, 0, 0, 0}, lq[4] = {0, 0, 0, 0};
    int bs = bs0 + g;
#pragma unroll
    for (int hh = 0; hh < 8; hh++) {
        float4 v;
        v.x = acc[hh][0] + bias4.x;
        v.y = acc[hh][1] + bias4.y;
        v.z = acc[hh][2] + bias4.z;
        v.w = acc[hh][3] + bias4.w;
        ls[0] += v.x; lq[0] += v.x * v.x;
        ls[1] += v.y; lq[1] += v.y * v.y;
        ls[2] += v.z; lq[2] += v.z * v.z;
        ls[3] += v.w; lq[3] += v.w * v.w;
        *(float4*)&g_y2[(bs * 32 + h8 + hh) * 128 + om] = v;
    }
#pragma unroll
    for (int j = 0; j < 4; j++) {
        atomicAdd(&ssum[om + j], ls[j]);
        atomicAdd(&ssq[om + j],  lq[j]);
    }
    __syncthreads();
    if (t < 128) {
        atomicAdd(&g_sum2[t], ssum[t]);
        atomicAdd(&g_sq2[t],  ssq[t]);
    }
}

// ---------------- final: inline BN2 + ReLU + max pool + poscopy -----------------
__global__ __launch_bounds__(256) void finalpool_kernel(float* __restrict__ out,
                                                        const float* __restrict__ gam2,
                                                        const float* __restrict__ bet2) {
    __shared__ float s_sc[128], s_sh[128];
    int t = threadIdx.x;
    if (t < 128) {
        float mean = g_sum2[t] * (1.0f / NELEM);
        float var  = g_sq2[t] * (1.0f / NELEM) - mean * mean;
        float s = gam2[t] * rsqrtf(var + 1e-5f);
        s_sc[t] = s;
        s_sh[t] = bet2[t] - mean * s;
    }
    __syncthreads();

    int gwarp = (blockIdx.x * blockDim.x + t) >> 5;   // bs
    int lane = t & 31;
    {
        int bs = gwarp;
        int b = bs >> 10, s = bs & 1023;

        float scl[4], sft[4];
#pragma unroll
        for (int j = 0; j < 4; j++) {
            scl[j] = s_sc[lane + 32 * j];
            sft[j] = s_sh[lane + 32 * j];
        }
        float m[4] = {-3.4e38f, -3.4e38f, -3.4e38f, -3.4e38f};
        const float* Y = &g_y2[bs * 32 * 128];
        for (int h = 0; h < 32; h++) {
#pragma unroll
            for (int j = 0; j < 4; j++) {
                float v = Y[h * 128 + lane + 32 * j] * scl[j] + sft[j];
                v = fmaxf(v, 0.f);
                m[j] = fmaxf(m[j], v);
            }
        }
        float* F = out + Bb * 3 * Ss + b * 128 * Ss + s;
#pragma unroll
        for (int j = 0; j < 4; j++) F[(lane + 32 * j) * Ss] = m[j];
    }

    // fused poscopy: first 24576 global threads copy pos_out
    int e = blockIdx.x * blockDim.x + t;
    if (e < Bb * 3 * Ss) {
        int b2_ = e / (3 * Ss);
        int r = e - b2_ * (3 * Ss);
        int c = r / Ss;
        int s2 = r - c * Ss;
        out[e] = g_centers[(b2_ * Ss + s2) * 3 + c];
    }
}

// ---------------- launch --------------------------------------------------------
extern "C" void kernel_launch(void* const* d_in, const int* in_sizes, int n_in,
                              void* d_out, int out_size) {
    const float* pos  = (const float*)d_in[0];
    const float* feat = (const float*)d_in[1];
    const float* w0   = (const float*)d_in[2];
    const float* b0   = (const float*)d_in[3];
    const float* g0   = (const float*)d_in[4];
    const float* be0  = (const float*)d_in[5];
    const float* w1   = (const float*)d_in[6];
    const float* b1   = (const float*)d_in[7];
    const float* g1   = (const float*)d_in[8];
    const float* be1  = (const float*)d_in[9];
    const float* w2   = (const float*)d_in[10];
    const float* b2   = (const float*)d_in[11];
    const float* g2   = (const float*)d_in[12];
    const float* be2  = (const float*)d_in[13];
    float* out = (float*)d_out;

    const int FUSED_DYN = (3 * Nn + 67 * 64 + 4 * 32 * 68) * (int)sizeof(float); // 101120
    const int C1_DYN = (64 * 64 + 4 * 32 * 64) * (int)sizeof(float);             // 49152
    const int C2_DYN = (64 * 128 + 2 * 32 * 64) * (int)sizeof(float);            // 49152
    cudaFuncSetAttribute(fused_kernel, cudaFuncAttributeMaxDynamicSharedMemorySize, FUSED_DYN);
    cudaFuncSetAttribute(conv1_kernel, cudaFuncAttributeMaxDynamicSharedMemorySize, C1_DYN);
    cudaFuncSetAttribute(conv2_kernel, cudaFuncAttributeMaxDynamicSharedMemorySize, C2_DYN);

    zero_stats_kernel<<<1, 128>>>();                             // 1
    fused_kernel<<<148, 512, FUSED_DYN>>>(pos, feat, w0, b0);    // 2
    conv1_kernel<<<Bb * Ss / 4, 256, C1_DYN>>>(w1, b1, g0, be0); // 3
    conv2_kernel<<<Bb * Ss / 2, 256, C2_DYN>>>(w2, b2, g1, be1); // 4
    finalpool_kernel<<<Bb * Ss / 8, 256>>>(out, g2, be2);        // 5
}

// round 12
// speedup vs baseline: 1.9172x; 1.0478x over previous
#include <cuda_runtime.h>
#include <cuda_bf16.h>
#include <cstdint>

#define Bb 8
#define Nn 4096
#define Dd 64
#define Ss 1024
#define Kk 32
#define RAD2 0.04f
#define NELEM 262144.0f   // B*32*S elements per channel for BN

// ---------------- scratch (device globals; no allocation allowed) ----------------
__device__ float g_featT[Bb * Nn * Dd];            // [b][n][c] point-major features
__device__ float g_centers[Bb * Ss * 3];           // [bs][3]
__device__ int   g_prog[Bb];                       // FPS progress (centers published)
__device__ int   g_tdone[Bb];                      // workers done transposing
__device__ float g_y0[Bb * Ss * Kk * 64];          // [bs][h][o]
__device__ float g_y1[Bb * Ss * Kk * 64];
__device__ float g_ymax[Bb * Ss * 128];            // per-(bs,c) max_h of y2 (pre-BN)
__device__ float g_ymin[Bb * Ss * 128];            // per-(bs,c) min_h of y2 (pre-BN)
__device__ float g_sum0[64],  g_sq0[64];
__device__ float g_sum1[64],  g_sq1[64];
__device__ float g_sum2[128], g_sq2[128];

__device__ __forceinline__ unsigned enc_mono(float f) {
    unsigned u = __float_as_uint(f);
    return (u & 0x80000000u) ? ~u : (u | 0x80000000u);
}
__device__ __forceinline__ float dec_mono(unsigned u) {
    return (u & 0x80000000u) ? __uint_as_float(u & 0x7fffffffu) : __uint_as_float(~u);
}

// ---------------- zero stats + progress ----------------
__global__ void zero_stats_kernel() {
    int t = threadIdx.x;
    if (t < 64)  { g_sum0[t] = 0.f; g_sq0[t] = 0.f; g_sum1[t] = 0.f; g_sq1[t] = 0.f; }
    if (t < 128) { g_sum2[t] = 0.f; g_sq2[t] = 0.f; }
    if (t < Bb)  { g_prog[t] = 0; g_tdone[t] = 0; }
}

// =====================================================================
// FUSED persistent kernel, grid = 148 (one wave, all co-resident):
//   blocks 0..7   : FPS producer (identical selection math)
//   blocks 8..147 : workers: transpose feat slice -> per-batch barrier;
//                   then per squad of 4 centers: wait progress ->
//                   ballquery (4 warps) -> conv0 GEMM + BN stats
// =====================================================================
__global__ __launch_bounds__(512) void fused_kernel(const float* __restrict__ pos,
                                                    const float* __restrict__ feat,
                                                    const float* __restrict__ w0,
                                                    const float* __restrict__ b0) {
    extern __shared__ __align__(16) float dyn[];
    float* tile = dyn;                       // [x:4096][y:4096][z:4096]
    int t = threadIdx.x;
    int warp = t >> 5, lane = t & 31;

    if (blockIdx.x < 8) {
        // ------------------- FPS producer -------------------
        float* sx = tile;
        float* sy = tile + Nn;
        float* sz = tile + 2 * Nn;
        __shared__ unsigned long long s_mv[2][16];

        int b = blockIdx.x;
        const float* P = pos + b * 3 * Nn;

        float px[8], py[8], pz[8], cum[8];
#pragma unroll
        for (int j = 0; j < 8; j++) {
            int n = t + 512 * j;
            px[j] = P[n];
            py[j] = P[Nn + n];
            pz[j] = P[2 * Nn + n];
            sx[n] = px[j]; sy[n] = py[j]; sz[n] = pz[j];
            cum[j] = 0.f;
        }

        const float NEG = -3.4e38f;
        if (t == 0) cum[0] = NEG;            // point 0 pre-selected
        __syncthreads();

        int cur = 0;
        for (int step = 1; step < Ss; step++) {
            int par = step & 1;
            float cx = sx[cur], cy = sy[cur], cz = sz[cur];

            if (t == 0) {
                float* c = &g_centers[(b * Ss + step - 1) * 3];
                c[0] = cx; c[1] = cy; c[2] = cz;
                if ((step & 31) == 0) {
                    __threadfence();
                    atomicExch(&g_prog[b], step);   // centers [0, step) published
                }
            }

            float m = NEG;
#pragma unroll
            for (int j = 0; j < 8; j++) {
                float dx = px[j] - cx, dy = py[j] - cy, dz = pz[j] - cz;
                float sqd = dx * dx + dy * dy + dz * dz;
                cum[j] = cum[j] + sqd;
                m = fmaxf(m, cum[j]);
            }

            unsigned um = enc_mono(m);
            unsigned uw = __reduce_max_sync(0xffffffffu, um);

            float mw = dec_mono(uw);
            int idx = 0x7fffffff;
#pragma unroll
            for (int j = 0; j < 8; j++)
                if (cum[j] == mw) idx = min(idx, t + 512 * j);
            idx = __reduce_min_sync(0xffffffffu, idx);

            if (lane == 0)
                s_mv[par][warp] = ((unsigned long long)uw << 32) | (unsigned)(~idx);
            __syncthreads();

            unsigned long long pk = s_mv[par][lane & 15];
            unsigned hi = (unsigned)(pk >> 32);
            unsigned lo = (unsigned)pk;
            unsigned mh = __reduce_max_sync(0xffffffffu, hi);
            unsigned ml = __reduce_max_sync(0xffffffffu, (hi == mh) ? lo : 0u);
            cur = (int)(~ml);

#pragma unroll
            for (int j = 0; j < 8; j++)
                if (cur == t + 512 * j) cum[j] = NEG;
        }

        if (t == 0) {
            float* c = &g_centers[(b * Ss + Ss - 1) * 3];
            c[0] = sx[cur]; c[1] = sy[cur]; c[2] = sz[cur];
            __threadfence();
            atomicExch(&g_prog[b], Ss);
        }
        return;
    }

    // ------------------- worker -------------------
    float* wT = dyn + 3 * Nn;                // 67*64 floats
    float* xs = dyn + 3 * Nn + 67 * 64;      // 8704 floats
    __shared__ int   sgi[128];
    __shared__ float sc3[12];
    __shared__ float ssum[64], ssq[64];

    int w  = blockIdx.x - 8;                 // 0..139
    int b  = w & 7;
    int wi = w >> 3;                         // 0..17
    int nb = (b < 4) ? 18 : 17;              // workers serving this batch

    const float* P = pos + b * 3 * Nn;
    for (int i = t; i < 3 * Nn; i += 512) tile[i] = P[i];
    for (int e = t; e < 67 * 64; e += 512) {
        int o = e & 63, i = e >> 6;
        wT[i * 64 + o] = w0[o * 67 + i];
    }
    if (t < 64) { ssum[t] = 0.f; ssq[t] = 0.f; }
    __syncthreads();

    // ---- cooperative feature transpose (hidden under FPS) ----
    const float* Fb = feat + b * (Dd * Nn);
    for (int tt = wi; tt < 128; tt += nb) {
        int n0 = tt * 32;
        for (int e = t; e < 2048; e += 512) {
            int c = e >> 5, i2 = e & 31;
            xs[i2 * 65 + c] = Fb[c * Nn + n0 + i2];      // coalesced read
        }
        __syncthreads();
        for (int e = t; e < 2048; e += 512) {
            int n = e >> 6, c = e & 63;
            g_featT[(b * Nn + n0 + n) * 64 + c] = xs[n * 65 + c];  // coalesced write
        }
        __syncthreads();
    }
    __threadfence();
    if (t == 0) {
        atomicAdd(&g_tdone[b], 1);
        while (*((volatile int*)&g_tdone[b]) < nb) __nanosleep(128);
    }
    __syncthreads();

    for (int squad = wi; squad < 256; squad += nb) {
        int s0 = squad * 4;

        if (t == 0) {
            while (*((volatile int*)&g_prog[b]) < s0 + 4) __nanosleep(64);
        }
        __syncthreads();

        // ---- ballquery: warp k handles center s0+k (identical logic) ----
        if (warp < 4) {
            int bs = b * Ss + s0 + warp;
            volatile float* C = (volatile float*)&g_centers[bs * 3];
            float cx = C[0], cy = C[1], cz = C[2];
            if (lane == 0) { sc3[warp * 3] = cx; sc3[warp * 3 + 1] = cy; sc3[warp * 3 + 2] = cz; }
            float csq = cx * cx + cy * cy + cz * cz;

            int cnt = 0, first = 0;
            int* G = &sgi[warp * 32];
            unsigned lanemask = (1u << lane) - 1u;
            for (int j0 = 0; j0 < Nn; j0 += 32) {
                int j = j0 + lane;
                float x = tile[j], y = tile[Nn + j], z = tile[2 * Nn + j];
                float dot = cx * x + cy * y + cz * z;
                float psq = x * x + y * y + z * z;
                float d = -2.0f * dot + csq + psq;
                bool ok = !(d > RAD2);
                unsigned m = __ballot_sync(0xffffffffu, ok);
                if (cnt == 0 && m) first = j0 + __ffs(m) - 1;
                int p = cnt + __popc(m & lanemask);
                if (ok && p < Kk) G[p] = j;
                cnt += __popc(m);
                if (cnt >= Kk) break;
            }
            for (int p = cnt + lane; p < Kk; p += 32) G[p] = first;
        }
        __syncthreads();

        // ---- gather 4 groups x 32 samples x 67 channels into xs ----
        for (int e = t; e < 4 * 32 * 67; e += 512) {
            int g = e / 2144;
            int r = e - g * 2144;
            int h = r / 67;
            int i = r - h * 67;
            int idx = sgi[g * 32 + h];
            float v;
            if (i < 3) v = tile[i * Nn + idx] - sc3[g * 3 + i];
            else       v = g_featT[(b * Nn + idx) * 64 + (i - 3)];
            xs[(g * 32 + h) * 68 + i] = v;
        }
        __syncthreads();

        // ---- conv0 GEMM: 512 threads, 4 groups ----
        int om = (t & 15) * 4;
        int hg = t >> 4;                     // 0..31
        int g  = hg >> 3;                    // 0..3
        int h4 = (hg & 7) * 4;

        float acc[4][4];
#pragma unroll
        for (int a = 0; a < 4; a++)
#pragma unroll
            for (int j = 0; j < 4; j++) acc[a][j] = 0.f;

        const float* xrow0 = &xs[(g * 32 + h4 + 0) * 68];
        const float* xrow1 = &xs[(g * 32 + h4 + 1) * 68];
        const float* xrow2 = &xs[(g * 32 + h4 + 2) * 68];
        const float* xrow3 = &xs[(g * 32 + h4 + 3) * 68];
        for (int i = 0; i < 67; i++) {
            float4 wv = *(const float4*)&wT[i * 64 + om];
            float xr0 = xrow0[i], xr1 = xrow1[i], xr2 = xrow2[i], xr3 = xrow3[i];
            acc[0][0] += xr0 * wv.x; acc[0][1] += xr0 * wv.y; acc[0][2] += xr0 * wv.z; acc[0][3] += xr0 * wv.w;
            acc[1][0] += xr1 * wv.x; acc[1][1] += xr1 * wv.y; acc[1][2] += xr1 * wv.z; acc[1][3] += xr1 * wv.w;
            acc[2][0] += xr2 * wv.x; acc[2][1] += xr2 * wv.y; acc[2][2] += xr2 * wv.z; acc[2][3] += xr2 * wv.w;
            acc[3][0] += xr3 * wv.x; acc[3][1] += xr3 * wv.y; acc[3][2] += xr3 * wv.z; acc[3][3] += xr3 * wv.w;
        }

        float4 bias4 = *(const float4*)&b0[om];
        float ls[4] = {0, 0, 0, 0}, lq[4] = {0, 0, 0, 0};
        int bs = b * Ss + s0 + g;
#pragma unroll
        for (int hh = 0; hh < 4; hh++) {
            float4 v;
            v.x = acc[hh][0] + bias4.x;
            v.y = acc[hh][1] + bias4.y;
            v.z = acc[hh][2] + bias4.z;
            v.w = acc[hh][3] + bias4.w;
            ls[0] += v.x; lq[0] += v.x * v.x;
            ls[1] += v.y; lq[1] += v.y * v.y;
            ls[2] += v.z; lq[2] += v.z * v.z;
            ls[3] += v.w; lq[3] += v.w * v.w;
            *(float4*)&g_y0[(bs * 32 + h4 + hh) * 64 + om] = v;
        }
#pragma unroll
        for (int j = 0; j < 4; j++) {
            atomicAdd(&ssum[om + j], ls[j]);
            atomicAdd(&ssq[om + j],  lq[j]);
        }
        __syncthreads();                     // protect xs/sgi for next task
    }

    if (t < 64) {
        atomicAdd(&g_sum0[t], ssum[t]);
        atomicAdd(&g_sq0[t],  ssq[t]);
    }
}

// ---------------- conv1: 64->64, 4 centers/block, 8x4 register tile -------------
__global__ __launch_bounds__(256) void conv1_kernel(const float* __restrict__ w1,
                                                    const float* __restrict__ b1,
                                                    const float* __restrict__ gam0,
                                                    const float* __restrict__ bet0) {
    extern __shared__ __align__(16) float dsm1[];
    float* wT = dsm1;                         // 64*64 = 4096 floats
    float* xs = dsm1 + 4096;                  // 4*32*64 = 8192 floats
    __shared__ float ssum[64], ssq[64];
    __shared__ float s_scale[64], s_shift[64];

    int t = threadIdx.x;
    int bs0 = blockIdx.x * 4;
    for (int e = t; e < 64 * 64; e += 256) {
        int o = e & 63, i = e >> 6;
        wT[i * 64 + o] = w1[o * 64 + i];
    }
    if (t < 64) {
        ssum[t] = 0.f; ssq[t] = 0.f;
        float mean = g_sum0[t] * (1.0f / NELEM);
        float var  = g_sq0[t] * (1.0f / NELEM) - mean * mean;
        float s = gam0[t] * rsqrtf(var + 1e-5f);
        s_scale[t] = s;
        s_shift[t] = bet0[t] - mean * s;
    }
    __syncthreads();

    const float* Y = &g_y0[bs0 * 2048];
    for (int e = t; e < 8192; e += 256) {
        int i = e & 63;
        float v = Y[e] * s_scale[i] + s_shift[i];
        xs[e] = fmaxf(v, 0.f);
    }
    __syncthreads();

    int om = (t & 15) * 4;
    int hg = t >> 4;                          // 0..15
    int g  = hg >> 2;                         // 0..3 (center)
    int h8 = (hg & 3) * 8;                    // 0,8,16,24

    float acc[8][4];
#pragma unroll
    for (int a = 0; a < 8; a++)
#pragma unroll
        for (int j = 0; j < 4; j++) acc[a][j] = 0.f;

    const float* xbase = &xs[(g * 32 + h8) * 64];
    for (int i = 0; i < 64; i += 4) {
        float4 wv0 = *(const float4*)&wT[(i + 0) * 64 + om];
        float4 wv1 = *(const float4*)&wT[(i + 1) * 64 + om];
        float4 wv2 = *(const float4*)&wT[(i + 2) * 64 + om];
        float4 wv3 = *(const float4*)&wT[(i + 3) * 64 + om];
#pragma unroll
        for (int r = 0; r < 8; r++) {
            float4 xv = *(const float4*)&xbase[r * 64 + i];
            acc[r][0] += xv.x * wv0.x; acc[r][1] += xv.x * wv0.y; acc[r][2] += xv.x * wv0.z; acc[r][3] += xv.x * wv0.w;
            acc[r][0] += xv.y * wv1.x; acc[r][1] += xv.y * wv1.y; acc[r][2] += xv.y * wv1.z; acc[r][3] += xv.y * wv1.w;
            acc[r][0] += xv.z * wv2.x; acc[r][1] += xv.z * wv2.y; acc[r][2] += xv.z * wv2.z; acc[r][3] += xv.z * wv2.w;
            acc[r][0] += xv.w * wv3.x; acc[r][1] += xv.w * wv3.y; acc[r][2] += xv.w * wv3.z; acc[r][3] += xv.w * wv3.w;
        }
    }

    float4 bias4 = *(const float4*)&b1[om];
    float ls[4] = {0, 0, 0, 0}, lq[4] = {0, 0, 0, 0};
    int bs = bs0 + g;
#pragma unroll
    for (int hh = 0; hh < 8; hh++) {
        float4 v;
        v.x = acc[hh][0] + bias4.x;
        v.y = acc[hh][1] + bias4.y;
        v.z = acc[hh][2] + bias4.z;
        v.w = acc[hh][3] + bias4.w;
        ls[0] += v.x; lq[0] += v.x * v.x;
        ls[1] += v.y; lq[1] += v.y * v.y;
        ls[2] += v.z; lq[2] += v.z * v.z;
        ls[3] += v.w; lq[3] += v.w * v.w;
        *(float4*)&g_y1[(bs * 32 + h8 + hh) * 64 + om] = v;
    }
#pragma unroll
    for (int j = 0; j < 4; j++) {
        atomicAdd(&ssum[om + j], ls[j]);
        atomicAdd(&ssq[om + j],  lq[j]);
    }
    __syncthreads();
    if (t < 64) {
        atomicAdd(&g_sum1[t], ssum[t]);
        atomicAdd(&g_sq1[t],  ssq[t]);
    }
}

// ---------------- conv2: 64->128, 2 centers/block, 8x4 tile, NO y2 store --------
// Outputs only: BN2 stats (ssum/ssq) + per-(bs,channel) max/min of y2 over h.
__global__ __launch_bounds__(256) void conv2_kernel(const float* __restrict__ w2,
                                                    const float* __restrict__ b2,
                                                    const float* __restrict__ gam1,
                                                    const float* __restrict__ bet1) {
    extern __shared__ __align__(16) float dsm2[];
    float* wT = dsm2;                         // 64*128 = 8192 floats
    float* xs = dsm2 + 8192;                  // 2*32*64 = 4096 floats
    __shared__ float ssum[128], ssq[128];
    __shared__ float s_scale[64], s_shift[64];
    __shared__ unsigned smax[256], smin[256]; // [g][c] monotone-encoded

    int t = threadIdx.x;
    int bs0 = blockIdx.x * 2;
    for (int e = t; e < 64 * 128; e += 256) {
        int o = e & 127, i = e >> 7;
        wT[i * 128 + o] = w2[o * 64 + i];
    }
    if (t < 128) { ssum[t] = 0.f; ssq[t] = 0.f; }
    smax[t] = 0u;
    smin[t] = 0xffffffffu;
    if (t < 64) {
        float mean = g_sum1[t] * (1.0f / NELEM);
        float var  = g_sq1[t] * (1.0f / NELEM) - mean * mean;
        float s = gam1[t] * rsqrtf(var + 1e-5f);
        s_scale[t] = s;
        s_shift[t] = bet1[t] - mean * s;
    }
    __syncthreads();

    const float* Y = &g_y1[bs0 * 2048];
    for (int e = t; e < 4096; e += 256) {
        int i = e & 63;
        float v = Y[e] * s_scale[i] + s_shift[i];
        xs[e] = fmaxf(v, 0.f);
    }
    __syncthreads();

    int om = (t & 31) * 4;
    int hg = t >> 5;                          // 0..7
    int g  = hg >> 2;                         // 0..1 (center)
    int h8 = (hg & 3) * 8;                    // 0,8,16,24

    float acc[8][4];
#pragma unroll
    for (int a = 0; a < 8; a++)
#pragma unroll
        for (int j = 0; j < 4; j++) acc[a][j] = 0.f;

    const float* xbase = &xs[(g * 32 + h8) * 64];
    for (int i = 0; i < 64; i += 4) {
        float4 wv0 = *(const float4*)&wT[(i + 0) * 128 + om];
        float4 wv1 = *(const float4*)&wT[(i + 1) * 128 + om];
        float4 wv2 = *(const float4*)&wT[(i + 2) * 128 + om];
        float4 wv3 = *(const float4*)&wT[(i + 3) * 128 + om];
#pragma unroll
        for (int r = 0; r < 8; r++) {
            float4 xv = *(const float4*)&xbase[r * 64 + i];
            acc[r][0] += xv.x * wv0.x; acc[r][1] += xv.x * wv0.y; acc[r][2] += xv.x * wv0.z; acc[r][3] += xv.x * wv0.w;
            acc[r][0] += xv.y * wv1.x; acc[r][1] += xv.y * wv1.y; acc[r][2] += xv.y * wv1.z; acc[r][3] += xv.y * wv1.w;
            acc[r][0] += xv.z * wv2.x; acc[r][1] += xv.z * wv2.y; acc[r][2] += xv.z * wv2.z; acc[r][3] += xv.z * wv2.w;
            acc[r][0] += xv.w * wv3.x; acc[r][1] += xv.w * wv3.y; acc[r][2] += xv.w * wv3.z; acc[r][3] += xv.w * wv3.w;
        }
    }

    float4 bias4 = *(const float4*)&b2[om];
    float ls[4] = {0, 0, 0, 0}, lq[4] = {0, 0, 0, 0};
    float vmx[4] = {-3.4e38f, -3.4e38f, -3.4e38f, -3.4e38f};
    float vmn[4] = { 3.4e38f,  3.4e38f,  3.4e38f,  3.4e38f};
#pragma unroll
    for (int hh = 0; hh < 8; hh++) {
        float4 v;
        v.x = acc[hh][0] + bias4.x;
        v.y = acc[hh][1] + bias4.y;
        v.z = acc[hh][2] + bias4.z;
        v.w = acc[hh][3] + bias4.w;
        ls[0] += v.x; lq[0] += v.x * v.x;
        ls[1] += v.y; lq[1] += v.y * v.y;
        ls[2] += v.z; lq[2] += v.z * v.z;
        ls[3] += v.w; lq[3] += v.w * v.w;
        vmx[0] = fmaxf(vmx[0], v.x); vmn[0] = fminf(vmn[0], v.x);
        vmx[1] = fmaxf(vmx[1], v.y); vmn[1] = fminf(vmn[1], v.y);
        vmx[2] = fmaxf(vmx[2], v.z); vmn[2] = fminf(vmn[2], v.z);
        vmx[3] = fmaxf(vmx[3], v.w); vmn[3] = fminf(vmn[3], v.w);
    }
#pragma unroll
    for (int j = 0; j < 4; j++) {
        atomicAdd(&ssum[om + j], ls[j]);
        atomicAdd(&ssq[om + j],  lq[j]);
        atomicMax(&smax[g * 128 + om + j], enc_mono(vmx[j]));
        atomicMin(&smin[g * 128 + om + j], enc_mono(vmn[j]));
    }
    __syncthreads();
    if (t < 128) {
        atomicAdd(&g_sum2[t], ssum[t]);
        atomicAdd(&g_sq2[t],  ssq[t]);
    }
    // write per-center channel max/min: t -> (g=t>>7, c=t&127)
    {
        int gg = t >> 7, cc = t & 127;
        int bs = bs0 + gg;
        g_ymax[bs * 128 + cc] = dec_mono(smax[gg * 128 + cc]);
        g_ymin[bs * 128 + cc] = dec_mono(smin[gg * 128 + cc]);
    }
}

// ---------------- final: BN2 on pooled extrema + relu + poscopy -----------------
__global__ __launch_bounds__(256) void finalpool_kernel(float* __restrict__ out,
                                                        const float* __restrict__ gam2,
                                                        const float* __restrict__ bet2) {
    __shared__ float s_sc[128], s_sh[128];
    int t = threadIdx.x;
    if (t < 128) {
        float mean = g_sum2[t] * (1.0f / NELEM);
        float var  = g_sq2[t] * (1.0f / NELEM) - mean * mean;
        float s = gam2[t] * rsqrtf(var + 1e-5f);
        s_sc[t] = s;
        s_sh[t] = bet2[t] - mean * s;
    }
    __syncthreads();

    int gwarp = (blockIdx.x * blockDim.x + t) >> 5;   // bs
    int lane = t & 31;
    {
        int bs = gwarp;
        int b = bs >> 10, s = bs & 1023;
        const float* MX = &g_ymax[bs * 128];
        const float* MN = &g_ymin[bs * 128];
        float* F = out + Bb * 3 * Ss + b * 128 * Ss + s;
#pragma unroll
        for (int j = 0; j < 4; j++) {
            int c = lane + 32 * j;
            float scl = s_sc[c], sft = s_sh[c];
            float y = (scl >= 0.f) ? MX[c] : MN[c];
            float v = fmaxf(y * scl + sft, 0.f);
            F[c * Ss] = v;
        }
    }

    // fused poscopy: first 24576 global threads copy pos_out
    int e = blockIdx.x * blockDim.x + t;
    if (e < Bb * 3 * Ss) {
        int b2_ = e / (3 * Ss);
        int r = e - b2_ * (3 * Ss);
        int c = r / Ss;
        int s2 = r - c * Ss;
        out[e] = g_centers[(b2_ * Ss + s2) * 3 + c];
    }
}

// ---------------- launch --------------------------------------------------------
extern "C" void kernel_launch(void* const* d_in, const int* in_sizes, int n_in,
                              void* d_out, int out_size) {
    const float* pos  = (const float*)d_in[0];
    const float* feat = (const float*)d_in[1];
    const float* w0   = (const float*)d_in[2];
    const float* b0   = (const float*)d_in[3];
    const float* g0   = (const float*)d_in[4];
    const float* be0  = (const float*)d_in[5];
    const float* w1   = (const float*)d_in[6];
    const float* b1   = (const float*)d_in[7];
    const float* g1   = (const float*)d_in[8];
    const float* be1  = (const float*)d_in[9];
    const float* w2   = (const float*)d_in[10];
    const float* b2   = (const float*)d_in[11];
    const float* g2   = (const float*)d_in[12];
    const float* be2  = (const float*)d_in[13];
    float* out = (float*)d_out;

    const int FUSED_DYN = (3 * Nn + 67 * 64 + 4 * 32 * 68) * (int)sizeof(float); // 101120
    const int C1_DYN = (64 * 64 + 4 * 32 * 64) * (int)sizeof(float);             // 49152
    const int C2_DYN = (64 * 128 + 2 * 32 * 64) * (int)sizeof(float);            // 49152
    cudaFuncSetAttribute(fused_kernel, cudaFuncAttributeMaxDynamicSharedMemorySize, FUSED_DYN);
    cudaFuncSetAttribute(conv1_kernel, cudaFuncAttributeMaxDynamicSharedMemorySize, C1_DYN);
    cudaFuncSetAttribute(conv2_kernel, cudaFuncAttributeMaxDynamicSharedMemorySize, C2_DYN);

    zero_stats_kernel<<<1, 128>>>();                             // 1
    fused_kernel<<<148, 512, FUSED_DYN>>>(pos, feat, w0, b0);    // 2
    conv1_kernel<<<Bb * Ss / 4, 256, C1_DYN>>>(w1, b1, g0, be0); // 3
    conv2_kernel<<<Bb * Ss / 2, 256, C2_DYN>>>(w2, b2, g1, be1); // 4
    finalpool_kernel<<<Bb * Ss / 8, 256>>>(out, g2, be2);        // 5
}

// round 14
// speedup vs baseline: 2.1175x; 1.1045x over previous
#include <cuda_runtime.h>
#include <cuda_bf16.h>
#include <cstdint>

#define Bb 8
#define Nn 4096
#define Dd 64
#define Ss 1024
#define Kk 32
#define RAD2 0.04f
#define NELEM 262144.0f   // B*32*S elements per channel for BN

// ---------------- scratch (device globals; no allocation allowed) ----------------
__device__ float g_featT[Bb * Nn * Dd];            // [b][n][c] point-major features
__device__ float g_centers[Bb * Ss * 3];           // [bs][3]
__device__ int   g_prog[Bb];                       // FPS progress (centers published)
__device__ int   g_tdone[Bb];                      // workers done transposing
__device__ float g_y0[Bb * Ss * Kk * 64];          // [bs][h][o]
__device__ float g_y1[Bb * Ss * Kk * 64];
__device__ float g_ymax[Bb * Ss * 128];            // per-(bs,c) max_h of y2 (pre-BN)
__device__ float g_ymin[Bb * Ss * 128];            // per-(bs,c) min_h of y2 (pre-BN)
__device__ float g_sum0[64],  g_sq0[64];
__device__ float g_sum1[64],  g_sq1[64];
__device__ float g_sum2[128], g_sq2[128];

__device__ __forceinline__ unsigned enc_mono(float f) {
    unsigned u = __float_as_uint(f);
    return (u & 0x80000000u) ? ~u : (u | 0x80000000u);
}
__device__ __forceinline__ float dec_mono(unsigned u) {
    return (u & 0x80000000u) ? __uint_as_float(u & 0x7fffffffu) : __uint_as_float(~u);
}

// ---------------- zero stats + progress ----------------
__global__ void zero_stats_kernel() {
    int t = threadIdx.x;
    if (t < 64)  { g_sum0[t] = 0.f; g_sq0[t] = 0.f; g_sum1[t] = 0.f; g_sq1[t] = 0.f; }
    if (t < 128) { g_sum2[t] = 0.f; g_sq2[t] = 0.f; }
    if (t < Bb)  { g_prog[t] = 0; g_tdone[t] = 0; }
}

// =====================================================================
// FUSED persistent kernel, grid = 148 (one wave, all co-resident):
//   blocks 0..7   : FPS producer (identical selection math)
//   blocks 8..147 : workers: transpose feat slice -> per-batch barrier;
//                   then per squad of 4 centers: wait progress ->
//                   ballquery (4 warps) -> conv0 GEMM + BN stats
// =====================================================================
__global__ __launch_bounds__(512) void fused_kernel(const float* __restrict__ pos,
                                                    const float* __restrict__ feat,
                                                    const float* __restrict__ w0,
                                                    const float* __restrict__ b0) {
    extern __shared__ __align__(16) float dyn[];
    float* tile = dyn;                       // [x:4096][y:4096][z:4096]
    int t = threadIdx.x;
    int warp = t >> 5, lane = t & 31;

    if (blockIdx.x < 8) {
        // ------------------- FPS producer -------------------
        float* sx = tile;
        float* sy = tile + Nn;
        float* sz = tile + 2 * Nn;
        __shared__ unsigned long long s_mv[2][16];

        int b = blockIdx.x;
        const float* P = pos + b * 3 * Nn;

        float px[8], py[8], pz[8], cum[8];
#pragma unroll
        for (int j = 0; j < 8; j++) {
            int n = t + 512 * j;
            px[j] = P[n];
            py[j] = P[Nn + n];
            pz[j] = P[2 * Nn + n];
            sx[n] = px[j]; sy[n] = py[j]; sz[n] = pz[j];
            cum[j] = 0.f;
        }

        const float NEG = -3.4e38f;
        if (t == 0) cum[0] = NEG;            // point 0 pre-selected
        __syncthreads();

        int cur = 0;
        for (int step = 1; step < Ss; step++) {
            int par = step & 1;
            float cx = sx[cur], cy = sy[cur], cz = sz[cur];

            if (t == 0) {
                float* c = &g_centers[(b * Ss + step - 1) * 3];
                c[0] = cx; c[1] = cy; c[2] = cz;
                if ((step & 31) == 0) {
                    __threadfence();
                    atomicExch(&g_prog[b], step);   // centers [0, step) published
                }
            }

            float m = NEG;
#pragma unroll
            for (int j = 0; j < 8; j++) {
                float dx = px[j] - cx, dy = py[j] - cy, dz = pz[j] - cz;
                float sqd = dx * dx + dy * dy + dz * dz;
                cum[j] = cum[j] + sqd;
                m = fmaxf(m, cum[j]);
            }

            unsigned um = enc_mono(m);
            unsigned uw = __reduce_max_sync(0xffffffffu, um);

            float mw = dec_mono(uw);
            int idx = 0x7fffffff;
#pragma unroll
            for (int j = 0; j < 8; j++)
                if (cum[j] == mw) idx = min(idx, t + 512 * j);
            idx = __reduce_min_sync(0xffffffffu, idx);

            if (lane == 0)
                s_mv[par][warp] = ((unsigned long long)uw << 32) | (unsigned)(~idx);
            __syncthreads();

            unsigned long long pk = s_mv[par][lane & 15];
            unsigned hi = (unsigned)(pk >> 32);
            unsigned lo = (unsigned)pk;
            unsigned mh = __reduce_max_sync(0xffffffffu, hi);
            unsigned ml = __reduce_max_sync(0xffffffffu, (hi == mh) ? lo : 0u);
            cur = (int)(~ml);

#pragma unroll
            for (int j = 0; j < 8; j++)
                if (cur == t + 512 * j) cum[j] = NEG;
        }

        if (t == 0) {
            float* c = &g_centers[(b * Ss + Ss - 1) * 3];
            c[0] = sx[cur]; c[1] = sy[cur]; c[2] = sz[cur];
            __threadfence();
            atomicExch(&g_prog[b], Ss);
        }
        return;
    }

    // ------------------- worker -------------------
    float* wT = dyn + 3 * Nn;                // 67*64 floats
    float* xs = dyn + 3 * Nn + 67 * 64;      // 8704 floats
    __shared__ int   sgi[128];
    __shared__ float sc3[12];
    __shared__ float ssum[64], ssq[64];

    int w  = blockIdx.x - 8;                 // 0..139
    int b  = w & 7;
    int wi = w >> 3;                         // 0..17
    int nb = (b < 4) ? 18 : 17;              // workers serving this batch

    const float* P = pos + b * 3 * Nn;
    for (int i = t; i < 3 * Nn; i += 512) tile[i] = P[i];
    for (int e = t; e < 67 * 64; e += 512) {
        int o = e & 63, i = e >> 6;
        wT[i * 64 + o] = w0[o * 67 + i];
    }
    if (t < 64) { ssum[t] = 0.f; ssq[t] = 0.f; }
    __syncthreads();

    // ---- cooperative feature transpose (hidden under FPS) ----
    const float* Fb = feat + b * (Dd * Nn);
    for (int tt = wi; tt < 128; tt += nb) {
        int n0 = tt * 32;
        for (int e = t; e < 2048; e += 512) {
            int c = e >> 5, i2 = e & 31;
            xs[i2 * 65 + c] = Fb[c * Nn + n0 + i2];      // coalesced read
        }
        __syncthreads();
        for (int e = t; e < 2048; e += 512) {
            int n = e >> 6, c = e & 63;
            g_featT[(b * Nn + n0 + n) * 64 + c] = xs[n * 65 + c];  // coalesced write
        }
        __syncthreads();
    }
    __threadfence();
    if (t == 0) {
        atomicAdd(&g_tdone[b], 1);
        while (*((volatile int*)&g_tdone[b]) < nb) __nanosleep(128);
    }
    __syncthreads();

    for (int squad = wi; squad < 256; squad += nb) {
        int s0 = squad * 4;

        if (t == 0) {
            while (*((volatile int*)&g_prog[b]) < s0 + 4) __nanosleep(64);
        }
        __syncthreads();

        // ---- ballquery: warp k handles center s0+k (identical logic) ----
        if (warp < 4) {
            int bs = b * Ss + s0 + warp;
            volatile float* C = (volatile float*)&g_centers[bs * 3];
            float cx = C[0], cy = C[1], cz = C[2];
            if (lane == 0) { sc3[warp * 3] = cx; sc3[warp * 3 + 1] = cy; sc3[warp * 3 + 2] = cz; }
            float csq = cx * cx + cy * cy + cz * cz;

            int cnt = 0, first = 0;
            int* G = &sgi[warp * 32];
            unsigned lanemask = (1u << lane) - 1u;
            for (int j0 = 0; j0 < Nn; j0 += 32) {
                int j = j0 + lane;
                float x = tile[j], y = tile[Nn + j], z = tile[2 * Nn + j];
                float dot = cx * x + cy * y + cz * z;
                float psq = x * x + y * y + z * z;
                float d = -2.0f * dot + csq + psq;
                bool ok = !(d > RAD2);
                unsigned m = __ballot_sync(0xffffffffu, ok);
                if (cnt == 0 && m) first = j0 + __ffs(m) - 1;
                int p = cnt + __popc(m & lanemask);
                if (ok && p < Kk) G[p] = j;
                cnt += __popc(m);
                if (cnt >= Kk) break;
            }
            for (int p = cnt + lane; p < Kk; p += 32) G[p] = first;
        }
        __syncthreads();

        // ---- gather 4 groups x 32 samples x 67 channels into xs ----
        for (int e = t; e < 4 * 32 * 67; e += 512) {
            int g = e / 2144;
            int r = e - g * 2144;
            int h = r / 67;
            int i = r - h * 67;
            int idx = sgi[g * 32 + h];
            float v;
            if (i < 3) v = tile[i * Nn + idx] - sc3[g * 3 + i];
            else       v = g_featT[(b * Nn + idx) * 64 + (i - 3)];
            xs[(g * 32 + h) * 68 + i] = v;
        }
        __syncthreads();

        // ---- conv0 GEMM: 512 threads, 4 groups ----
        int om = (t & 15) * 4;
        int hg = t >> 4;                     // 0..31
        int g  = hg >> 3;                    // 0..3
        int h4 = (hg & 7) * 4;

        float acc[4][4];
#pragma unroll
        for (int a = 0; a < 4; a++)
#pragma unroll
            for (int j = 0; j < 4; j++) acc[a][j] = 0.f;

        const float* xrow0 = &xs[(g * 32 + h4 + 0) * 68];
        const float* xrow1 = &xs[(g * 32 + h4 + 1) * 68];
        const float* xrow2 = &xs[(g * 32 + h4 + 2) * 68];
        const float* xrow3 = &xs[(g * 32 + h4 + 3) * 68];
        for (int i = 0; i < 67; i++) {
            float4 wv = *(const float4*)&wT[i * 64 + om];
            float xr0 = xrow0[i], xr1 = xrow1[i], xr2 = xrow2[i], xr3 = xrow3[i];
            acc[0][0] += xr0 * wv.x; acc[0][1] += xr0 * wv.y; acc[0][2] += xr0 * wv.z; acc[0][3] += xr0 * wv.w;
            acc[1][0] += xr1 * wv.x; acc[1][1] += xr1 * wv.y; acc[1][2] += xr1 * wv.z; acc[1][3] += xr1 * wv.w;
            acc[2][0] += xr2 * wv.x; acc[2][1] += xr2 * wv.y; acc[2][2] += xr2 * wv.z; acc[2][3] += xr2 * wv.w;
            acc[3][0] += xr3 * wv.x; acc[3][1] += xr3 * wv.y; acc[3][2] += xr3 * wv.z; acc[3][3] += xr3 * wv.w;
        }

        float4 bias4 = *(const float4*)&b0[om];
        float ls[4] = {0, 0, 0, 0}, lq[4] = {0, 0, 0, 0};
        int bs = b * Ss + s0 + g;
#pragma unroll
        for (int hh = 0; hh < 4; hh++) {
            float4 v;
            v.x = acc[hh][0] + bias4.x;
            v.y = acc[hh][1] + bias4.y;
            v.z = acc[hh][2] + bias4.z;
            v.w = acc[hh][3] + bias4.w;
            ls[0] += v.x; lq[0] += v.x * v.x;
            ls[1] += v.y; lq[1] += v.y * v.y;
            ls[2] += v.z; lq[2] += v.z * v.z;
            ls[3] += v.w; lq[3] += v.w * v.w;
            *(float4*)&g_y0[(bs * 32 + h4 + hh) * 64 + om] = v;
        }
#pragma unroll
        for (int j = 0; j < 4; j++) {
            atomicAdd(&ssum[om + j], ls[j]);
            atomicAdd(&ssq[om + j],  lq[j]);
        }
        __syncthreads();                     // protect xs/sgi for next task
    }

    if (t < 64) {
        atomicAdd(&g_sum0[t], ssum[t]);
        atomicAdd(&g_sq0[t],  ssq[t]);
    }
}

// ---------------- conv1: 64->64, 4 centers/block, 8x4 register tile -------------
__global__ __launch_bounds__(256, 4) void conv1_kernel(const float* __restrict__ w1,
                                                       const float* __restrict__ b1,
                                                       const float* __restrict__ gam0,
                                                       const float* __restrict__ bet0) {
    extern __shared__ __align__(16) float dsm1[];
    float* wT = dsm1;                         // 64*64 = 4096 floats
    float* xs = dsm1 + 4096;                  // 4*32*64 = 8192 floats
    __shared__ float ssum[64], ssq[64];
    __shared__ float s_scale[64], s_shift[64];

    int t = threadIdx.x;
    int bs0 = blockIdx.x * 4;
    for (int e = t; e < 64 * 64; e += 256) {
        int o = e & 63, i = e >> 6;
        wT[i * 64 + o] = w1[o * 64 + i];
    }
    if (t < 64) {
        ssum[t] = 0.f; ssq[t] = 0.f;
        float mean = g_sum0[t] * (1.0f / NELEM);
        float var  = g_sq0[t] * (1.0f / NELEM) - mean * mean;
        float s = gam0[t] * rsqrtf(var + 1e-5f);
        s_scale[t] = s;
        s_shift[t] = bet0[t] - mean * s;
    }
    __syncthreads();

    const float* Y = &g_y0[bs0 * 2048];
    for (int e = t; e < 8192; e += 256) {
        int i = e & 63;
        float v = Y[e] * s_scale[i] + s_shift[i];
        xs[e] = fmaxf(v, 0.f);
    }
    __syncthreads();

    int om = (t & 15) * 4;
    int hg = t >> 4;                          // 0..15
    int g  = hg >> 2;                         // 0..3 (center)
    int h8 = (hg & 3) * 8;                    // 0,8,16,24

    float acc[8][4];
#pragma unroll
    for (int a = 0; a < 8; a++)
#pragma unroll
        for (int j = 0; j < 4; j++) acc[a][j] = 0.f;

    const float* xbase = &xs[(g * 32 + h8) * 64];
    for (int i = 0; i < 64; i += 4) {
        float4 wv0 = *(const float4*)&wT[(i + 0) * 64 + om];
        float4 wv1 = *(const float4*)&wT[(i + 1) * 64 + om];
        float4 wv2 = *(const float4*)&wT[(i + 2) * 64 + om];
        float4 wv3 = *(const float4*)&wT[(i + 3) * 64 + om];
#pragma unroll
        for (int r = 0; r < 8; r++) {
            float4 xv = *(const float4*)&xbase[r * 64 + i];
            acc[r][0] += xv.x * wv0.x; acc[r][1] += xv.x * wv0.y; acc[r][2] += xv.x * wv0.z; acc[r][3] += xv.x * wv0.w;
            acc[r][0] += xv.y * wv1.x; acc[r][1] += xv.y * wv1.y; acc[r][2] += xv.y * wv1.z; acc[r][3] += xv.y * wv1.w;
            acc[r][0] += xv.z * wv2.x; acc[r][1] += xv.z * wv2.y; acc[r][2] += xv.z * wv2.z; acc[r][3] += xv.z * wv2.w;
            acc[r][0] += xv.w * wv3.x; acc[r][1] += xv.w * wv3.y; acc[r][2] += xv.w * wv3.z; acc[r][3] += xv.w * wv3.w;
        }
    }

    float4 bias4 = *(const float4*)&b1[om];
    float ls[4] = {0, 0, 0, 0}, lq[4] = {0, 0, 0, 0};
    int bs = bs0 + g;
#pragma unroll
    for (int hh = 0; hh < 8; hh++) {
        float4 v;
        v.x = acc[hh][0] + bias4.x;
        v.y = acc[hh][1] + bias4.y;
        v.z = acc[hh][2] + bias4.z;
        v.w = acc[hh][3] + bias4.w;
        ls[0] += v.x; lq[0] += v.x * v.x;
        ls[1] += v.y; lq[1] += v.y * v.y;
        ls[2] += v.z; lq[2] += v.z * v.z;
        ls[3] += v.w; lq[3] += v.w * v.w;
        *(float4*)&g_y1[(bs * 32 + h8 + hh) * 64 + om] = v;
    }
#pragma unroll
    for (int j = 0; j < 4; j++) {
        atomicAdd(&ssum[om + j], ls[j]);
        atomicAdd(&ssq[om + j],  lq[j]);
    }
    __syncthreads();
    if (t < 64) {
        atomicAdd(&g_sum1[t], ssum[t]);
        atomicAdd(&g_sq1[t],  ssq[t]);
    }
}

// ---------------- conv2: 64->128 split into 2 half-panels of 64 outputs ---------
// Block pair (quad, half): 4 centers x 64 output channels, 16KB weight tile.
// Outputs only: BN2 stats + per-(bs,channel) max/min of y2 over h.
__global__ __launch_bounds__(256, 4) void conv2_kernel(const float* __restrict__ w2,
                                                       const float* __restrict__ b2,
                                                       const float* __restrict__ gam1,
                                                       const float* __restrict__ bet1) {
    extern __shared__ __align__(16) float dsm2[];
    float* wT = dsm2;                         // 64*64 = 4096 floats (half panel)
    float* xs = dsm2 + 4096;                  // 4*32*64 = 8192 floats
    __shared__ float ssum[64], ssq[64];
    __shared__ float s_scale[64], s_shift[64];
    __shared__ unsigned smax[256], smin[256]; // [g 0..3][c 0..63] monotone-encoded

    int t = threadIdx.x;
    int half = blockIdx.x & 1;
    int bs0  = (blockIdx.x >> 1) * 4;
    int ocb  = half * 64;

    for (int e = t; e < 64 * 64; e += 256) {
        int o = e & 63, i = e >> 6;
        wT[i * 64 + o] = w2[(ocb + o) * 64 + i];
    }
    if (t < 64) { ssum[t] = 0.f; ssq[t] = 0.f; }
    smax[t] = 0u;
    smin[t] = 0xffffffffu;
    if (t < 64) {
        float mean = g_sum1[t] * (1.0f / NELEM);
        float var  = g_sq1[t] * (1.0f / NELEM) - mean * mean;
        float s = gam1[t] * rsqrtf(var + 1e-5f);
        s_scale[t] = s;
        s_shift[t] = bet1[t] - mean * s;
    }
    __syncthreads();

    const float* Y = &g_y1[bs0 * 2048];
    for (int e = t; e < 8192; e += 256) {
        int i = e & 63;
        float v = Y[e] * s_scale[i] + s_shift[i];
        xs[e] = fmaxf(v, 0.f);
    }
    __syncthreads();

    int om = (t & 15) * 4;                    // 0..60 within half
    int hg = t >> 4;                          // 0..15
    int g  = hg >> 2;                         // 0..3 (center)
    int h8 = (hg & 3) * 8;                    // 0,8,16,24

    float acc[8][4];
#pragma unroll
    for (int a = 0; a < 8; a++)
#pragma unroll
        for (int j = 0; j < 4; j++) acc[a][j] = 0.f;

    const float* xbase = &xs[(g * 32 + h8) * 64];
    for (int i = 0; i < 64; i += 4) {
        float4 wv0 = *(const float4*)&wT[(i + 0) * 64 + om];
        float4 wv1 = *(const float4*)&wT[(i + 1) * 64 + om];
        float4 wv2 = *(const float4*)&wT[(i + 2) * 64 + om];
        float4 wv3 = *(const float4*)&wT[(i + 3) * 64 + om];
#pragma unroll
        for (int r = 0; r < 8; r++) {
            float4 xv = *(const float4*)&xbase[r * 64 + i];
            acc[r][0] += xv.x * wv0.x; acc[r][1] += xv.x * wv0.y; acc[r][2] += xv.x * wv0.z; acc[r][3] += xv.x * wv0.w;
            acc[r][0] += xv.y * wv1.x; acc[r][1] += xv.y * wv1.y; acc[r][2] += xv.y * wv1.z; acc[r][3] += xv.y * wv1.w;
            acc[r][0] += xv.z * wv2.x; acc[r][1] += xv.z * wv2.y; acc[r][2] += xv.z * wv2.z; acc[r][3] += xv.z * wv2.w;
            acc[r][0] += xv.w * wv3.x; acc[r][1] += xv.w * wv3.y; acc[r][2] += xv.w * wv3.z; acc[r][3] += xv.w * wv3.w;
        }
    }

    float4 bias4 = *(const float4*)&b2[ocb + om];
    float ls[4] = {0, 0, 0, 0}, lq[4] = {0, 0, 0, 0};
    float vmx[4] = {-3.4e38f, -3.4e38f, -3.4e38f, -3.4e38f};
    float vmn[4] = { 3.4e38f,  3.4e38f,  3.4e38f,  3.4e38f};
#pragma unroll
    for (int hh = 0; hh < 8; hh++) {
        float4 v;
        v.x = acc[hh][0] + bias4.x;
        v.y = acc[hh][1] + bias4.y;
        v.z = acc[hh][2] + bias4.z;
        v.w = acc[hh][3] + bias4.w;
        ls[0] += v.x; lq[0] += v.x * v.x;
        ls[1] += v.y; lq[1] += v.y * v.y;
        ls[2] += v.z; lq[2] += v.z * v.z;
        ls[3] += v.w; lq[3] += v.w * v.w;
        vmx[0] = fmaxf(vmx[0], v.x); vmn[0] = fminf(vmn[0], v.x);
        vmx[1] = fmaxf(vmx[1], v.y); vmn[1] = fminf(vmn[1], v.y);
        vmx[2] = fmaxf(vmx[2], v.z); vmn[2] = fminf(vmn[2], v.z);
        vmx[3] = fmaxf(vmx[3], v.w); vmn[3] = fminf(vmn[3], v.w);
    }
#pragma unroll
    for (int j = 0; j < 4; j++) {
        atomicAdd(&ssum[om + j], ls[j]);
        atomicAdd(&ssq[om + j],  lq[j]);
        atomicMax(&smax[g * 64 + om + j], enc_mono(vmx[j]));
        atomicMin(&smin[g * 64 + om + j], enc_mono(vmn[j]));
    }
    __syncthreads();
    if (t < 64) {
        atomicAdd(&g_sum2[ocb + t], ssum[t]);
        atomicAdd(&g_sq2[ocb + t],  ssq[t]);
    }
    // write per-center channel max/min: t -> (g=t>>6, c=t&63)
    {
        int gg = t >> 6, cc = t & 63;
        int bs = bs0 + gg;
        g_ymax[bs * 128 + ocb + cc] = dec_mono(smax[gg * 64 + cc]);
        g_ymin[bs * 128 + ocb + cc] = dec_mono(smin[gg * 64 + cc]);
    }
}

// ---------------- final: BN2 on pooled extrema + relu + poscopy -----------------
__global__ __launch_bounds__(256) void finalpool_kernel(float* __restrict__ out,
                                                        const float* __restrict__ gam2,
                                                        const float* __restrict__ bet2) {
    __shared__ float s_sc[128], s_sh[128];
    int t = threadIdx.x;
    if (t < 128) {
        float mean = g_sum2[t] * (1.0f / NELEM);
        float var  = g_sq2[t] * (1.0f / NELEM) - mean * mean;
        float s = gam2[t] * rsqrtf(var + 1e-5f);
        s_sc[t] = s;
        s_sh[t] = bet2[t] - mean * s;
    }
    __syncthreads();

    int gwarp = (blockIdx.x * blockDim.x + t) >> 5;   // bs
    int lane = t & 31;
    {
        int bs = gwarp;
        int b = bs >> 10, s = bs & 1023;
        const float* MX = &g_ymax[bs * 128];
        const float* MN = &g_ymin[bs * 128];
        float* F = out + Bb * 3 * Ss + b * 128 * Ss + s;
#pragma unroll
        for (int j = 0; j < 4; j++) {
            int c = lane + 32 * j;
            float scl = s_sc[c], sft = s_sh[c];
            float y = (scl >= 0.f) ? MX[c] : MN[c];
            float v = fmaxf(y * scl + sft, 0.f);
            F[c * Ss] = v;
        }
    }

    // fused poscopy: first 24576 global threads copy pos_out
    int e = blockIdx.x * blockDim.x + t;
    if (e < Bb * 3 * Ss) {
        int b2_ = e / (3 * Ss);
        int r = e - b2_ * (3 * Ss);
        int c = r / Ss;
        int s2 = r - c * Ss;
        out[e] = g_centers[(b2_ * Ss + s2) * 3 + c];
    }
}

// ---------------- launch --------------------------------------------------------
extern "C" void kernel_launch(void* const* d_in, const int* in_sizes, int n_in,
                              void* d_out, int out_size) {
    const float* pos  = (const float*)d_in[0];
    const float* feat = (const float*)d_in[1];
    const float* w0   = (const float*)d_in[2];
    const float* b0   = (const float*)d_in[3];
    const float* g0   = (const float*)d_in[4];
    const float* be0  = (const float*)d_in[5];
    const float* w1   = (const float*)d_in[6];
    const float* b1   = (const float*)d_in[7];
    const float* g1   = (const float*)d_in[8];
    const float* be1  = (const float*)d_in[9];
    const float* w2   = (const float*)d_in[10];
    const float* b2   = (const float*)d_in[11];
    const float* g2   = (const float*)d_in[12];
    const float* be2  = (const float*)d_in[13];
    float* out = (float*)d_out;

    const int FUSED_DYN = (3 * Nn + 67 * 64 + 4 * 32 * 68) * (int)sizeof(float); // 101120
    const int C1_DYN = (64 * 64 + 4 * 32 * 64) * (int)sizeof(float);             // 49152
    const int C2_DYN = (64 * 64 + 4 * 32 * 64) * (int)sizeof(float);             // 49152
    cudaFuncSetAttribute(fused_kernel, cudaFuncAttributeMaxDynamicSharedMemorySize, FUSED_DYN);
    cudaFuncSetAttribute(conv1_kernel, cudaFuncAttributeMaxDynamicSharedMemorySize, C1_DYN);
    cudaFuncSetAttribute(conv2_kernel, cudaFuncAttributeMaxDynamicSharedMemorySize, C2_DYN);

    zero_stats_kernel<<<1, 128>>>();                              // 1
    fused_kernel<<<148, 512, FUSED_DYN>>>(pos, feat, w0, b0);     // 2
    conv1_kernel<<<Bb * Ss / 4, 256, C1_DYN>>>(w1, b1, g0, be0);  // 3
    conv2_kernel<<<Bb * Ss / 2, 256, C2_DYN>>>(w2, b2, g1, be1);  // 4
    finalpool_kernel<<<Bb * Ss / 8, 256>>>(out, g2, be2);         // 5
}